// round 1
// baseline (speedup 1.0000x reference)
#include <cuda_runtime.h>

// Problem constants
#define BB 2
#define TT 2048
#define CC 1024
#define HH 16
#define GG 4
#define HD 64
#define KV 256
#define ROWS (BB * TT)  // 4096

// Scratch (allocation-free rule: __device__ globals)
__device__ float g_Q[ROWS * CC];   // 16 MB
__device__ float g_K[ROWS * KV];   //  4 MB
__device__ float g_V[ROWS * KV];   //  4 MB
__device__ float g_O[ROWS * CC];   // 16 MB

// ---------------------------------------------------------------------------
// Tiled fp32 GEMM with fused bias: C = A(MxK) @ B(KxN) + bias(N)
// 64x64 block tile, BK=16, 256 threads, 4x4 microtile per thread.
// M,N,K all multiples of 64/16 here, so no bounds checks.
// ---------------------------------------------------------------------------
__global__ void __launch_bounds__(256) gemm_bias_kernel(
    const float* __restrict__ A, const float* __restrict__ Bw,
    const float* __restrict__ bias, float* __restrict__ Cd,
    int M, int N, int K)
{
    __shared__ float As[16][68];   // As[k][m] (A tile transposed)
    __shared__ float Bs[16][68];   // Bs[k][n]

    const int tid = threadIdx.x;
    const int tx = tid & 15;
    const int ty = tid >> 4;
    const int bm = blockIdx.y << 6;
    const int bn = blockIdx.x << 6;

    float acc[4][4];
#pragma unroll
    for (int i = 0; i < 4; i++)
#pragma unroll
        for (int j = 0; j < 4; j++) acc[i][j] = 0.0f;

    // A-tile loader coords: 64 rows x 16 k; one float4 per thread
    const int am = tid >> 2;          // 0..63
    const int ak = (tid & 3) << 2;    // 0,4,8,12
    // B-tile loader coords: 16 k x 64 n; one float4 per thread
    const int bk = tid >> 4;          // 0..15
    const int bn4 = (tid & 15) << 2;  // 0..60

    const float* Aptr = A + (size_t)(bm + am) * K + ak;
    const float* Bptr = Bw + (size_t)bk * N + bn + bn4;

    for (int k0 = 0; k0 < K; k0 += 16) {
        float4 a = *(const float4*)(Aptr + k0);
        As[ak + 0][am] = a.x;
        As[ak + 1][am] = a.y;
        As[ak + 2][am] = a.z;
        As[ak + 3][am] = a.w;
        *(float4*)&Bs[bk][bn4] = *(const float4*)(Bptr + (size_t)k0 * N);
        __syncthreads();

#pragma unroll
        for (int kk = 0; kk < 16; kk++) {
            float4 av = *(const float4*)&As[kk][ty << 2];
            float4 bv = *(const float4*)&Bs[kk][tx << 2];
            acc[0][0] += av.x * bv.x; acc[0][1] += av.x * bv.y;
            acc[0][2] += av.x * bv.z; acc[0][3] += av.x * bv.w;
            acc[1][0] += av.y * bv.x; acc[1][1] += av.y * bv.y;
            acc[1][2] += av.y * bv.z; acc[1][3] += av.y * bv.w;
            acc[2][0] += av.z * bv.x; acc[2][1] += av.z * bv.y;
            acc[2][2] += av.z * bv.z; acc[2][3] += av.z * bv.w;
            acc[3][0] += av.w * bv.x; acc[3][1] += av.w * bv.y;
            acc[3][2] += av.w * bv.z; acc[3][3] += av.w * bv.w;
        }
        __syncthreads();
    }

    float4 bb = *(const float4*)(bias + bn + (tx << 2));
#pragma unroll
    for (int i = 0; i < 4; i++) {
        float4 o;
        o.x = acc[i][0] + bb.x;
        o.y = acc[i][1] + bb.y;
        o.z = acc[i][2] + bb.z;
        o.w = acc[i][3] + bb.w;
        *(float4*)(Cd + (size_t)(bm + (ty << 2) + i) * N + bn + (tx << 2)) = o;
    }
}

// ---------------------------------------------------------------------------
// Causal GQA flash attention, fp32.
// Q: (4096, 1024) row-major (B*T rows, head h at cols h*64..h*64+63)
// K/V: (4096, 256) (group g at cols g*64..)
// O: (4096, 1024) same layout as Q.
// Block: 64 q-rows x full head-dim. Iterates k-tiles of 32 up to the causal
// boundary (skips fully-masked tiles entirely).
// Threads: 256 as 16x16; S microtile 4x2, O microtile 4x4.
// ---------------------------------------------------------------------------
__global__ void __launch_bounds__(256) attn_kernel(
    const float* __restrict__ Q, const float* __restrict__ K,
    const float* __restrict__ V, float* __restrict__ O)
{
    __shared__ float Qs[64][68];
    __shared__ float Ks[32][68];
    __shared__ float Vs[32][68];
    __shared__ float Ps[64][36];

    const int tid = threadIdx.x;
    const int tx = tid & 15;
    const int ty = tid >> 4;
    const int qtile = blockIdx.x;   // 0..31
    const int h = blockIdx.y;       // 0..15
    const int b = blockIdx.z;       // 0..1
    const int g = h >> 2;           // GQA group
    const int q0 = qtile << 6;

    const float* Qg = Q + (size_t)(b * TT + q0) * CC + h * HD;
    const float* Kg = K + (size_t)(b * TT) * KV + g * HD;
    const float* Vg = V + (size_t)(b * TT) * KV + g * HD;

    // Load Q tile (64 x 64)
    for (int i = tid; i < 64 * 16; i += 256) {
        int r = i >> 4;
        int c4 = (i & 15) << 2;
        *(float4*)&Qs[r][c4] = *(const float4*)&Qg[(size_t)r * CC + c4];
    }
    __syncthreads();

    float m[4], l[4], acc[4][4];
#pragma unroll
    for (int i = 0; i < 4; i++) {
        m[i] = -1e30f;
        l[i] = 0.0f;
#pragma unroll
        for (int j = 0; j < 4; j++) acc[i][j] = 0.0f;
    }

    const float scale = 0.125f;  // 1/sqrt(64)
    const int ktiles = (q0 + 64) >> 5;  // cover keys 0..q0+63

    for (int jt = 0; jt < ktiles; jt++) {
        const int k0 = jt << 5;
        // Load K,V tiles (32 x 64 each)
        for (int i = tid; i < 32 * 16; i += 256) {
            int r = i >> 4;
            int c4 = (i & 15) << 2;
            *(float4*)&Ks[r][c4] = *(const float4*)&Kg[(size_t)(k0 + r) * KV + c4];
            *(float4*)&Vs[r][c4] = *(const float4*)&Vg[(size_t)(k0 + r) * KV + c4];
        }
        __syncthreads();

        // S = Q @ K^T for rows ty*4..+3, cols tx*2..+1
        float s[4][2];
#pragma unroll
        for (int i = 0; i < 4; i++) { s[i][0] = 0.0f; s[i][1] = 0.0f; }
#pragma unroll
        for (int d4 = 0; d4 < 64; d4 += 4) {
            float4 kv0 = *(const float4*)&Ks[(tx << 1) + 0][d4];
            float4 kv1 = *(const float4*)&Ks[(tx << 1) + 1][d4];
#pragma unroll
            for (int i = 0; i < 4; i++) {
                float4 qv = *(const float4*)&Qs[(ty << 2) + i][d4];
                s[i][0] += qv.x * kv0.x + qv.y * kv0.y + qv.z * kv0.z + qv.w * kv0.w;
                s[i][1] += qv.x * kv1.x + qv.y * kv1.y + qv.z * kv1.z + qv.w * kv1.w;
            }
        }

        // scale + causal mask
#pragma unroll
        for (int i = 0; i < 4; i++) {
            int qr = q0 + (ty << 2) + i;
#pragma unroll
            for (int c = 0; c < 2; c++) {
                int kc = k0 + (tx << 1) + c;
                s[i][c] = (kc <= qr) ? s[i][c] * scale : -1e30f;
            }
        }

        // online softmax update
#pragma unroll
        for (int i = 0; i < 4; i++) {
            float rmax = fmaxf(s[i][0], s[i][1]);
#pragma unroll
            for (int o = 1; o < 16; o <<= 1)
                rmax = fmaxf(rmax, __shfl_xor_sync(0xffffffffu, rmax, o));
            float mnew = fmaxf(m[i], rmax);
            float alpha = __expf(m[i] - mnew);
            m[i] = mnew;
            float p0 = __expf(s[i][0] - mnew);
            float p1 = __expf(s[i][1] - mnew);
            Ps[(ty << 2) + i][(tx << 1) + 0] = p0;
            Ps[(ty << 2) + i][(tx << 1) + 1] = p1;
            float rsum = p0 + p1;
#pragma unroll
            for (int o = 1; o < 16; o <<= 1)
                rsum += __shfl_xor_sync(0xffffffffu, rsum, o);
            l[i] = l[i] * alpha + rsum;
#pragma unroll
            for (int j = 0; j < 4; j++) acc[i][j] *= alpha;
        }
        __syncwarp();  // Ps rows of this ty are produced by this half-warp only

        // O += P @ V  (rows ty*4..+3, cols tx*4..+3, sum over c=0..31)
#pragma unroll
        for (int c = 0; c < 32; c += 4) {
            float4 v0 = *(const float4*)&Vs[c + 0][tx << 2];
            float4 v1 = *(const float4*)&Vs[c + 1][tx << 2];
            float4 v2 = *(const float4*)&Vs[c + 2][tx << 2];
            float4 v3 = *(const float4*)&Vs[c + 3][tx << 2];
#pragma unroll
            for (int i = 0; i < 4; i++) {
                float4 p = *(const float4*)&Ps[(ty << 2) + i][c];
                acc[i][0] += p.x * v0.x + p.y * v1.x + p.z * v2.x + p.w * v3.x;
                acc[i][1] += p.x * v0.y + p.y * v1.y + p.z * v2.y + p.w * v3.y;
                acc[i][2] += p.x * v0.z + p.y * v1.z + p.z * v2.z + p.w * v3.z;
                acc[i][3] += p.x * v0.w + p.y * v1.w + p.z * v2.w + p.w * v3.w;
            }
        }
        __syncthreads();  // protect Ks/Vs/Ps before next iteration's loads
    }

    // epilogue: normalize and store
    float* Og = O + (size_t)(b * TT + q0) * CC + h * HD;
#pragma unroll
    for (int i = 0; i < 4; i++) {
        float inv = 1.0f / l[i];
        float4 o;
        o.x = acc[i][0] * inv;
        o.y = acc[i][1] * inv;
        o.z = acc[i][2] * inv;
        o.w = acc[i][3] * inv;
        *(float4*)&Og[(size_t)((ty << 2) + i) * CC + (tx << 2)] = o;
    }
}

// ---------------------------------------------------------------------------
extern "C" void kernel_launch(void* const* d_in, const int* in_sizes, int n_in,
                              void* d_out, int out_size)
{
    (void)in_sizes; (void)n_in; (void)out_size;
    const float* x  = (const float*)d_in[0];
    const float* Wq = (const float*)d_in[1];
    const float* bq = (const float*)d_in[2];
    const float* Wk = (const float*)d_in[3];
    const float* bk = (const float*)d_in[4];
    const float* Wv = (const float*)d_in[5];
    const float* bv = (const float*)d_in[6];
    const float* Wp = (const float*)d_in[7];
    const float* bp = (const float*)d_in[8];
    float* out = (float*)d_out;

    float *Qp, *Kp, *Vp, *Op;
    cudaGetSymbolAddress((void**)&Qp, g_Q);
    cudaGetSymbolAddress((void**)&Kp, g_K);
    cudaGetSymbolAddress((void**)&Vp, g_V);
    cudaGetSymbolAddress((void**)&Op, g_O);

    // QKV projections
    gemm_bias_kernel<<<dim3(CC / 64, ROWS / 64), 256>>>(x, Wq, bq, Qp, ROWS, CC, CC);
    gemm_bias_kernel<<<dim3(KV / 64, ROWS / 64), 256>>>(x, Wk, bk, Kp, ROWS, KV, CC);
    gemm_bias_kernel<<<dim3(KV / 64, ROWS / 64), 256>>>(x, Wv, bv, Vp, ROWS, KV, CC);

    // Causal GQA attention
    attn_kernel<<<dim3(TT / 64, HH, BB), 256>>>(Qp, Kp, Vp, Op);

    // Output projection
    gemm_bias_kernel<<<dim3(CC / 64, ROWS / 64), 256>>>(Op, Wp, bp, out, ROWS, CC, CC);
}

// round 3
// speedup vs baseline: 2.5937x; 2.5937x over previous
#include <cuda_runtime.h>

// Problem constants
#define BB 2
#define TT 2048
#define CC 1024
#define HH 16
#define GG 4
#define HD 64
#define KV 256
#define ROWS (BB * TT)  // 4096

// Scratch (allocation-free rule: __device__ globals)
__device__ float g_Q[ROWS * CC];   // 16 MB
__device__ float g_K[ROWS * KV];   //  4 MB
__device__ float g_V[ROWS * KV];   //  4 MB
__device__ float g_O[ROWS * CC];   // 16 MB

// ---------------------------------------------------------------------------
// helpers
// ---------------------------------------------------------------------------
__device__ __forceinline__ float to_tf32(float x) {
    unsigned y;
    asm("cvt.rna.tf32.f32 %0, %1;" : "=r"(y) : "f"(x));
    return __uint_as_float(y);
}

// D += A@B, m16n8k8 tf32, A row-major, B col-major (we do the addressing)
__device__ __forceinline__ void mma_tf32(float* d, const unsigned* a, const unsigned* b) {
    asm volatile(
        "mma.sync.aligned.m16n8k8.row.col.f32.tf32.tf32.f32 "
        "{%0,%1,%2,%3}, {%4,%5,%6,%7}, {%8,%9}, {%0,%1,%2,%3};"
        : "+f"(d[0]), "+f"(d[1]), "+f"(d[2]), "+f"(d[3])
        : "r"(a[0]), "r"(a[1]), "r"(a[2]), "r"(a[3]),
          "r"(b[0]), "r"(b[1]));
}

// ---------------------------------------------------------------------------
// TF32 tensor-core GEMM with fused bias: C = A(MxK) @ B(KxN) + bias(N)
// 128x64 block tile, BK=32, 256 threads (8 warps as 4x2), warp tile 32x32.
// ---------------------------------------------------------------------------
__global__ void __launch_bounds__(256) gemm_tf32_kernel(
    const float* __restrict__ A, const float* __restrict__ Bw,
    const float* __restrict__ bias, float* __restrict__ Cd,
    int M, int N, int K)
{
    __shared__ float As[128][36];  // [m][k], pad 36 -> a-frag reads conflict-free
    __shared__ float Bs[32][72];   // [k][n], pad 72 -> b-frag reads conflict-free

    const int tid = threadIdx.x;
    const int lane = tid & 31;
    const int warp = tid >> 5;
    const int gid = lane >> 2;   // groupID (row within frag)
    const int tig = lane & 3;    // thread-in-group (col within frag)
    const int wm = (warp & 3) << 5;   // warp M offset 0..96
    const int wn = (warp >> 2) << 5;  // warp N offset 0..32
    const int bm = blockIdx.y << 7;
    const int bn = blockIdx.x << 6;

    float acc[2][4][4];
#pragma unroll
    for (int mi = 0; mi < 2; mi++)
#pragma unroll
        for (int ni = 0; ni < 4; ni++)
#pragma unroll
            for (int c = 0; c < 4; c++) acc[mi][ni][c] = 0.0f;

    for (int k0 = 0; k0 < K; k0 += 32) {
        // A tile: 128x32 = 1024 float4, 4 per thread
#pragma unroll
        for (int i = 0; i < 4; i++) {
            int linear = tid + (i << 8);
            int r = linear >> 3;
            int c4 = (linear & 7) << 2;
            float4 v = *(const float4*)&A[(size_t)(bm + r) * K + k0 + c4];
            v.x = to_tf32(v.x); v.y = to_tf32(v.y);
            v.z = to_tf32(v.z); v.w = to_tf32(v.w);
            *(float4*)&As[r][c4] = v;
        }
        // B tile: 32x64 = 512 float4, 2 per thread
#pragma unroll
        for (int i = 0; i < 2; i++) {
            int linear = tid + (i << 8);
            int r = linear >> 4;
            int c4 = (linear & 15) << 2;
            float4 v = *(const float4*)&Bw[(size_t)(k0 + r) * N + bn + c4];
            v.x = to_tf32(v.x); v.y = to_tf32(v.y);
            v.z = to_tf32(v.z); v.w = to_tf32(v.w);
            *(float4*)&Bs[r][c4] = v;
        }
        __syncthreads();

#pragma unroll
        for (int j = 0; j < 4; j++) {   // k-steps of 8 within BK=32
            unsigned a[2][4], b[4][2];
#pragma unroll
            for (int mi = 0; mi < 2; mi++) {
                int r = wm + (mi << 4) + gid;
                int c = (j << 3) + tig;
                a[mi][0] = __float_as_uint(As[r][c]);
                a[mi][1] = __float_as_uint(As[r + 8][c]);
                a[mi][2] = __float_as_uint(As[r][c + 4]);
                a[mi][3] = __float_as_uint(As[r + 8][c + 4]);
            }
#pragma unroll
            for (int ni = 0; ni < 4; ni++) {
                int c = wn + (ni << 3) + gid;
                int r = (j << 3) + tig;
                b[ni][0] = __float_as_uint(Bs[r][c]);
                b[ni][1] = __float_as_uint(Bs[r + 4][c]);
            }
#pragma unroll
            for (int mi = 0; mi < 2; mi++)
#pragma unroll
                for (int ni = 0; ni < 4; ni++)
                    mma_tf32(acc[mi][ni], a[mi], b[ni]);
        }
        __syncthreads();
    }

    // epilogue: bias + store (float2, cols tig*2,tig*2+1 adjacent)
#pragma unroll
    for (int mi = 0; mi < 2; mi++) {
        int r0 = bm + wm + (mi << 4) + gid;
#pragma unroll
        for (int ni = 0; ni < 4; ni++) {
            int c = bn + wn + (ni << 3) + (tig << 1);
            float2 bb = *(const float2*)&bias[c];
            float2 o0, o1;
            o0.x = acc[mi][ni][0] + bb.x;
            o0.y = acc[mi][ni][1] + bb.y;
            o1.x = acc[mi][ni][2] + bb.x;
            o1.y = acc[mi][ni][3] + bb.y;
            *(float2*)&Cd[(size_t)r0 * N + c] = o0;
            *(float2*)&Cd[(size_t)(r0 + 8) * N + c] = o1;
        }
    }
}

// ---------------------------------------------------------------------------
// Causal GQA flash attention with tf32 mma.
// Block = 64 q-rows x head (hd=64). 4 warps (128 thr), warp owns 16 q-rows.
// k-tiles of 32 keys. Q lives in A-fragments in registers for whole kernel.
// ---------------------------------------------------------------------------
__global__ void __launch_bounds__(128) attn_tf32_kernel(
    const float* __restrict__ Q, const float* __restrict__ K,
    const float* __restrict__ V, float* __restrict__ O)
{
    __shared__ float Qs[64][68];
    __shared__ float Ks[32][68];   // [key][d]
    __shared__ float Vs[32][72];   // [key][d]
    __shared__ float Ps[64][36];   // [qrow][key_local]

    const int tid = threadIdx.x;
    const int lane = tid & 31;
    const int w = tid >> 5;      // warp 0..3 -> q rows w*16..
    const int gid = lane >> 2;
    const int tig = lane & 3;
    const int q0 = blockIdx.x << 6;
    const int h = blockIdx.y;
    const int b = blockIdx.z;
    const int g = h >> 2;

    const float* Qg = Q + (size_t)(b * TT + q0) * CC + h * HD;
    const float* Kg = K + (size_t)(b * TT) * KV + g * HD;
    const float* Vg = V + (size_t)(b * TT) * KV + g * HD;

    // Load Q tile, fold softmax scale (1/8) into Q, convert to tf32.
    for (int i = tid; i < 64 * 16; i += 128) {
        int r = i >> 4;
        int c4 = (i & 15) << 2;
        float4 v = *(const float4*)&Qg[(size_t)r * CC + c4];
        v.x = to_tf32(v.x * 0.125f); v.y = to_tf32(v.y * 0.125f);
        v.z = to_tf32(v.z * 0.125f); v.w = to_tf32(v.w * 0.125f);
        *(float4*)&Qs[r][c4] = v;
    }
    __syncthreads();

    // Q A-fragments for all 8 k-steps (d=64)
    unsigned qa[8][4];
#pragma unroll
    for (int j = 0; j < 8; j++) {
        int r = (w << 4) + gid;
        int c = (j << 3) + tig;
        qa[j][0] = __float_as_uint(Qs[r][c]);
        qa[j][1] = __float_as_uint(Qs[r + 8][c]);
        qa[j][2] = __float_as_uint(Qs[r][c + 4]);
        qa[j][3] = __float_as_uint(Qs[r + 8][c + 4]);
    }

    float m_lo = -1e30f, m_hi = -1e30f, l_lo = 0.0f, l_hi = 0.0f;
    float acc[8][4];
#pragma unroll
    for (int nd = 0; nd < 8; nd++)
#pragma unroll
        for (int c = 0; c < 4; c++) acc[nd][c] = 0.0f;

    const int row_lo = q0 + (w << 4) + gid;
    const int row_hi = row_lo + 8;
    const int ktiles = (q0 + 64) >> 5;

    for (int kt = 0; kt < ktiles; kt++) {
        const int k0 = kt << 5;
        // K/V tiles: 32x16 float4 each, 4 per thread each
        for (int i = tid; i < 32 * 16; i += 128) {
            int r = i >> 4;
            int c4 = (i & 15) << 2;
            float4 kv = *(const float4*)&Kg[(size_t)(k0 + r) * KV + c4];
            kv.x = to_tf32(kv.x); kv.y = to_tf32(kv.y);
            kv.z = to_tf32(kv.z); kv.w = to_tf32(kv.w);
            *(float4*)&Ks[r][c4] = kv;
            float4 vv = *(const float4*)&Vg[(size_t)(k0 + r) * KV + c4];
            vv.x = to_tf32(vv.x); vv.y = to_tf32(vv.y);
            vv.z = to_tf32(vv.z); vv.w = to_tf32(vv.w);
            *(float4*)&Vs[r][c4] = vv;
        }
        __syncthreads();

        // S = Q @ K^T  (warp: 16 rows x 32 keys as 4 n-tiles)
        float s[4][4];
#pragma unroll
        for (int ni = 0; ni < 4; ni++)
#pragma unroll
            for (int c = 0; c < 4; c++) s[ni][c] = 0.0f;

#pragma unroll
        for (int j = 0; j < 8; j++) {
            unsigned kb[4][2];
#pragma unroll
            for (int ni = 0; ni < 4; ni++) {
                // B element (k=d, n=key) -> Ks[key][d]
                int key = (ni << 3) + gid;
                int d = (j << 3) + tig;
                kb[ni][0] = __float_as_uint(Ks[key][d]);
                kb[ni][1] = __float_as_uint(Ks[key][d + 4]);
            }
#pragma unroll
            for (int ni = 0; ni < 4; ni++)
                mma_tf32(s[ni], qa[j], kb[ni]);
        }

        // causal mask (only tiles overlapping the diagonal)
        if (k0 + 31 > q0) {
#pragma unroll
            for (int ni = 0; ni < 4; ni++) {
                int cg = k0 + (ni << 3) + (tig << 1);
                if (cg > row_lo)     s[ni][0] = -1e30f;
                if (cg + 1 > row_lo) s[ni][1] = -1e30f;
                if (cg > row_hi)     s[ni][2] = -1e30f;
                if (cg + 1 > row_hi) s[ni][3] = -1e30f;
            }
        }

        // online softmax: row owned by the 4 lanes sharing gid (xor 1,2)
        float mx_lo = -1e30f, mx_hi = -1e30f;
#pragma unroll
        for (int ni = 0; ni < 4; ni++) {
            mx_lo = fmaxf(mx_lo, fmaxf(s[ni][0], s[ni][1]));
            mx_hi = fmaxf(mx_hi, fmaxf(s[ni][2], s[ni][3]));
        }
        mx_lo = fmaxf(mx_lo, __shfl_xor_sync(0xffffffffu, mx_lo, 1));
        mx_lo = fmaxf(mx_lo, __shfl_xor_sync(0xffffffffu, mx_lo, 2));
        mx_hi = fmaxf(mx_hi, __shfl_xor_sync(0xffffffffu, mx_hi, 1));
        mx_hi = fmaxf(mx_hi, __shfl_xor_sync(0xffffffffu, mx_hi, 2));

        float mn_lo = fmaxf(m_lo, mx_lo);
        float mn_hi = fmaxf(m_hi, mx_hi);
        float alpha_lo = __expf(m_lo - mn_lo);
        float alpha_hi = __expf(m_hi - mn_hi);
        m_lo = mn_lo; m_hi = mn_hi;

        float sum_lo = 0.0f, sum_hi = 0.0f;
#pragma unroll
        for (int ni = 0; ni < 4; ni++) {
            s[ni][0] = __expf(s[ni][0] - mn_lo);
            s[ni][1] = __expf(s[ni][1] - mn_lo);
            s[ni][2] = __expf(s[ni][2] - mn_hi);
            s[ni][3] = __expf(s[ni][3] - mn_hi);
            sum_lo += s[ni][0] + s[ni][1];
            sum_hi += s[ni][2] + s[ni][3];
        }
        sum_lo += __shfl_xor_sync(0xffffffffu, sum_lo, 1);
        sum_lo += __shfl_xor_sync(0xffffffffu, sum_lo, 2);
        sum_hi += __shfl_xor_sync(0xffffffffu, sum_hi, 1);
        sum_hi += __shfl_xor_sync(0xffffffffu, sum_hi, 2);
        l_lo = l_lo * alpha_lo + sum_lo;
        l_hi = l_hi * alpha_hi + sum_hi;

#pragma unroll
        for (int nd = 0; nd < 8; nd++) {
            acc[nd][0] *= alpha_lo; acc[nd][1] *= alpha_lo;
            acc[nd][2] *= alpha_hi; acc[nd][3] *= alpha_hi;
        }

        // stage P (tf32) for use as A-fragments
        {
            int rl = (w << 4) + gid;
#pragma unroll
            for (int ni = 0; ni < 4; ni++) {
                int c = (ni << 3) + (tig << 1);
                Ps[rl][c]     = to_tf32(s[ni][0]);
                Ps[rl][c + 1] = to_tf32(s[ni][1]);
                Ps[rl + 8][c]     = to_tf32(s[ni][2]);
                Ps[rl + 8][c + 1] = to_tf32(s[ni][3]);
            }
        }
        __syncwarp();

        // O += P @ V  (k=32 keys over 4 k-steps; n=64 dims over 8 n-tiles)
        unsigned pa[4][4];
        {
            int rl = (w << 4) + gid;
#pragma unroll
            for (int j = 0; j < 4; j++) {
                int c = (j << 3) + tig;
                pa[j][0] = __float_as_uint(Ps[rl][c]);
                pa[j][1] = __float_as_uint(Ps[rl + 8][c]);
                pa[j][2] = __float_as_uint(Ps[rl][c + 4]);
                pa[j][3] = __float_as_uint(Ps[rl + 8][c + 4]);
            }
        }
#pragma unroll
        for (int j = 0; j < 4; j++) {
#pragma unroll
            for (int nd = 0; nd < 8; nd++) {
                unsigned vb[2];
                int key = (j << 3) + tig;
                int d = (nd << 3) + gid;
                vb[0] = __float_as_uint(Vs[key][d]);
                vb[1] = __float_as_uint(Vs[key + 4][d]);
                mma_tf32(acc[nd], pa[j], vb);
            }
        }
        __syncthreads();  // protect Ks/Vs before next tile load
    }

    // epilogue: normalize, store
    float inv_lo = 1.0f / l_lo;
    float inv_hi = 1.0f / l_hi;
    float* Og = O + (size_t)(b * TT + q0 + (w << 4) + gid) * CC + h * HD;
#pragma unroll
    for (int nd = 0; nd < 8; nd++) {
        int c = (nd << 3) + (tig << 1);
        float2 o0, o1;
        o0.x = acc[nd][0] * inv_lo;
        o0.y = acc[nd][1] * inv_lo;
        o1.x = acc[nd][2] * inv_hi;
        o1.y = acc[nd][3] * inv_hi;
        *(float2*)&Og[c] = o0;
        *(float2*)&Og[(size_t)8 * CC + c] = o1;
    }
}

// ---------------------------------------------------------------------------
extern "C" void kernel_launch(void* const* d_in, const int* in_sizes, int n_in,
                              void* d_out, int out_size)
{
    (void)in_sizes; (void)n_in; (void)out_size;
    const float* x  = (const float*)d_in[0];
    const float* Wq = (const float*)d_in[1];
    const float* bq = (const float*)d_in[2];
    const float* Wk = (const float*)d_in[3];
    const float* bk = (const float*)d_in[4];
    const float* Wv = (const float*)d_in[5];
    const float* bv = (const float*)d_in[6];
    const float* Wp = (const float*)d_in[7];
    const float* bp = (const float*)d_in[8];
    float* out = (float*)d_out;

    float *Qp, *Kp, *Vp, *Op;
    cudaGetSymbolAddress((void**)&Qp, g_Q);
    cudaGetSymbolAddress((void**)&Kp, g_K);
    cudaGetSymbolAddress((void**)&Vp, g_V);
    cudaGetSymbolAddress((void**)&Op, g_O);

    // QKV projections (tf32 tensor cores)
    gemm_tf32_kernel<<<dim3(CC / 64, ROWS / 128), 256>>>(x, Wq, bq, Qp, ROWS, CC, CC);
    gemm_tf32_kernel<<<dim3(KV / 64, ROWS / 128), 256>>>(x, Wk, bk, Kp, ROWS, KV, CC);
    gemm_tf32_kernel<<<dim3(KV / 64, ROWS / 128), 256>>>(x, Wv, bv, Vp, ROWS, KV, CC);

    // Causal GQA attention (tf32 tensor cores)
    attn_tf32_kernel<<<dim3(TT / 64, HH, BB), 128>>>(Qp, Kp, Vp, Op);

    // Output projection
    gemm_tf32_kernel<<<dim3(CC / 64, ROWS / 128), 256>>>(Op, Wp, bp, out, ROWS, CC, CC);
}

// round 4
// speedup vs baseline: 2.8644x; 1.1044x over previous
#include <cuda_runtime.h>

// Problem constants
#define BB 2
#define TT 2048
#define CC 1024
#define HH 16
#define GG 4
#define HD 64
#define KV 256
#define ROWS (BB * TT)  // 4096

// Scratch (allocation-free rule: __device__ globals)
__device__ float g_Q[ROWS * CC];   // 16 MB
__device__ float g_K[ROWS * KV];   //  4 MB
__device__ float g_V[ROWS * KV];   //  4 MB
__device__ float g_O[ROWS * CC];   // 16 MB

// ---------------------------------------------------------------------------
// helpers
// ---------------------------------------------------------------------------
__device__ __forceinline__ float to_tf32(float x) {
    unsigned y;
    asm("cvt.rna.tf32.f32 %0, %1;" : "=r"(y) : "f"(x));
    return __uint_as_float(y);
}

// D += A@B, m16n8k8 tf32, A row-major, B col-major (we do the addressing)
__device__ __forceinline__ void mma_tf32(float* d, const unsigned* a, const unsigned* b) {
    asm volatile(
        "mma.sync.aligned.m16n8k8.row.col.f32.tf32.tf32.f32 "
        "{%0,%1,%2,%3}, {%4,%5,%6,%7}, {%8,%9}, {%0,%1,%2,%3};"
        : "+f"(d[0]), "+f"(d[1]), "+f"(d[2]), "+f"(d[3])
        : "r"(a[0]), "r"(a[1]), "r"(a[2]), "r"(a[3]),
          "r"(b[0]), "r"(b[1]));
}

// ---------------------------------------------------------------------------
// GEMM body: C = A(MxK) @ B(KxN) + bias(N)
// 128x128 block tile, BK=32, 256 threads = 8 warps (2 in M x 4 in N),
// warp tile 64x32 (4 m-frags x 4 n-frags = 16 mmas per k-step).
// A stored with in-row pair-permutation so a-frag pairs (c, c+4) are adjacent
// -> LDS.64 fragment loads. B scalar loads, width 136 (stride 8 mod 32) ->
// conflict-free.
// ---------------------------------------------------------------------------
__device__ __forceinline__ void gemm_body(
    const float* __restrict__ A, const float* __restrict__ Bw,
    const float* __restrict__ bias, float* __restrict__ Cd,
    int N, int K, int bx, int by)
{
    __shared__ float As[128][36];   // pair-permuted columns
    __shared__ float Bs[32][136];   // [k][n]

    const int tid = threadIdx.x;
    const int lane = tid & 31;
    const int warp = tid >> 5;
    const int gid = lane >> 2;
    const int tig = lane & 3;
    const int wm = (warp & 1) << 6;   // 0 or 64
    const int wn = (warp >> 1) << 5;  // 0,32,64,96
    const int bm = by << 7;
    const int bn = bx << 7;

    float acc[4][4][4];
#pragma unroll
    for (int mi = 0; mi < 4; mi++)
#pragma unroll
        for (int ni = 0; ni < 4; ni++)
#pragma unroll
            for (int c = 0; c < 4; c++) acc[mi][ni][c] = 0.0f;

    for (int k0 = 0; k0 < K; k0 += 32) {
        // A tile: 128x32 = 1024 float4, 4 per thread, pair-permuted store
#pragma unroll
        for (int t = 0; t < 4; t++) {
            int i = tid + (t << 8);
            int r = i >> 3;
            int c4 = (i & 7) << 2;
            float4 v = *(const float4*)&A[(size_t)(bm + r) * K + k0 + c4];
            int base = (c4 & ~7) + ((c4 & 4) ? 1 : 0);
            As[r][base + 0] = to_tf32(v.x);
            As[r][base + 2] = to_tf32(v.y);
            As[r][base + 4] = to_tf32(v.z);
            As[r][base + 6] = to_tf32(v.w);
        }
        // B tile: 32x128 = 1024 float4, 4 per thread
#pragma unroll
        for (int t = 0; t < 4; t++) {
            int i = tid + (t << 8);
            int r = i >> 5;
            int c4 = (i & 31) << 2;
            float4 v = *(const float4*)&Bw[(size_t)(k0 + r) * N + bn + c4];
            v.x = to_tf32(v.x); v.y = to_tf32(v.y);
            v.z = to_tf32(v.z); v.w = to_tf32(v.w);
            *(float4*)&Bs[r][c4] = v;
        }
        __syncthreads();

#pragma unroll
        for (int j = 0; j < 4; j++) {
            unsigned a[4][4], b[4][2];
#pragma unroll
            for (int mi = 0; mi < 4; mi++) {
                int r = wm + (mi << 4) + gid;
                float2 u0 = *(const float2*)&As[r][(j << 3) + (tig << 1)];
                float2 u1 = *(const float2*)&As[r + 8][(j << 3) + (tig << 1)];
                a[mi][0] = __float_as_uint(u0.x);
                a[mi][1] = __float_as_uint(u1.x);
                a[mi][2] = __float_as_uint(u0.y);
                a[mi][3] = __float_as_uint(u1.y);
            }
#pragma unroll
            for (int ni = 0; ni < 4; ni++) {
                int kr = (j << 3) + tig;
                int n = wn + (ni << 3) + gid;
                b[ni][0] = __float_as_uint(Bs[kr][n]);
                b[ni][1] = __float_as_uint(Bs[kr + 4][n]);
            }
#pragma unroll
            for (int mi = 0; mi < 4; mi++)
#pragma unroll
                for (int ni = 0; ni < 4; ni++)
                    mma_tf32(acc[mi][ni], a[mi], b[ni]);
        }
        __syncthreads();
    }

    // epilogue: bias + store
#pragma unroll
    for (int mi = 0; mi < 4; mi++) {
        int r0 = bm + wm + (mi << 4) + gid;
#pragma unroll
        for (int ni = 0; ni < 4; ni++) {
            int c = bn + wn + (ni << 3) + (tig << 1);
            float2 bb = *(const float2*)&bias[c];
            float2 o0, o1;
            o0.x = acc[mi][ni][0] + bb.x;
            o0.y = acc[mi][ni][1] + bb.y;
            o1.x = acc[mi][ni][2] + bb.x;
            o1.y = acc[mi][ni][3] + bb.y;
            *(float2*)&Cd[(size_t)r0 * N + c] = o0;
            *(float2*)&Cd[(size_t)(r0 + 8) * N + c] = o1;
        }
    }
}

__global__ void __launch_bounds__(256) gemm_tf32_kernel(
    const float* __restrict__ A, const float* __restrict__ Bw,
    const float* __restrict__ bias, float* __restrict__ Cd,
    int N, int K)
{
    gemm_body(A, Bw, bias, Cd, N, K, blockIdx.x, blockIdx.y);
}

// K and V projections in one launch (grid.z selects)
__global__ void __launch_bounds__(256) gemm_kv_kernel(
    const float* __restrict__ x,
    const float* __restrict__ Wk, const float* __restrict__ bk, float* __restrict__ Kp,
    const float* __restrict__ Wv, const float* __restrict__ bv, float* __restrict__ Vp)
{
    if (blockIdx.z == 0)
        gemm_body(x, Wk, bk, Kp, KV, CC, blockIdx.x, blockIdx.y);
    else
        gemm_body(x, Wv, bv, Vp, KV, CC, blockIdx.x, blockIdx.y);
}

// ---------------------------------------------------------------------------
// Causal GQA flash attention with tf32 mma.
// Block = 128 q-rows x head (hd=64). 8 warps (256 thr), warp owns 16 q-rows.
// k-tiles of 32 keys. Q lives in A-fragments in registers for whole kernel.
// Q/K/P tiles stored with pair-permutation -> LDS.64 fragment loads.
// Smem overlay: Q staging buffer reused for Ksp/Vs/Ps after frag extraction.
// ---------------------------------------------------------------------------
__global__ void __launch_bounds__(256) attn_tf32_kernel(
    const float* __restrict__ Q, const float* __restrict__ K,
    const float* __restrict__ V, float* __restrict__ O)
{
    __shared__ __align__(16) float sb[9088];
    // overlay: Qs[128][68] (8704 floats) for staging, then:
    float (*Qs)[68] = (float(*)[68])sb;
    float (*Ksp)[68] = (float(*)[68])sb;            // 2176 floats
    float (*Vs)[72]  = (float(*)[72])(sb + 2176);   // 2304 floats
    float (*Ps)[36]  = (float(*)[36])(sb + 4480);   // 4608 floats

    const int tid = threadIdx.x;
    const int lane = tid & 31;
    const int w = tid >> 5;      // warp 0..7 -> q rows w*16..
    const int gid = lane >> 2;
    const int tig = lane & 3;
    const int qt = gridDim.x - 1 - blockIdx.x;  // heavy tiles first
    const int q0 = qt << 7;
    const int h = blockIdx.y;
    const int b = blockIdx.z;
    const int g = h >> 2;

    const float* Qg = Q + (size_t)(b * TT + q0) * CC + h * HD;
    const float* Kg = K + (size_t)(b * TT) * KV + g * HD;
    const float* Vg = V + (size_t)(b * TT) * KV + g * HD;

    // Load Q tile 128x64, fold scale, cvt, pair-permuted store
    for (int i = tid; i < 128 * 16; i += 256) {
        int r = i >> 4;
        int c4 = (i & 15) << 2;
        float4 v = *(const float4*)&Qg[(size_t)r * CC + c4];
        int base = (c4 & ~7) + ((c4 & 4) ? 1 : 0);
        Qs[r][base + 0] = to_tf32(v.x * 0.125f);
        Qs[r][base + 2] = to_tf32(v.y * 0.125f);
        Qs[r][base + 4] = to_tf32(v.z * 0.125f);
        Qs[r][base + 6] = to_tf32(v.w * 0.125f);
    }
    __syncthreads();

    // Q A-fragments for all 8 k-steps (d=64); packed float2 loads
    const int rl = (w << 4) + gid;
    unsigned qa[8][4];
#pragma unroll
    for (int j = 0; j < 8; j++) {
        float2 u0 = *(const float2*)&Qs[rl][(j << 3) + (tig << 1)];
        float2 u1 = *(const float2*)&Qs[rl + 8][(j << 3) + (tig << 1)];
        qa[j][0] = __float_as_uint(u0.x);
        qa[j][1] = __float_as_uint(u1.x);
        qa[j][2] = __float_as_uint(u0.y);
        qa[j][3] = __float_as_uint(u1.y);
    }
    __syncthreads();  // buffer reuse: Qs -> Ksp/Vs/Ps

    float m_lo = -1e30f, m_hi = -1e30f, l_lo = 0.0f, l_hi = 0.0f;
    float acc[8][4];
#pragma unroll
    for (int nd = 0; nd < 8; nd++)
#pragma unroll
        for (int c = 0; c < 4; c++) acc[nd][c] = 0.0f;

    const int row_lo = q0 + rl;
    const int row_hi = row_lo + 8;
    const int p0c = ((tig << 1) & 3) << 1;            // perm8(2*tig) = {0,4,1,5}
    const int perm_p0 = ((2 * tig) & 3) * 2 + ((2 * tig) >> 2);
    const int perm_p1 = ((2 * tig + 1) & 3) * 2 + ((2 * tig + 1) >> 2);
    (void)p0c;
    const int ktiles = (q0 >> 5) + 4;

    for (int kt = 0; kt < ktiles; kt++) {
        const int k0 = kt << 5;
        // K (pair-permuted) + V (plain) tiles: 32x16 float4 each, 2/thread each
#pragma unroll
        for (int t = 0; t < 2; t++) {
            int i = tid + (t << 8);
            int r = i >> 4;
            int c4 = (i & 15) << 2;
            float4 kv = *(const float4*)&Kg[(size_t)(k0 + r) * KV + c4];
            int base = (c4 & ~7) + ((c4 & 4) ? 1 : 0);
            Ksp[r][base + 0] = to_tf32(kv.x);
            Ksp[r][base + 2] = to_tf32(kv.y);
            Ksp[r][base + 4] = to_tf32(kv.z);
            Ksp[r][base + 6] = to_tf32(kv.w);
            float4 vv = *(const float4*)&Vg[(size_t)(k0 + r) * KV + c4];
            vv.x = to_tf32(vv.x); vv.y = to_tf32(vv.y);
            vv.z = to_tf32(vv.z); vv.w = to_tf32(vv.w);
            *(float4*)&Vs[r][c4] = vv;
        }
        __syncthreads();

        // S = Q @ K^T  (warp: 16 rows x 32 keys as 4 n-tiles)
        float s[4][4];
#pragma unroll
        for (int ni = 0; ni < 4; ni++)
#pragma unroll
            for (int c = 0; c < 4; c++) s[ni][c] = 0.0f;

#pragma unroll
        for (int j = 0; j < 8; j++) {
#pragma unroll
            for (int ni = 0; ni < 4; ni++) {
                int key = (ni << 3) + gid;
                float2 kk = *(const float2*)&Ksp[key][(j << 3) + (tig << 1)];
                unsigned kb[2] = { __float_as_uint(kk.x), __float_as_uint(kk.y) };
                mma_tf32(s[ni], qa[j], kb);
            }
        }

        // causal mask (only tiles overlapping the diagonal)
        if (k0 + 31 > q0) {
#pragma unroll
            for (int ni = 0; ni < 4; ni++) {
                int cg = k0 + (ni << 3) + (tig << 1);
                if (cg > row_lo)     s[ni][0] = -1e30f;
                if (cg + 1 > row_lo) s[ni][1] = -1e30f;
                if (cg > row_hi)     s[ni][2] = -1e30f;
                if (cg + 1 > row_hi) s[ni][3] = -1e30f;
            }
        }

        // online softmax: row owned by the 4 lanes sharing gid (xor 1,2)
        float mx_lo = -1e30f, mx_hi = -1e30f;
#pragma unroll
        for (int ni = 0; ni < 4; ni++) {
            mx_lo = fmaxf(mx_lo, fmaxf(s[ni][0], s[ni][1]));
            mx_hi = fmaxf(mx_hi, fmaxf(s[ni][2], s[ni][3]));
        }
        mx_lo = fmaxf(mx_lo, __shfl_xor_sync(0xffffffffu, mx_lo, 1));
        mx_lo = fmaxf(mx_lo, __shfl_xor_sync(0xffffffffu, mx_lo, 2));
        mx_hi = fmaxf(mx_hi, __shfl_xor_sync(0xffffffffu, mx_hi, 1));
        mx_hi = fmaxf(mx_hi, __shfl_xor_sync(0xffffffffu, mx_hi, 2));

        float mn_lo = fmaxf(m_lo, mx_lo);
        float mn_hi = fmaxf(m_hi, mx_hi);
        float alpha_lo = __expf(m_lo - mn_lo);
        float alpha_hi = __expf(m_hi - mn_hi);
        m_lo = mn_lo; m_hi = mn_hi;

        float sum_lo = 0.0f, sum_hi = 0.0f;
#pragma unroll
        for (int ni = 0; ni < 4; ni++) {
            s[ni][0] = __expf(s[ni][0] - mn_lo);
            s[ni][1] = __expf(s[ni][1] - mn_lo);
            s[ni][2] = __expf(s[ni][2] - mn_hi);
            s[ni][3] = __expf(s[ni][3] - mn_hi);
            sum_lo += s[ni][0] + s[ni][1];
            sum_hi += s[ni][2] + s[ni][3];
        }
        sum_lo += __shfl_xor_sync(0xffffffffu, sum_lo, 1);
        sum_lo += __shfl_xor_sync(0xffffffffu, sum_lo, 2);
        sum_hi += __shfl_xor_sync(0xffffffffu, sum_hi, 1);
        sum_hi += __shfl_xor_sync(0xffffffffu, sum_hi, 2);
        l_lo = l_lo * alpha_lo + sum_lo;
        l_hi = l_hi * alpha_hi + sum_hi;

#pragma unroll
        for (int nd = 0; nd < 8; nd++) {
            acc[nd][0] *= alpha_lo; acc[nd][1] *= alpha_lo;
            acc[nd][2] *= alpha_hi; acc[nd][3] *= alpha_hi;
        }

        // stage P (tf32) pair-permuted for A-fragment float2 loads
#pragma unroll
        for (int ni = 0; ni < 4; ni++) {
            int cb = ni << 3;
            Ps[rl][cb + perm_p0]     = to_tf32(s[ni][0]);
            Ps[rl][cb + perm_p1]     = to_tf32(s[ni][1]);
            Ps[rl + 8][cb + perm_p0] = to_tf32(s[ni][2]);
            Ps[rl + 8][cb + perm_p1] = to_tf32(s[ni][3]);
        }
        __syncwarp();

        // O += P @ V  (k=32 keys over 4 k-steps; n=64 dims over 8 n-tiles)
        unsigned pa[4][4];
#pragma unroll
        for (int j = 0; j < 4; j++) {
            float2 u0 = *(const float2*)&Ps[rl][(j << 3) + (tig << 1)];
            float2 u1 = *(const float2*)&Ps[rl + 8][(j << 3) + (tig << 1)];
            pa[j][0] = __float_as_uint(u0.x);
            pa[j][1] = __float_as_uint(u1.x);
            pa[j][2] = __float_as_uint(u0.y);
            pa[j][3] = __float_as_uint(u1.y);
        }
#pragma unroll
        for (int j = 0; j < 4; j++) {
#pragma unroll
            for (int nd = 0; nd < 8; nd++) {
                int d = (nd << 3) + gid;
                int key = (j << 3) + tig;
                unsigned vb[2] = { __float_as_uint(Vs[key][d]),
                                   __float_as_uint(Vs[key + 4][d]) };
                mma_tf32(acc[nd], pa[j], vb);
            }
        }
        __syncthreads();  // protect Ksp/Vs/Ps before next tile load
    }

    // epilogue: normalize, store
    float inv_lo = 1.0f / l_lo;
    float inv_hi = 1.0f / l_hi;
    float* Og = O + (size_t)(b * TT + q0 + rl) * CC + h * HD;
#pragma unroll
    for (int nd = 0; nd < 8; nd++) {
        int c = (nd << 3) + (tig << 1);
        float2 o0, o1;
        o0.x = acc[nd][0] * inv_lo;
        o0.y = acc[nd][1] * inv_lo;
        o1.x = acc[nd][2] * inv_hi;
        o1.y = acc[nd][3] * inv_hi;
        *(float2*)&Og[c] = o0;
        *(float2*)&Og[(size_t)8 * CC + c] = o1;
    }
}

// ---------------------------------------------------------------------------
extern "C" void kernel_launch(void* const* d_in, const int* in_sizes, int n_in,
                              void* d_out, int out_size)
{
    (void)in_sizes; (void)n_in; (void)out_size;
    const float* x  = (const float*)d_in[0];
    const float* Wq = (const float*)d_in[1];
    const float* bq = (const float*)d_in[2];
    const float* Wk = (const float*)d_in[3];
    const float* bk = (const float*)d_in[4];
    const float* Wv = (const float*)d_in[5];
    const float* bv = (const float*)d_in[6];
    const float* Wp = (const float*)d_in[7];
    const float* bp = (const float*)d_in[8];
    float* out = (float*)d_out;

    float *Qp, *Kp, *Vp, *Op;
    cudaGetSymbolAddress((void**)&Qp, g_Q);
    cudaGetSymbolAddress((void**)&Kp, g_K);
    cudaGetSymbolAddress((void**)&Vp, g_V);
    cudaGetSymbolAddress((void**)&Op, g_O);

    // Q projection (tf32 tensor cores, 128x128 tiles)
    gemm_tf32_kernel<<<dim3(CC / 128, ROWS / 128), 256>>>(x, Wq, bq, Qp, CC, CC);
    // K + V projections in one launch
    gemm_kv_kernel<<<dim3(KV / 128, ROWS / 128, 2), 256>>>(x, Wk, bk, Kp, Wv, bv, Vp);

    // Causal GQA attention (tf32 tensor cores, 128-row q-tiles)
    attn_tf32_kernel<<<dim3(TT / 128, HH, BB), 256>>>(Qp, Kp, Vp, Op);

    // Output projection
    gemm_tf32_kernel<<<dim3(CC / 128, ROWS / 128), 256>>>(Op, Wp, bp, out, CC, CC);
}

// round 6
// speedup vs baseline: 2.9905x; 1.0440x over previous
#include <cuda_runtime.h>
#include <cstdint>

// Problem constants
#define BB 2
#define TT 2048
#define CC 1024
#define HH 16
#define GG 4
#define HD 64
#define KV 256
#define ROWS (BB * TT)  // 4096

// Scratch (allocation-free rule: __device__ globals)
__device__ float g_X[ROWS * CC];   // 16 MB  tf32-rounded x
__device__ float g_Q[ROWS * CC];   // 16 MB
__device__ float g_K[ROWS * KV];   //  4 MB
__device__ float g_V[ROWS * KV];   //  4 MB
__device__ float g_O[ROWS * CC];   // 16 MB  tf32-rounded attention output

// ---------------------------------------------------------------------------
// helpers
// ---------------------------------------------------------------------------
__device__ __forceinline__ float to_tf32(float x) {
    unsigned y;
    asm("cvt.rna.tf32.f32 %0, %1;" : "=r"(y) : "f"(x));
    return __uint_as_float(y);
}

__device__ __forceinline__ uint32_t smem_u32(const void* p) {
    uint32_t a;
    asm("{ .reg .u64 t; cvta.to.shared.u64 t, %1; cvt.u32.u64 %0, t; }"
        : "=r"(a) : "l"(p));
    return a;
}

__device__ __forceinline__ void cp_async16(uint32_t saddr, const void* g) {
    asm volatile("cp.async.cg.shared.global [%0], [%1], 16;"
                 :: "r"(saddr), "l"(g) : "memory");
}
#define CP_COMMIT() asm volatile("cp.async.commit_group;" ::: "memory")
#define CP_WAIT(n)  asm volatile("cp.async.wait_group %0;" :: "n"(n) : "memory")

// D += A@B, m16n8k8 tf32, A row-major, B col-major
__device__ __forceinline__ void mma_tf32(float* d, const unsigned* a, const unsigned* b) {
    asm volatile(
        "mma.sync.aligned.m16n8k8.row.col.f32.tf32.tf32.f32 "
        "{%0,%1,%2,%3}, {%4,%5,%6,%7}, {%8,%9}, {%0,%1,%2,%3};"
        : "+f"(d[0]), "+f"(d[1]), "+f"(d[2]), "+f"(d[3])
        : "r"(a[0]), "r"(a[1]), "r"(a[2]), "r"(a[3]),
          "r"(b[0]), "r"(b[1]));
}

// ---------------------------------------------------------------------------
// tf32 rounding prepass for activations
// ---------------------------------------------------------------------------
__global__ void __launch_bounds__(256) cvt_tf32_kernel(
    const float* __restrict__ in, float* __restrict__ out, int n4)
{
    int i = blockIdx.x * 256 + threadIdx.x;
    if (i < n4) {
        float4 v = ((const float4*)in)[i];
        v.x = to_tf32(v.x); v.y = to_tf32(v.y);
        v.z = to_tf32(v.z); v.w = to_tf32(v.w);
        ((float4*)out)[i] = v;
    }
}

// ---------------------------------------------------------------------------
// TF32 mma.sync GEMM v3: C = A(MxK tf32-rounded) @ B(KxN raw) + bias
// 128x128 block tile, BK=32, 128 threads (4 warps 2x2), warp tile 64x64.
// 3-stage cp.async pipeline. A smem [128][36], B smem [32][136] (both
// conflict-free for the fragment access patterns; cp.async dst 16B-aligned:
// 36*4=144 and 136*4=544 are multiples of 16).
// ---------------------------------------------------------------------------
#define A_STRIDE 36
#define B_STRIDE 136
#define STAGE_FLOATS (128 * A_STRIDE + 32 * B_STRIDE)  // 4608+4352 = 8960
#define GEMM_SMEM_BYTES (3 * STAGE_FLOATS * 4)         // 107520

__device__ __forceinline__ void gemm_issue(
    float* smem_f, int st, const float* __restrict__ Ag,
    const float* __restrict__ Bg, int Kdim, int N, int k0, int tid)
{
    float* dA = smem_f + st * STAGE_FLOATS;
    float* dB = dA + 128 * A_STRIDE;
#pragma unroll
    for (int t = 0; t < 8; t++) {
        int ch = tid + (t << 7);
        int r = ch >> 3;
        int c4 = (ch & 7) << 2;
        cp_async16(smem_u32(dA + r * A_STRIDE + c4),
                   &Ag[(size_t)r * Kdim + k0 + c4]);
    }
#pragma unroll
    for (int t = 0; t < 8; t++) {
        int ch = tid + (t << 7);
        int r = ch >> 5;
        int c4 = (ch & 31) << 2;
        cp_async16(smem_u32(dB + r * B_STRIDE + c4),
                   &Bg[(size_t)(k0 + r) * N + c4]);
    }
}

__device__ __forceinline__ void gemm_body_v3(
    const float* __restrict__ A, const float* __restrict__ Bw,
    const float* __restrict__ bias, float* __restrict__ Cd,
    int N, int Kdim, int bx, int by, float* smem_f)
{
    const int tid = threadIdx.x;
    const int lane = tid & 31;
    const int warp = tid >> 5;
    const int gid = lane >> 2;
    const int tig = lane & 3;
    const int wm = (warp & 1) << 6;   // 0 or 64
    const int wn = (warp >> 1) << 6;  // 0 or 64
    const int bm = by << 7;
    const int bn = bx << 7;

    const float* Ag = A + (size_t)bm * Kdim;
    const float* Bg = Bw + bn;
    const int ntiles = Kdim >> 5;

    float acc[4][8][4];
#pragma unroll
    for (int mi = 0; mi < 4; mi++)
#pragma unroll
        for (int ni = 0; ni < 8; ni++)
#pragma unroll
            for (int c = 0; c < 4; c++) acc[mi][ni][c] = 0.0f;

    gemm_issue(smem_f, 0, Ag, Bg, Kdim, N, 0, tid);  CP_COMMIT();
    gemm_issue(smem_f, 1, Ag, Bg, Kdim, N, 32, tid); CP_COMMIT();

    for (int kt = 0; kt < ntiles; kt++) {
        const int st = kt % 3;
        if (kt + 2 < ntiles) {
            gemm_issue(smem_f, (kt + 2) % 3, Ag, Bg, Kdim, N, (kt + 2) << 5, tid);
            CP_COMMIT();
            CP_WAIT(2);
        } else if (kt + 1 < ntiles) {
            CP_WAIT(1);
        } else {
            CP_WAIT(0);
        }
        __syncthreads();

        const float* As_ = smem_f + st * STAGE_FLOATS;
        const float* Bs_ = As_ + 128 * A_STRIDE;
#pragma unroll
        for (int j = 0; j < 4; j++) {
            unsigned a[4][4];
#pragma unroll
            for (int mi = 0; mi < 4; mi++) {
                int r = wm + (mi << 4) + gid;
                int c = (j << 3) + tig;
                a[mi][0] = __float_as_uint(As_[r * A_STRIDE + c]);
                a[mi][1] = __float_as_uint(As_[(r + 8) * A_STRIDE + c]);
                a[mi][2] = __float_as_uint(As_[r * A_STRIDE + c + 4]);
                a[mi][3] = __float_as_uint(As_[(r + 8) * A_STRIDE + c + 4]);
            }
#pragma unroll
            for (int ni = 0; ni < 8; ni++) {
                int n = wn + (ni << 3) + gid;
                int kr = (j << 3) + tig;
                unsigned b[2];
                b[0] = __float_as_uint(to_tf32(Bs_[kr * B_STRIDE + n]));
                b[1] = __float_as_uint(to_tf32(Bs_[(kr + 4) * B_STRIDE + n]));
#pragma unroll
                for (int mi = 0; mi < 4; mi++)
                    mma_tf32(acc[mi][ni], a[mi], b);
            }
        }
        __syncthreads();
    }

    // epilogue: bias + store
#pragma unroll
    for (int mi = 0; mi < 4; mi++) {
        int r0 = bm + wm + (mi << 4) + gid;
#pragma unroll
        for (int ni = 0; ni < 8; ni++) {
            int c = bn + wn + (ni << 3) + (tig << 1);
            float2 bb = *(const float2*)&bias[c];
            float2 o0, o1;
            o0.x = acc[mi][ni][0] + bb.x;
            o0.y = acc[mi][ni][1] + bb.y;
            o1.x = acc[mi][ni][2] + bb.x;
            o1.y = acc[mi][ni][3] + bb.y;
            *(float2*)&Cd[(size_t)r0 * N + c] = o0;
            *(float2*)&Cd[(size_t)(r0 + 8) * N + c] = o1;
        }
    }
}

// Fused QKV projections: grid.x = 12 (8 Q cols + 2 K + 2 V), grid.y = 32.
__global__ void __launch_bounds__(128) gemm_qkv_kernel(
    const float* __restrict__ xT,
    const float* __restrict__ Wq, const float* __restrict__ bq, float* __restrict__ Qp,
    const float* __restrict__ Wk, const float* __restrict__ bk, float* __restrict__ Kp,
    const float* __restrict__ Wv, const float* __restrict__ bv, float* __restrict__ Vp)
{
    extern __shared__ __align__(16) float smem_f[];
    const int bx = blockIdx.x;
    const float* Bw; const float* bias; float* Cd; int N, bxx;
    if (bx < 8)       { Bw = Wq; bias = bq; Cd = Qp; N = CC; bxx = bx; }
    else if (bx < 10) { Bw = Wk; bias = bk; Cd = Kp; N = KV; bxx = bx - 8; }
    else              { Bw = Wv; bias = bv; Cd = Vp; N = KV; bxx = bx - 10; }
    gemm_body_v3(xT, Bw, bias, Cd, N, CC, bxx, blockIdx.y, smem_f);
}

__global__ void __launch_bounds__(128) gemm_p_kernel(
    const float* __restrict__ A, const float* __restrict__ Wp,
    const float* __restrict__ bp, float* __restrict__ out)
{
    extern __shared__ __align__(16) float smem_f[];
    gemm_body_v3(A, Wp, bp, out, CC, CC, blockIdx.x, blockIdx.y, smem_f);
}

// ---------------------------------------------------------------------------
// Causal GQA flash attention with tf32 mma (R4 kernel; epilogue now emits
// tf32-rounded output so the P-projection needs no A-side conversion).
// ---------------------------------------------------------------------------
__global__ void __launch_bounds__(256) attn_tf32_kernel(
    const float* __restrict__ Q, const float* __restrict__ K,
    const float* __restrict__ V, float* __restrict__ O)
{
    __shared__ __align__(16) float sb[9088];
    float (*Qs)[68] = (float(*)[68])sb;
    float (*Ksp)[68] = (float(*)[68])sb;            // 2176 floats
    float (*Vs)[72]  = (float(*)[72])(sb + 2176);   // 2304 floats
    float (*Ps)[36]  = (float(*)[36])(sb + 4480);   // 4608 floats

    const int tid = threadIdx.x;
    const int lane = tid & 31;
    const int w = tid >> 5;
    const int gid = lane >> 2;
    const int tig = lane & 3;
    const int qt = gridDim.x - 1 - blockIdx.x;
    const int q0 = qt << 7;
    const int h = blockIdx.y;
    const int b = blockIdx.z;
    const int g = h >> 2;

    const float* Qg = Q + (size_t)(b * TT + q0) * CC + h * HD;
    const float* Kg = K + (size_t)(b * TT) * KV + g * HD;
    const float* Vg = V + (size_t)(b * TT) * KV + g * HD;

    for (int i = tid; i < 128 * 16; i += 256) {
        int r = i >> 4;
        int c4 = (i & 15) << 2;
        float4 v = *(const float4*)&Qg[(size_t)r * CC + c4];
        int base = (c4 & ~7) + ((c4 & 4) ? 1 : 0);
        Qs[r][base + 0] = to_tf32(v.x * 0.125f);
        Qs[r][base + 2] = to_tf32(v.y * 0.125f);
        Qs[r][base + 4] = to_tf32(v.z * 0.125f);
        Qs[r][base + 6] = to_tf32(v.w * 0.125f);
    }
    __syncthreads();

    const int rl = (w << 4) + gid;
    unsigned qa[8][4];
#pragma unroll
    for (int j = 0; j < 8; j++) {
        float2 u0 = *(const float2*)&Qs[rl][(j << 3) + (tig << 1)];
        float2 u1 = *(const float2*)&Qs[rl + 8][(j << 3) + (tig << 1)];
        qa[j][0] = __float_as_uint(u0.x);
        qa[j][1] = __float_as_uint(u1.x);
        qa[j][2] = __float_as_uint(u0.y);
        qa[j][3] = __float_as_uint(u1.y);
    }
    __syncthreads();

    float m_lo = -1e30f, m_hi = -1e30f, l_lo = 0.0f, l_hi = 0.0f;
    float acc[8][4];
#pragma unroll
    for (int nd = 0; nd < 8; nd++)
#pragma unroll
        for (int c = 0; c < 4; c++) acc[nd][c] = 0.0f;

    const int row_lo = q0 + rl;
    const int row_hi = row_lo + 8;
    const int perm_p0 = ((2 * tig) & 3) * 2 + ((2 * tig) >> 2);
    const int perm_p1 = ((2 * tig + 1) & 3) * 2 + ((2 * tig + 1) >> 2);
    const int ktiles = (q0 >> 5) + 4;

    for (int kt = 0; kt < ktiles; kt++) {
        const int k0 = kt << 5;
#pragma unroll
        for (int t = 0; t < 2; t++) {
            int i = tid + (t << 8);
            int r = i >> 4;
            int c4 = (i & 15) << 2;
            float4 kv = *(const float4*)&Kg[(size_t)(k0 + r) * KV + c4];
            int base = (c4 & ~7) + ((c4 & 4) ? 1 : 0);
            Ksp[r][base + 0] = to_tf32(kv.x);
            Ksp[r][base + 2] = to_tf32(kv.y);
            Ksp[r][base + 4] = to_tf32(kv.z);
            Ksp[r][base + 6] = to_tf32(kv.w);
            float4 vv = *(const float4*)&Vg[(size_t)(k0 + r) * KV + c4];
            vv.x = to_tf32(vv.x); vv.y = to_tf32(vv.y);
            vv.z = to_tf32(vv.z); vv.w = to_tf32(vv.w);
            *(float4*)&Vs[r][c4] = vv;
        }
        __syncthreads();

        float s[4][4];
#pragma unroll
        for (int ni = 0; ni < 4; ni++)
#pragma unroll
            for (int c = 0; c < 4; c++) s[ni][c] = 0.0f;

#pragma unroll
        for (int j = 0; j < 8; j++) {
#pragma unroll
            for (int ni = 0; ni < 4; ni++) {
                int key = (ni << 3) + gid;
                float2 kk = *(const float2*)&Ksp[key][(j << 3) + (tig << 1)];
                unsigned kb[2] = { __float_as_uint(kk.x), __float_as_uint(kk.y) };
                mma_tf32(s[ni], qa[j], kb);
            }
        }

        if (k0 + 31 > q0) {
#pragma unroll
            for (int ni = 0; ni < 4; ni++) {
                int cg = k0 + (ni << 3) + (tig << 1);
                if (cg > row_lo)     s[ni][0] = -1e30f;
                if (cg + 1 > row_lo) s[ni][1] = -1e30f;
                if (cg > row_hi)     s[ni][2] = -1e30f;
                if (cg + 1 > row_hi) s[ni][3] = -1e30f;
            }
        }

        float mx_lo = -1e30f, mx_hi = -1e30f;
#pragma unroll
        for (int ni = 0; ni < 4; ni++) {
            mx_lo = fmaxf(mx_lo, fmaxf(s[ni][0], s[ni][1]));
            mx_hi = fmaxf(mx_hi, fmaxf(s[ni][2], s[ni][3]));
        }
        mx_lo = fmaxf(mx_lo, __shfl_xor_sync(0xffffffffu, mx_lo, 1));
        mx_lo = fmaxf(mx_lo, __shfl_xor_sync(0xffffffffu, mx_lo, 2));
        mx_hi = fmaxf(mx_hi, __shfl_xor_sync(0xffffffffu, mx_hi, 1));
        mx_hi = fmaxf(mx_hi, __shfl_xor_sync(0xffffffffu, mx_hi, 2));

        float mn_lo = fmaxf(m_lo, mx_lo);
        float mn_hi = fmaxf(m_hi, mx_hi);
        float alpha_lo = __expf(m_lo - mn_lo);
        float alpha_hi = __expf(m_hi - mn_hi);
        m_lo = mn_lo; m_hi = mn_hi;

        float sum_lo = 0.0f, sum_hi = 0.0f;
#pragma unroll
        for (int ni = 0; ni < 4; ni++) {
            s[ni][0] = __expf(s[ni][0] - mn_lo);
            s[ni][1] = __expf(s[ni][1] - mn_lo);
            s[ni][2] = __expf(s[ni][2] - mn_hi);
            s[ni][3] = __expf(s[ni][3] - mn_hi);
            sum_lo += s[ni][0] + s[ni][1];
            sum_hi += s[ni][2] + s[ni][3];
        }
        sum_lo += __shfl_xor_sync(0xffffffffu, sum_lo, 1);
        sum_lo += __shfl_xor_sync(0xffffffffu, sum_lo, 2);
        sum_hi += __shfl_xor_sync(0xffffffffu, sum_hi, 1);
        sum_hi += __shfl_xor_sync(0xffffffffu, sum_hi, 2);
        l_lo = l_lo * alpha_lo + sum_lo;
        l_hi = l_hi * alpha_hi + sum_hi;

#pragma unroll
        for (int nd = 0; nd < 8; nd++) {
            acc[nd][0] *= alpha_lo; acc[nd][1] *= alpha_lo;
            acc[nd][2] *= alpha_hi; acc[nd][3] *= alpha_hi;
        }

#pragma unroll
        for (int ni = 0; ni < 4; ni++) {
            int cb = ni << 3;
            Ps[rl][cb + perm_p0]     = to_tf32(s[ni][0]);
            Ps[rl][cb + perm_p1]     = to_tf32(s[ni][1]);
            Ps[rl + 8][cb + perm_p0] = to_tf32(s[ni][2]);
            Ps[rl + 8][cb + perm_p1] = to_tf32(s[ni][3]);
        }
        __syncwarp();

        unsigned pa[4][4];
#pragma unroll
        for (int j = 0; j < 4; j++) {
            float2 u0 = *(const float2*)&Ps[rl][(j << 3) + (tig << 1)];
            float2 u1 = *(const float2*)&Ps[rl + 8][(j << 3) + (tig << 1)];
            pa[j][0] = __float_as_uint(u0.x);
            pa[j][1] = __float_as_uint(u1.x);
            pa[j][2] = __float_as_uint(u0.y);
            pa[j][3] = __float_as_uint(u1.y);
        }
#pragma unroll
        for (int j = 0; j < 4; j++) {
#pragma unroll
            for (int nd = 0; nd < 8; nd++) {
                int d = (nd << 3) + gid;
                int key = (j << 3) + tig;
                unsigned vb[2] = { __float_as_uint(Vs[key][d]),
                                   __float_as_uint(Vs[key + 4][d]) };
                mma_tf32(acc[nd], pa[j], vb);
            }
        }
        __syncthreads();
    }

    float inv_lo = 1.0f / l_lo;
    float inv_hi = 1.0f / l_hi;
    float* Og = O + (size_t)(b * TT + q0 + rl) * CC + h * HD;
#pragma unroll
    for (int nd = 0; nd < 8; nd++) {
        int c = (nd << 3) + (tig << 1);
        float2 o0, o1;
        o0.x = to_tf32(acc[nd][0] * inv_lo);
        o0.y = to_tf32(acc[nd][1] * inv_lo);
        o1.x = to_tf32(acc[nd][2] * inv_hi);
        o1.y = to_tf32(acc[nd][3] * inv_hi);
        *(float2*)&Og[c] = o0;
        *(float2*)&Og[(size_t)8 * CC + c] = o1;
    }
}

// ---------------------------------------------------------------------------
extern "C" void kernel_launch(void* const* d_in, const int* in_sizes, int n_in,
                              void* d_out, int out_size)
{
    (void)in_sizes; (void)n_in; (void)out_size;
    const float* x  = (const float*)d_in[0];
    const float* Wq = (const float*)d_in[1];
    const float* bq = (const float*)d_in[2];
    const float* Wk = (const float*)d_in[3];
    const float* bk = (const float*)d_in[4];
    const float* Wv = (const float*)d_in[5];
    const float* bv = (const float*)d_in[6];
    const float* Wp = (const float*)d_in[7];
    const float* bp = (const float*)d_in[8];
    float* out = (float*)d_out;

    float *Xp, *Qp, *Kp, *Vp, *Op;
    cudaGetSymbolAddress((void**)&Xp, g_X);
    cudaGetSymbolAddress((void**)&Qp, g_Q);
    cudaGetSymbolAddress((void**)&Kp, g_K);
    cudaGetSymbolAddress((void**)&Vp, g_V);
    cudaGetSymbolAddress((void**)&Op, g_O);

    cudaFuncSetAttribute(gemm_qkv_kernel,
                         cudaFuncAttributeMaxDynamicSharedMemorySize, GEMM_SMEM_BYTES);
    cudaFuncSetAttribute(gemm_p_kernel,
                         cudaFuncAttributeMaxDynamicSharedMemorySize, GEMM_SMEM_BYTES);

    // Round x to tf32 once (A operand of all three projections)
    const int n4 = ROWS * CC / 4;
    cvt_tf32_kernel<<<(n4 + 255) / 256, 256>>>(x, Xp, n4);

    // Fused Q/K/V projections
    gemm_qkv_kernel<<<dim3(12, ROWS / 128), 128, GEMM_SMEM_BYTES>>>(
        Xp, Wq, bq, Qp, Wk, bk, Kp, Wv, bv, Vp);

    // Causal GQA attention (emits tf32-rounded O)
    attn_tf32_kernel<<<dim3(TT / 128, HH, BB), 256>>>(Qp, Kp, Vp, Op);

    // Output projection
    gemm_p_kernel<<<dim3(CC / 128, ROWS / 128), 128, GEMM_SMEM_BYTES>>>(
        Op, Wp, bp, out);
}

// round 8
// speedup vs baseline: 3.5108x; 1.1740x over previous
#include <cuda_runtime.h>
#include <cstdint>

// Problem constants
#define BB 2
#define TT 2048
#define CC 1024
#define HH 16
#define GG 4
#define HD 64
#define KV 256
#define ROWS (BB * TT)  // 4096

// Scratch (allocation-free rule: __device__ globals)
__device__ float g_X[ROWS * CC];    // tf32-rounded x
__device__ float g_Q[ROWS * CC];
__device__ float g_K[ROWS * KV];
__device__ float g_V[ROWS * KV];
__device__ float g_O[ROWS * CC];    // tf32-rounded attention output
__device__ float g_Wq32[CC * CC];   // tf32-rounded weights
__device__ float g_Wk32[CC * KV];
__device__ float g_Wv32[CC * KV];
__device__ float g_Wp32[CC * CC];

// ---------------------------------------------------------------------------
// helpers
// ---------------------------------------------------------------------------
__device__ __forceinline__ float to_tf32(float x) {
    unsigned y;
    asm("cvt.rna.tf32.f32 %0, %1;" : "=r"(y) : "f"(x));
    return __uint_as_float(y);
}

__device__ __forceinline__ uint32_t smem_u32(const void* p) {
    uint32_t a;
    asm("{ .reg .u64 t; cvta.to.shared.u64 t, %1; cvt.u32.u64 %0, t; }"
        : "=r"(a) : "l"(p));
    return a;
}

__device__ __forceinline__ void cp_async16(uint32_t saddr, const void* g) {
    asm volatile("cp.async.cg.shared.global [%0], [%1], 16;"
                 :: "r"(saddr), "l"(g) : "memory");
}
#define CP_COMMIT() asm volatile("cp.async.commit_group;" ::: "memory")
#define CP_WAIT(n)  asm volatile("cp.async.wait_group %0;" :: "n"(n) : "memory")

// D += A@B, m16n8k8 tf32, A row-major, B col-major
__device__ __forceinline__ void mma_tf32(float* d, const unsigned* a, const unsigned* b) {
    asm volatile(
        "mma.sync.aligned.m16n8k8.row.col.f32.tf32.tf32.f32 "
        "{%0,%1,%2,%3}, {%4,%5,%6,%7}, {%8,%9}, {%0,%1,%2,%3};"
        : "+f"(d[0]), "+f"(d[1]), "+f"(d[2]), "+f"(d[3])
        : "r"(a[0]), "r"(a[1]), "r"(a[2]), "r"(a[3]),
          "r"(b[0]), "r"(b[1]));
}

// ---------------------------------------------------------------------------
// tf32 rounding prepass
// ---------------------------------------------------------------------------
__global__ void __launch_bounds__(256) cvt_tf32_kernel(
    const float* __restrict__ in, float* __restrict__ out, int n4)
{
    int i = blockIdx.x * 256 + threadIdx.x;
    if (i < n4) {
        float4 v = ((const float4*)in)[i];
        v.x = to_tf32(v.x); v.y = to_tf32(v.y);
        v.z = to_tf32(v.z); v.w = to_tf32(v.w);
        ((float4*)out)[i] = v;
    }
}

// ---------------------------------------------------------------------------
// TF32 mma.sync GEMM v4: C = A(MxK, tf32) @ B(KxN, tf32) + bias
// 128x128 block tile, BK=32, 128 threads (4 warps 2x2), warp tile 64x64.
// 2-stage cp.async pipeline, 3 CTAs/SM. No conversions in mainloop.
// round_out != 0 -> emit tf32-rounded C.
// ---------------------------------------------------------------------------
#define A_STRIDE 36
#define B_STRIDE 136
#define STAGE_FLOATS (128 * A_STRIDE + 32 * B_STRIDE)  // 8960
#define GEMM_SMEM_BYTES (2 * STAGE_FLOATS * 4)         // 71680

__device__ __forceinline__ void gemm_issue(
    float* smem_f, int st, const float* __restrict__ Ag,
    const float* __restrict__ Bg, int Kdim, int N, int k0, int tid)
{
    float* dA = smem_f + st * STAGE_FLOATS;
    float* dB = dA + 128 * A_STRIDE;
#pragma unroll
    for (int t = 0; t < 8; t++) {
        int ch = tid + (t << 7);
        int r = ch >> 3;
        int c4 = (ch & 7) << 2;
        cp_async16(smem_u32(dA + r * A_STRIDE + c4),
                   &Ag[(size_t)r * Kdim + k0 + c4]);
    }
#pragma unroll
    for (int t = 0; t < 8; t++) {
        int ch = tid + (t << 7);
        int r = ch >> 5;
        int c4 = (ch & 31) << 2;
        cp_async16(smem_u32(dB + r * B_STRIDE + c4),
                   &Bg[(size_t)(k0 + r) * N + c4]);
    }
}

__device__ __forceinline__ void gemm_body_v4(
    const float* __restrict__ A, const float* __restrict__ Bw,
    const float* __restrict__ bias, float* __restrict__ Cd,
    int N, int Kdim, int bx, int by, float* smem_f, int round_out)
{
    const int tid = threadIdx.x;
    const int lane = tid & 31;
    const int warp = tid >> 5;
    const int gid = lane >> 2;
    const int tig = lane & 3;
    const int wm = (warp & 1) << 6;
    const int wn = (warp >> 1) << 6;
    const int bm = by << 7;
    const int bn = bx << 7;

    const float* Ag = A + (size_t)bm * Kdim;
    const float* Bg = Bw + bn;
    const int ntiles = Kdim >> 5;

    float acc[4][8][4];
#pragma unroll
    for (int mi = 0; mi < 4; mi++)
#pragma unroll
        for (int ni = 0; ni < 8; ni++)
#pragma unroll
            for (int c = 0; c < 4; c++) acc[mi][ni][c] = 0.0f;

    gemm_issue(smem_f, 0, Ag, Bg, Kdim, N, 0, tid);
    CP_COMMIT();

    for (int kt = 0; kt < ntiles; kt++) {
        if (kt + 1 < ntiles) {
            gemm_issue(smem_f, (kt + 1) & 1, Ag, Bg, Kdim, N, (kt + 1) << 5, tid);
            CP_COMMIT();
            CP_WAIT(1);
        } else {
            CP_WAIT(0);
        }
        __syncthreads();

        const float* As_ = smem_f + (kt & 1) * STAGE_FLOATS;
        const float* Bs_ = As_ + 128 * A_STRIDE;
#pragma unroll
        for (int j = 0; j < 4; j++) {
            unsigned a[4][4];
#pragma unroll
            for (int mi = 0; mi < 4; mi++) {
                int r = wm + (mi << 4) + gid;
                int c = (j << 3) + tig;
                a[mi][0] = __float_as_uint(As_[r * A_STRIDE + c]);
                a[mi][1] = __float_as_uint(As_[(r + 8) * A_STRIDE + c]);
                a[mi][2] = __float_as_uint(As_[r * A_STRIDE + c + 4]);
                a[mi][3] = __float_as_uint(As_[(r + 8) * A_STRIDE + c + 4]);
            }
#pragma unroll
            for (int ni = 0; ni < 8; ni++) {
                int n = wn + (ni << 3) + gid;
                int kr = (j << 3) + tig;
                unsigned b[2];
                b[0] = __float_as_uint(Bs_[kr * B_STRIDE + n]);
                b[1] = __float_as_uint(Bs_[(kr + 4) * B_STRIDE + n]);
#pragma unroll
                for (int mi = 0; mi < 4; mi++)
                    mma_tf32(acc[mi][ni], a[mi], b);
            }
        }
        __syncthreads();
    }

    // epilogue: bias + (optional tf32 round) + store
#pragma unroll
    for (int mi = 0; mi < 4; mi++) {
        int r0 = bm + wm + (mi << 4) + gid;
#pragma unroll
        for (int ni = 0; ni < 8; ni++) {
            int c = bn + wn + (ni << 3) + (tig << 1);
            float2 bb = *(const float2*)&bias[c];
            float2 o0, o1;
            o0.x = acc[mi][ni][0] + bb.x;
            o0.y = acc[mi][ni][1] + bb.y;
            o1.x = acc[mi][ni][2] + bb.x;
            o1.y = acc[mi][ni][3] + bb.y;
            if (round_out) {
                o0.x = to_tf32(o0.x); o0.y = to_tf32(o0.y);
                o1.x = to_tf32(o1.x); o1.y = to_tf32(o1.y);
            }
            *(float2*)&Cd[(size_t)r0 * N + c] = o0;
            *(float2*)&Cd[(size_t)(r0 + 8) * N + c] = o1;
        }
    }
}

// Fused QKV projections: grid.x = 12 (8 Q cols + 2 K + 2 V), grid.y = 32.
__global__ void __launch_bounds__(128, 3) gemm_qkv_kernel(
    const float* __restrict__ xT,
    const float* __restrict__ Wq, const float* __restrict__ bq, float* __restrict__ Qp,
    const float* __restrict__ Wk, const float* __restrict__ bk, float* __restrict__ Kp,
    const float* __restrict__ Wv, const float* __restrict__ bv, float* __restrict__ Vp)
{
    extern __shared__ __align__(16) float smem_f[];
    const int bx = blockIdx.x;
    const float* Bw; const float* bias; float* Cd; int N, bxx;
    if (bx < 8)       { Bw = Wq; bias = bq; Cd = Qp; N = CC; bxx = bx; }
    else if (bx < 10) { Bw = Wk; bias = bk; Cd = Kp; N = KV; bxx = bx - 8; }
    else              { Bw = Wv; bias = bv; Cd = Vp; N = KV; bxx = bx - 10; }
    gemm_body_v4(xT, Bw, bias, Cd, N, CC, bxx, blockIdx.y, smem_f, 1);
}

__global__ void __launch_bounds__(128, 3) gemm_p_kernel(
    const float* __restrict__ A, const float* __restrict__ Wp,
    const float* __restrict__ bp, float* __restrict__ out)
{
    extern __shared__ __align__(16) float smem_f[];
    gemm_body_v4(A, Wp, bp, out, CC, CC, blockIdx.x, blockIdx.y, smem_f, 0);
}

// ---------------------------------------------------------------------------
// Causal GQA flash attention, tf32 mma, cp.async double-buffered K/V.
// Inputs Q/K/V are already tf32-rounded, so the mainloop is conversion-free.
// Block = 128 q-rows x head. 8 warps; warp owns 16 q-rows. k-tile = 32.
// DYNAMIC shared memory (54,272 B > 48KB static limit).
// Layout (floats): K bufs @ st*2176 [32][68]; V bufs @ 4352+st*2304 [32][72];
// Ps @ 8960 [128][36]; Q staging overlays the whole buffer in the prologue.
// ---------------------------------------------------------------------------
#define ATTN_SMEM_FLOATS 13568
#define ATTN_SMEM_BYTES (ATTN_SMEM_FLOATS * 4)  // 54272

__global__ void __launch_bounds__(256) attn_tf32_kernel(
    const float* __restrict__ Q, const float* __restrict__ K,
    const float* __restrict__ V, float* __restrict__ O)
{
    extern __shared__ __align__(16) float sb[];
    float (*Qs)[68] = (float(*)[68])sb;            // prologue overlay
    float (*Ps)[36] = (float(*)[36])(sb + 8960);   // 4608 floats

    const int tid = threadIdx.x;
    const int lane = tid & 31;
    const int w = tid >> 5;
    const int gid = lane >> 2;
    const int tig = lane & 3;
    const int qt = gridDim.x - 1 - blockIdx.x;  // heavy tiles first
    const int q0 = qt << 7;
    const int h = blockIdx.y;
    const int b = blockIdx.z;
    const int g = h >> 2;

    const float* Qg = Q + (size_t)(b * TT + q0) * CC + h * HD;
    const float* Kg = K + (size_t)(b * TT) * KV + g * HD;
    const float* Vg = V + (size_t)(b * TT) * KV + g * HD;

    // Prologue: stage Q (tf32 values), fold exact 0.125 scale
    for (int i = tid; i < 128 * 16; i += 256) {
        int r = i >> 4;
        int c4 = (i & 15) << 2;
        float4 v = *(const float4*)&Qg[(size_t)r * CC + c4];
        v.x *= 0.125f; v.y *= 0.125f; v.z *= 0.125f; v.w *= 0.125f;
        *(float4*)&Qs[r][c4] = v;
    }
    __syncthreads();

    const int rl = (w << 4) + gid;
    unsigned qa[8][4];
#pragma unroll
    for (int j = 0; j < 8; j++) {
        int c = (j << 3) + tig;
        qa[j][0] = __float_as_uint(Qs[rl][c]);
        qa[j][1] = __float_as_uint(Qs[rl + 8][c]);
        qa[j][2] = __float_as_uint(Qs[rl][c + 4]);
        qa[j][3] = __float_as_uint(Qs[rl + 8][c + 4]);
    }
    __syncthreads();  // Qs dead -> K/V buffers live

    float m_lo = -1e30f, m_hi = -1e30f, l_lo = 0.0f, l_hi = 0.0f;
    float acc[8][4];
#pragma unroll
    for (int nd = 0; nd < 8; nd++)
#pragma unroll
        for (int c = 0; c < 4; c++) acc[nd][c] = 0.0f;

    const int row_lo = q0 + rl;
    const int row_hi = row_lo + 8;
    const int perm_p0 = ((2 * tig) & 3) * 2 + ((2 * tig) >> 2);
    const int perm_p1 = ((2 * tig + 1) & 3) * 2 + ((2 * tig + 1) >> 2);
    const int ktiles = (q0 >> 5) + 4;

    // cp.async tile issue: K 512 chunks + V 512 chunks, 256 threads -> 2+2
#define ATTN_ISSUE(kt_) do {                                               \
    int _st = (kt_) & 1;                                                   \
    float* _Kb = sb + _st * 2176;                                          \
    float* _Vb = sb + 4352 + _st * 2304;                                   \
    int _k0 = (kt_) << 5;                                                  \
    _Pragma("unroll")                                                      \
    for (int t = 0; t < 2; t++) {                                          \
        int ch = tid + (t << 8);                                           \
        int r = ch >> 4;                                                   \
        int c4 = (ch & 15) << 2;                                           \
        cp_async16(smem_u32(_Kb + r * 68 + c4),                            \
                   &Kg[(size_t)(_k0 + r) * KV + c4]);                      \
        cp_async16(smem_u32(_Vb + r * 72 + c4),                            \
                   &Vg[(size_t)(_k0 + r) * KV + c4]);                      \
    }                                                                      \
} while (0)

    ATTN_ISSUE(0);
    CP_COMMIT();

    for (int kt = 0; kt < ktiles; kt++) {
        if (kt + 1 < ktiles) {
            ATTN_ISSUE(kt + 1);
            CP_COMMIT();
            CP_WAIT(1);
        } else {
            CP_WAIT(0);
        }
        __syncthreads();

        const int st = kt & 1;
        const float* Ks_ = sb + st * 2176;        // [32][68]
        const float* Vs_ = sb + 4352 + st * 2304; // [32][72]
        const int k0 = kt << 5;

        // S = Q @ K^T
        float s[4][4];
#pragma unroll
        for (int ni = 0; ni < 4; ni++)
#pragma unroll
            for (int c = 0; c < 4; c++) s[ni][c] = 0.0f;

#pragma unroll
        for (int j = 0; j < 8; j++) {
#pragma unroll
            for (int ni = 0; ni < 4; ni++) {
                int key = (ni << 3) + gid;
                int d = (j << 3) + tig;
                unsigned kb[2] = { __float_as_uint(Ks_[key * 68 + d]),
                                   __float_as_uint(Ks_[key * 68 + d + 4]) };
                mma_tf32(s[ni], qa[j], kb);
            }
        }

        // causal mask
        if (k0 + 31 > q0) {
#pragma unroll
            for (int ni = 0; ni < 4; ni++) {
                int cg = k0 + (ni << 3) + (tig << 1);
                if (cg > row_lo)     s[ni][0] = -1e30f;
                if (cg + 1 > row_lo) s[ni][1] = -1e30f;
                if (cg > row_hi)     s[ni][2] = -1e30f;
                if (cg + 1 > row_hi) s[ni][3] = -1e30f;
            }
        }

        // online softmax
        float mx_lo = -1e30f, mx_hi = -1e30f;
#pragma unroll
        for (int ni = 0; ni < 4; ni++) {
            mx_lo = fmaxf(mx_lo, fmaxf(s[ni][0], s[ni][1]));
            mx_hi = fmaxf(mx_hi, fmaxf(s[ni][2], s[ni][3]));
        }
        mx_lo = fmaxf(mx_lo, __shfl_xor_sync(0xffffffffu, mx_lo, 1));
        mx_lo = fmaxf(mx_lo, __shfl_xor_sync(0xffffffffu, mx_lo, 2));
        mx_hi = fmaxf(mx_hi, __shfl_xor_sync(0xffffffffu, mx_hi, 1));
        mx_hi = fmaxf(mx_hi, __shfl_xor_sync(0xffffffffu, mx_hi, 2));

        float mn_lo = fmaxf(m_lo, mx_lo);
        float mn_hi = fmaxf(m_hi, mx_hi);
        float alpha_lo = __expf(m_lo - mn_lo);
        float alpha_hi = __expf(m_hi - mn_hi);
        m_lo = mn_lo; m_hi = mn_hi;

        float sum_lo = 0.0f, sum_hi = 0.0f;
#pragma unroll
        for (int ni = 0; ni < 4; ni++) {
            s[ni][0] = __expf(s[ni][0] - mn_lo);
            s[ni][1] = __expf(s[ni][1] - mn_lo);
            s[ni][2] = __expf(s[ni][2] - mn_hi);
            s[ni][3] = __expf(s[ni][3] - mn_hi);
            sum_lo += s[ni][0] + s[ni][1];
            sum_hi += s[ni][2] + s[ni][3];
        }
        sum_lo += __shfl_xor_sync(0xffffffffu, sum_lo, 1);
        sum_lo += __shfl_xor_sync(0xffffffffu, sum_lo, 2);
        sum_hi += __shfl_xor_sync(0xffffffffu, sum_hi, 1);
        sum_hi += __shfl_xor_sync(0xffffffffu, sum_hi, 2);
        l_lo = l_lo * alpha_lo + sum_lo;
        l_hi = l_hi * alpha_hi + sum_hi;

#pragma unroll
        for (int nd = 0; nd < 8; nd++) {
            acc[nd][0] *= alpha_lo; acc[nd][1] *= alpha_lo;
            acc[nd][2] *= alpha_hi; acc[nd][3] *= alpha_hi;
        }

        // stage P (tf32) pair-permuted for LDS.64 A-fragment loads
#pragma unroll
        for (int ni = 0; ni < 4; ni++) {
            int cb = ni << 3;
            Ps[rl][cb + perm_p0]     = to_tf32(s[ni][0]);
            Ps[rl][cb + perm_p1]     = to_tf32(s[ni][1]);
            Ps[rl + 8][cb + perm_p0] = to_tf32(s[ni][2]);
            Ps[rl + 8][cb + perm_p1] = to_tf32(s[ni][3]);
        }
        __syncwarp();

        // O += P @ V
        unsigned pa[4][4];
#pragma unroll
        for (int j = 0; j < 4; j++) {
            float2 u0 = *(const float2*)&Ps[rl][(j << 3) + (tig << 1)];
            float2 u1 = *(const float2*)&Ps[rl + 8][(j << 3) + (tig << 1)];
            pa[j][0] = __float_as_uint(u0.x);
            pa[j][1] = __float_as_uint(u1.x);
            pa[j][2] = __float_as_uint(u0.y);
            pa[j][3] = __float_as_uint(u1.y);
        }
#pragma unroll
        for (int j = 0; j < 4; j++) {
#pragma unroll
            for (int nd = 0; nd < 8; nd++) {
                int d = (nd << 3) + gid;
                int key = (j << 3) + tig;
                unsigned vb[2] = { __float_as_uint(Vs_[key * 72 + d]),
                                   __float_as_uint(Vs_[(key + 4) * 72 + d]) };
                mma_tf32(acc[nd], pa[j], vb);
            }
        }
        __syncthreads();  // compute done before buffer refill next iter
    }

    // epilogue: normalize, tf32-round (feeds final projection), store
    float inv_lo = 1.0f / l_lo;
    float inv_hi = 1.0f / l_hi;
    float* Og = O + (size_t)(b * TT + q0 + rl) * CC + h * HD;
#pragma unroll
    for (int nd = 0; nd < 8; nd++) {
        int c = (nd << 3) + (tig << 1);
        float2 o0, o1;
        o0.x = to_tf32(acc[nd][0] * inv_lo);
        o0.y = to_tf32(acc[nd][1] * inv_lo);
        o1.x = to_tf32(acc[nd][2] * inv_hi);
        o1.y = to_tf32(acc[nd][3] * inv_hi);
        *(float2*)&Og[c] = o0;
        *(float2*)&Og[(size_t)8 * CC + c] = o1;
    }
#undef ATTN_ISSUE
}

// ---------------------------------------------------------------------------
extern "C" void kernel_launch(void* const* d_in, const int* in_sizes, int n_in,
                              void* d_out, int out_size)
{
    (void)in_sizes; (void)n_in; (void)out_size;
    const float* x  = (const float*)d_in[0];
    const float* Wq = (const float*)d_in[1];
    const float* bq = (const float*)d_in[2];
    const float* Wk = (const float*)d_in[3];
    const float* bk = (const float*)d_in[4];
    const float* Wv = (const float*)d_in[5];
    const float* bv = (const float*)d_in[6];
    const float* Wp = (const float*)d_in[7];
    const float* bp = (const float*)d_in[8];
    float* out = (float*)d_out;

    float *Xp, *Qp, *Kp, *Vp, *Op, *Wq32, *Wk32, *Wv32, *Wp32;
    cudaGetSymbolAddress((void**)&Xp, g_X);
    cudaGetSymbolAddress((void**)&Qp, g_Q);
    cudaGetSymbolAddress((void**)&Kp, g_K);
    cudaGetSymbolAddress((void**)&Vp, g_V);
    cudaGetSymbolAddress((void**)&Op, g_O);
    cudaGetSymbolAddress((void**)&Wq32, g_Wq32);
    cudaGetSymbolAddress((void**)&Wk32, g_Wk32);
    cudaGetSymbolAddress((void**)&Wv32, g_Wv32);
    cudaGetSymbolAddress((void**)&Wp32, g_Wp32);

    cudaFuncSetAttribute(gemm_qkv_kernel,
                         cudaFuncAttributeMaxDynamicSharedMemorySize, GEMM_SMEM_BYTES);
    cudaFuncSetAttribute(gemm_p_kernel,
                         cudaFuncAttributeMaxDynamicSharedMemorySize, GEMM_SMEM_BYTES);
    cudaFuncSetAttribute(attn_tf32_kernel,
                         cudaFuncAttributeMaxDynamicSharedMemorySize, ATTN_SMEM_BYTES);

    // tf32 rounding prepass: activations + all weights (one-time per call)
    cvt_tf32_kernel<<<(ROWS * CC / 4 + 255) / 256, 256>>>(x, Xp, ROWS * CC / 4);
    cvt_tf32_kernel<<<(CC * CC / 4 + 255) / 256, 256>>>(Wq, Wq32, CC * CC / 4);
    cvt_tf32_kernel<<<(CC * KV / 4 + 255) / 256, 256>>>(Wk, Wk32, CC * KV / 4);
    cvt_tf32_kernel<<<(CC * KV / 4 + 255) / 256, 256>>>(Wv, Wv32, CC * KV / 4);
    cvt_tf32_kernel<<<(CC * CC / 4 + 255) / 256, 256>>>(Wp, Wp32, CC * CC / 4);

    // Fused Q/K/V projections (emit tf32-rounded outputs)
    gemm_qkv_kernel<<<dim3(12, ROWS / 128), 128, GEMM_SMEM_BYTES>>>(
        Xp, Wq32, bq, Qp, Wk32, bk, Kp, Wv32, bv, Vp);

    // Causal GQA attention (conversion-free, cp.async double-buffered)
    attn_tf32_kernel<<<dim3(TT / 128, HH, BB), 256, ATTN_SMEM_BYTES>>>(
        Qp, Kp, Vp, Op);

    // Output projection
    gemm_p_kernel<<<dim3(CC / 128, ROWS / 128), 128, GEMM_SMEM_BYTES>>>(
        Op, Wp32, bp, out);
}

// round 9
// speedup vs baseline: 4.7182x; 1.3439x over previous
#include <cuda_runtime.h>
#include <cuda_fp16.h>
#include <cstdint>

// Problem constants
#define BB 2
#define TT 2048
#define CC 1024
#define HH 16
#define GG 4
#define HD 64
#define KV 256
#define ROWS (BB * TT)  // 4096

// Q scale with folded log2(e) for exp2-based softmax
#define QSCALE (0.125f * 1.44269504088896f)

// Scratch (allocation-free rule: __device__ globals)
__device__ float  g_X[ROWS * CC];     // tf32-rounded x
__device__ __half g_Qh[ROWS * CC];    // fp16 Q (pre-scaled by QSCALE)
__device__ __half g_Kh[ROWS * KV];    // fp16 K, row-major
__device__ __half g_Vh[ROWS * KV];    // fp16 V, key-pair-interleaved per (b,g)
__device__ float  g_O[ROWS * CC];     // tf32-rounded attention output
__device__ float  g_Wq32[CC * CC];    // tf32-rounded weights
__device__ float  g_Wk32[CC * KV];
__device__ float  g_Wv32[CC * KV];
__device__ float  g_Wp32[CC * CC];

// ---------------------------------------------------------------------------
// helpers
// ---------------------------------------------------------------------------
__device__ __forceinline__ float to_tf32(float x) {
    unsigned y;
    asm("cvt.rna.tf32.f32 %0, %1;" : "=r"(y) : "f"(x));
    return __uint_as_float(y);
}

__device__ __forceinline__ uint32_t smem_u32(const void* p) {
    uint32_t a;
    asm("{ .reg .u64 t; cvta.to.shared.u64 t, %1; cvt.u32.u64 %0, t; }"
        : "=r"(a) : "l"(p));
    return a;
}

__device__ __forceinline__ void cp_async16(uint32_t saddr, const void* g) {
    asm volatile("cp.async.cg.shared.global [%0], [%1], 16;"
                 :: "r"(saddr), "l"(g) : "memory");
}
#define CP_COMMIT() asm volatile("cp.async.commit_group;" ::: "memory")
#define CP_WAIT(n)  asm volatile("cp.async.wait_group %0;" :: "n"(n) : "memory")

// tf32 m16n8k8 (GEMMs)
__device__ __forceinline__ void mma_tf32(float* d, const unsigned* a, const unsigned* b) {
    asm volatile(
        "mma.sync.aligned.m16n8k8.row.col.f32.tf32.tf32.f32 "
        "{%0,%1,%2,%3}, {%4,%5,%6,%7}, {%8,%9}, {%0,%1,%2,%3};"
        : "+f"(d[0]), "+f"(d[1]), "+f"(d[2]), "+f"(d[3])
        : "r"(a[0]), "r"(a[1]), "r"(a[2]), "r"(a[3]),
          "r"(b[0]), "r"(b[1]));
}

// fp16 m16n8k16, fp32 accum (attention)
__device__ __forceinline__ void mma_f16(float* d, const unsigned* a,
                                        unsigned b0, unsigned b1) {
    asm volatile(
        "mma.sync.aligned.m16n8k16.row.col.f32.f16.f16.f32 "
        "{%0,%1,%2,%3}, {%4,%5,%6,%7}, {%8,%9}, {%0,%1,%2,%3};"
        : "+f"(d[0]), "+f"(d[1]), "+f"(d[2]), "+f"(d[3])
        : "r"(a[0]), "r"(a[1]), "r"(a[2]), "r"(a[3]),
          "r"(b0), "r"(b1));
}

// V interleaved index: per (b,g), token pairs adjacent per d
__device__ __forceinline__ size_t vh_index(int b, int g, int t, int d) {
    return ((size_t)(b * GG + g) * (TT / 2) + (t >> 1)) * (HD * 2) + d * 2 + (t & 1);
}

// ---------------------------------------------------------------------------
// tf32 rounding prepass
// ---------------------------------------------------------------------------
__global__ void __launch_bounds__(256) cvt_tf32_kernel(
    const float* __restrict__ in, float* __restrict__ out, int n4)
{
    int i = blockIdx.x * 256 + threadIdx.x;
    if (i < n4) {
        float4 v = ((const float4*)in)[i];
        v.x = to_tf32(v.x); v.y = to_tf32(v.y);
        v.z = to_tf32(v.z); v.w = to_tf32(v.w);
        ((float4*)out)[i] = v;
    }
}

// ---------------------------------------------------------------------------
// TF32 mma.sync GEMM: 128x128 block tile, BK=32, 128 threads, warp 64x64.
// 2-stage cp.async pipeline. Epilogue modes:
//   0: fp32 out (final projection)
//   1: fp16 Q out, scaled by QSCALE
//   2: fp16 K out, row-major
//   3: fp16 V out, key-pair-interleaved
// ---------------------------------------------------------------------------
#define A_STRIDE 36
#define B_STRIDE 136
#define STAGE_FLOATS (128 * A_STRIDE + 32 * B_STRIDE)  // 8960
#define GEMM_SMEM_BYTES (2 * STAGE_FLOATS * 4)         // 71680

__device__ __forceinline__ void gemm_issue(
    float* smem_f, int st, const float* __restrict__ Ag,
    const float* __restrict__ Bg, int Kdim, int N, int k0, int tid)
{
    float* dA = smem_f + st * STAGE_FLOATS;
    float* dB = dA + 128 * A_STRIDE;
#pragma unroll
    for (int t = 0; t < 8; t++) {
        int ch = tid + (t << 7);
        int r = ch >> 3;
        int c4 = (ch & 7) << 2;
        cp_async16(smem_u32(dA + r * A_STRIDE + c4),
                   &Ag[(size_t)r * Kdim + k0 + c4]);
    }
#pragma unroll
    for (int t = 0; t < 8; t++) {
        int ch = tid + (t << 7);
        int r = ch >> 5;
        int c4 = (ch & 31) << 2;
        cp_async16(smem_u32(dB + r * B_STRIDE + c4),
                   &Bg[(size_t)(k0 + r) * N + c4]);
    }
}

__device__ __forceinline__ void gemm_body_v5(
    const float* __restrict__ A, const float* __restrict__ Bw,
    const float* __restrict__ bias, void* __restrict__ Cd,
    int N, int Kdim, int bx, int by, float* smem_f, int mode)
{
    const int tid = threadIdx.x;
    const int lane = tid & 31;
    const int warp = tid >> 5;
    const int gid = lane >> 2;
    const int tig = lane & 3;
    const int wm = (warp & 1) << 6;
    const int wn = (warp >> 1) << 6;
    const int bm = by << 7;
    const int bn = bx << 7;

    const float* Ag = A + (size_t)bm * Kdim;
    const float* Bg = Bw + bn;
    const int ntiles = Kdim >> 5;

    float acc[4][8][4];
#pragma unroll
    for (int mi = 0; mi < 4; mi++)
#pragma unroll
        for (int ni = 0; ni < 8; ni++)
#pragma unroll
            for (int c = 0; c < 4; c++) acc[mi][ni][c] = 0.0f;

    gemm_issue(smem_f, 0, Ag, Bg, Kdim, N, 0, tid);
    CP_COMMIT();

    for (int kt = 0; kt < ntiles; kt++) {
        if (kt + 1 < ntiles) {
            gemm_issue(smem_f, (kt + 1) & 1, Ag, Bg, Kdim, N, (kt + 1) << 5, tid);
            CP_COMMIT();
            CP_WAIT(1);
        } else {
            CP_WAIT(0);
        }
        __syncthreads();

        const float* As_ = smem_f + (kt & 1) * STAGE_FLOATS;
        const float* Bs_ = As_ + 128 * A_STRIDE;
#pragma unroll
        for (int j = 0; j < 4; j++) {
            unsigned a[4][4];
#pragma unroll
            for (int mi = 0; mi < 4; mi++) {
                int r = wm + (mi << 4) + gid;
                int c = (j << 3) + tig;
                a[mi][0] = __float_as_uint(As_[r * A_STRIDE + c]);
                a[mi][1] = __float_as_uint(As_[(r + 8) * A_STRIDE + c]);
                a[mi][2] = __float_as_uint(As_[r * A_STRIDE + c + 4]);
                a[mi][3] = __float_as_uint(As_[(r + 8) * A_STRIDE + c + 4]);
            }
#pragma unroll
            for (int ni = 0; ni < 8; ni++) {
                int n = wn + (ni << 3) + gid;
                int kr = (j << 3) + tig;
                unsigned b[2];
                b[0] = __float_as_uint(Bs_[kr * B_STRIDE + n]);
                b[1] = __float_as_uint(Bs_[(kr + 4) * B_STRIDE + n]);
#pragma unroll
                for (int mi = 0; mi < 4; mi++)
                    mma_tf32(acc[mi][ni], a[mi], b);
            }
        }
        __syncthreads();
    }

    // epilogue
#pragma unroll
    for (int mi = 0; mi < 4; mi++) {
        int r0 = bm + wm + (mi << 4) + gid;
#pragma unroll
        for (int ni = 0; ni < 8; ni++) {
            int c = bn + wn + (ni << 3) + (tig << 1);
            float2 bb = *(const float2*)&bias[c];
            float o00 = acc[mi][ni][0] + bb.x;
            float o01 = acc[mi][ni][1] + bb.y;
            float o10 = acc[mi][ni][2] + bb.x;
            float o11 = acc[mi][ni][3] + bb.y;
            if (mode == 0) {
                float* C = (float*)Cd;
                *(float2*)&C[(size_t)r0 * N + c] = make_float2(o00, o01);
                *(float2*)&C[(size_t)(r0 + 8) * N + c] = make_float2(o10, o11);
            } else if (mode == 1) {
                __half* C = (__half*)Cd;
                *(__half2*)&C[(size_t)r0 * N + c] =
                    __floats2half2_rn(o00 * QSCALE, o01 * QSCALE);
                *(__half2*)&C[(size_t)(r0 + 8) * N + c] =
                    __floats2half2_rn(o10 * QSCALE, o11 * QSCALE);
            } else if (mode == 2) {
                __half* C = (__half*)Cd;
                *(__half2*)&C[(size_t)r0 * N + c] = __floats2half2_rn(o00, o01);
                *(__half2*)&C[(size_t)(r0 + 8) * N + c] = __floats2half2_rn(o10, o11);
            } else {
                __half* C = (__half*)Cd;
                int gg = c >> 6, d = c & 63;
                int b0_ = r0 >> 11, t0 = r0 & 2047;
                int b1_ = (r0 + 8) >> 11, t1 = (r0 + 8) & 2047;
                C[vh_index(b0_, gg, t0, d)]     = __float2half_rn(o00);
                C[vh_index(b0_, gg, t0, d + 1)] = __float2half_rn(o01);
                C[vh_index(b1_, gg, t1, d)]     = __float2half_rn(o10);
                C[vh_index(b1_, gg, t1, d + 1)] = __float2half_rn(o11);
            }
        }
    }
}

// Fused QKV projections: grid.x = 12 (8 Q cols + 2 K + 2 V), grid.y = 32.
__global__ void __launch_bounds__(128, 3) gemm_qkv_kernel(
    const float* __restrict__ xT,
    const float* __restrict__ Wq, const float* __restrict__ bq, __half* __restrict__ Qh,
    const float* __restrict__ Wk, const float* __restrict__ bk, __half* __restrict__ Kh,
    const float* __restrict__ Wv, const float* __restrict__ bv, __half* __restrict__ Vh)
{
    extern __shared__ __align__(16) float smem_f[];
    const int bx = blockIdx.x;
    const float* Bw; const float* bias; void* Cd; int N, bxx, mode;
    if (bx < 8)       { Bw = Wq; bias = bq; Cd = Qh; N = CC; bxx = bx;      mode = 1; }
    else if (bx < 10) { Bw = Wk; bias = bk; Cd = Kh; N = KV; bxx = bx - 8;  mode = 2; }
    else              { Bw = Wv; bias = bv; Cd = Vh; N = KV; bxx = bx - 10; mode = 3; }
    gemm_body_v5(xT, Bw, bias, Cd, N, CC, bxx, blockIdx.y, smem_f, mode);
}

__global__ void __launch_bounds__(128, 3) gemm_p_kernel(
    const float* __restrict__ A, const float* __restrict__ Wp,
    const float* __restrict__ bp, float* __restrict__ out)
{
    extern __shared__ __align__(16) float smem_f[];
    gemm_body_v5(A, Wp, bp, out, CC, CC, blockIdx.x, blockIdx.y, smem_f, 0);
}

// ---------------------------------------------------------------------------
// Causal GQA flash attention, fp16 m16n8k16, fp32 softmax/accum.
// Block = 128 q-rows x head. 8 warps; warp owns 16 q-rows. k-tile = 32.
// Smem (halves): Ks st @ st*2304 [32][72]; Vp st @ 4608+st*2304 [16][144];
// Ps @ 9216 [128][72]; Q staging overlays [128][72] at offset 0.
// Q pre-scaled by 0.125*log2e -> exp2f softmax, no muls.
// ---------------------------------------------------------------------------
__global__ void __launch_bounds__(256) attn_f16_kernel(
    const __half* __restrict__ Qh, const __half* __restrict__ Kh,
    const __half* __restrict__ Vh, float* __restrict__ O)
{
    __shared__ __align__(16) __half sbh[18432];  // 36,864 B

    const int tid = threadIdx.x;
    const int lane = tid & 31;
    const int w = tid >> 5;
    const int gid = lane >> 2;
    const int tig = lane & 3;
    const int qt = gridDim.x - 1 - blockIdx.x;  // heavy tiles first
    const int q0 = qt << 7;
    const int h = blockIdx.y;
    const int b = blockIdx.z;
    const int g = h >> 2;

    const __half* Qg = Qh + (size_t)(b * TT + q0) * CC + h * HD;
    const __half* Kg = Kh + (size_t)(b * TT) * KV + g * HD;
    const __half* Vg = Vh + (size_t)(b * GG + g) * (TT / 2) * (HD * 2);

    // Prologue: stage Q fp16 (128 rows x 64 halves = 8 chunks/row)
#pragma unroll
    for (int t = 0; t < 4; t++) {
        int ch = tid + (t << 8);
        int r = ch >> 3;
        int c8 = (ch & 7) << 3;
        cp_async16(smem_u32(sbh + r * 72 + c8), Qg + (size_t)r * CC + c8);
    }
    CP_COMMIT();
    CP_WAIT(0);
    __syncthreads();

    const int rl = (w << 4) + gid;
    unsigned qa[4][4];
#pragma unroll
    for (int jj = 0; jj < 4; jj++) {
        int base = rl * 72 + (jj << 4) + (tig << 1);
        qa[jj][0] = *(const unsigned*)(sbh + base);
        qa[jj][1] = *(const unsigned*)(sbh + base + 8 * 72);
        qa[jj][2] = *(const unsigned*)(sbh + base + 8);
        qa[jj][3] = *(const unsigned*)(sbh + base + 8 * 72 + 8);
    }
    __syncthreads();  // Q staging dead -> K/V buffers live

    float m_lo = -1e30f, m_hi = -1e30f, l_lo = 0.0f, l_hi = 0.0f;
    float acc[8][4];
#pragma unroll
    for (int nd = 0; nd < 8; nd++)
#pragma unroll
        for (int c = 0; c < 4; c++) acc[nd][c] = 0.0f;

    const int row_lo = q0 + rl;
    const int row_hi = row_lo + 8;
    const int ktiles = (q0 >> 5) + 4;
    __half* Ps = sbh + 9216;

    // Per-tile cp.async: K 256 chunks + V 256 chunks, 1 each per thread
#define ATTN_ISSUE(kt_) do {                                                \
    int _st = (kt_) & 1;                                                    \
    int _k0 = (kt_) << 5;                                                   \
    {                                                                       \
        int _r = tid >> 3, _c8 = (tid & 7) << 3;                            \
        cp_async16(smem_u32(sbh + _st * 2304 + _r * 72 + _c8),              \
                   Kg + (size_t)(_k0 + _r) * KV + _c8);                     \
    }                                                                       \
    {                                                                       \
        int _tp = tid >> 4, _cc8 = (tid & 15) << 3;                         \
        cp_async16(smem_u32(sbh + 4608 + _st * 2304 + _tp * 144 + _cc8),    \
                   Vg + (size_t)((_k0 >> 1) + _tp) * 128 + _cc8);           \
    }                                                                       \
} while (0)

    ATTN_ISSUE(0);
    CP_COMMIT();

    for (int kt = 0; kt < ktiles; kt++) {
        if (kt + 1 < ktiles) {
            ATTN_ISSUE(kt + 1);
            CP_COMMIT();
            CP_WAIT(1);
        } else {
            CP_WAIT(0);
        }
        __syncthreads();

        const int st = kt & 1;
        const __half* Ks_ = sbh + st * 2304;          // [32][72]
        const __half* Vp_ = sbh + 4608 + st * 2304;   // [16][144]
        const int k0 = kt << 5;

        // S = Q @ K^T : 4 k-steps x 4 n-tiles = 16 mmas
        float s[4][4];
#pragma unroll
        for (int ni = 0; ni < 4; ni++)
#pragma unroll
            for (int c = 0; c < 4; c++) s[ni][c] = 0.0f;

#pragma unroll
        for (int jj = 0; jj < 4; jj++) {
#pragma unroll
            for (int ni = 0; ni < 4; ni++) {
                int key = (ni << 3) + gid;
                int koff = key * 72 + (jj << 4) + (tig << 1);
                unsigned b0 = *(const unsigned*)(Ks_ + koff);
                unsigned b1 = *(const unsigned*)(Ks_ + koff + 8);
                mma_f16(s[ni], qa[jj], b0, b1);
            }
        }

        // causal mask
        if (k0 + 31 > q0) {
#pragma unroll
            for (int ni = 0; ni < 4; ni++) {
                int cg = k0 + (ni << 3) + (tig << 1);
                if (cg > row_lo)     s[ni][0] = -1e30f;
                if (cg + 1 > row_lo) s[ni][1] = -1e30f;
                if (cg > row_hi)     s[ni][2] = -1e30f;
                if (cg + 1 > row_hi) s[ni][3] = -1e30f;
            }
        }

        // online softmax (base-2; scale folded into Q)
        float mx_lo = -1e30f, mx_hi = -1e30f;
#pragma unroll
        for (int ni = 0; ni < 4; ni++) {
            mx_lo = fmaxf(mx_lo, fmaxf(s[ni][0], s[ni][1]));
            mx_hi = fmaxf(mx_hi, fmaxf(s[ni][2], s[ni][3]));
        }
        mx_lo = fmaxf(mx_lo, __shfl_xor_sync(0xffffffffu, mx_lo, 1));
        mx_lo = fmaxf(mx_lo, __shfl_xor_sync(0xffffffffu, mx_lo, 2));
        mx_hi = fmaxf(mx_hi, __shfl_xor_sync(0xffffffffu, mx_hi, 1));
        mx_hi = fmaxf(mx_hi, __shfl_xor_sync(0xffffffffu, mx_hi, 2));

        float mn_lo = fmaxf(m_lo, mx_lo);
        float mn_hi = fmaxf(m_hi, mx_hi);
        float alpha_lo = exp2f(m_lo - mn_lo);
        float alpha_hi = exp2f(m_hi - mn_hi);
        m_lo = mn_lo; m_hi = mn_hi;

        float sum_lo = 0.0f, sum_hi = 0.0f;
#pragma unroll
        for (int ni = 0; ni < 4; ni++) {
            s[ni][0] = exp2f(s[ni][0] - mn_lo);
            s[ni][1] = exp2f(s[ni][1] - mn_lo);
            s[ni][2] = exp2f(s[ni][2] - mn_hi);
            s[ni][3] = exp2f(s[ni][3] - mn_hi);
            sum_lo += s[ni][0] + s[ni][1];
            sum_hi += s[ni][2] + s[ni][3];
        }
        sum_lo += __shfl_xor_sync(0xffffffffu, sum_lo, 1);
        sum_lo += __shfl_xor_sync(0xffffffffu, sum_lo, 2);
        sum_hi += __shfl_xor_sync(0xffffffffu, sum_hi, 1);
        sum_hi += __shfl_xor_sync(0xffffffffu, sum_hi, 2);
        l_lo = l_lo * alpha_lo + sum_lo;
        l_hi = l_hi * alpha_hi + sum_hi;

#pragma unroll
        for (int nd = 0; nd < 8; nd++) {
            acc[nd][0] *= alpha_lo; acc[nd][1] *= alpha_lo;
            acc[nd][2] *= alpha_hi; acc[nd][3] *= alpha_hi;
        }

        // stage P fp16 (half2 stores, natural layout)
#pragma unroll
        for (int ni = 0; ni < 4; ni++) {
            int c = (ni << 3) + (tig << 1);
            *(__half2*)(Ps + rl * 72 + c)       = __floats2half2_rn(s[ni][0], s[ni][1]);
            *(__half2*)(Ps + (rl + 8) * 72 + c) = __floats2half2_rn(s[ni][2], s[ni][3]);
        }
        __syncwarp();

        // O += P @ V : 2 k-steps x 8 n-tiles = 16 mmas
        unsigned pa[2][4];
#pragma unroll
        for (int jj = 0; jj < 2; jj++) {
            int base = rl * 72 + (jj << 4) + (tig << 1);
            pa[jj][0] = *(const unsigned*)(Ps + base);
            pa[jj][1] = *(const unsigned*)(Ps + base + 8 * 72);
            pa[jj][2] = *(const unsigned*)(Ps + base + 8);
            pa[jj][3] = *(const unsigned*)(Ps + base + 8 * 72 + 8);
        }
#pragma unroll
        for (int jj = 0; jj < 2; jj++) {
#pragma unroll
            for (int nd = 0; nd < 8; nd++) {
                int d = (nd << 3) + gid;
                int voff = ((jj << 3) + tig) * 144 + (d << 1);
                unsigned b0 = *(const unsigned*)(Vp_ + voff);
                unsigned b1 = *(const unsigned*)(Vp_ + voff + 576);  // +4 key-pairs
                mma_f16(acc[nd], pa[jj], b0, b1);
            }
        }
        __syncthreads();
    }

    // epilogue: normalize, tf32-round (feeds tf32 projection), store fp32
    float inv_lo = 1.0f / l_lo;
    float inv_hi = 1.0f / l_hi;
    float* Og = O + (size_t)(b * TT + q0 + rl) * CC + h * HD;
#pragma unroll
    for (int nd = 0; nd < 8; nd++) {
        int c = (nd << 3) + (tig << 1);
        float2 o0, o1;
        o0.x = to_tf32(acc[nd][0] * inv_lo);
        o0.y = to_tf32(acc[nd][1] * inv_lo);
        o1.x = to_tf32(acc[nd][2] * inv_hi);
        o1.y = to_tf32(acc[nd][3] * inv_hi);
        *(float2*)&Og[c] = o0;
        *(float2*)&Og[(size_t)8 * CC + c] = o1;
    }
#undef ATTN_ISSUE
}

// ---------------------------------------------------------------------------
extern "C" void kernel_launch(void* const* d_in, const int* in_sizes, int n_in,
                              void* d_out, int out_size)
{
    (void)in_sizes; (void)n_in; (void)out_size;
    const float* x  = (const float*)d_in[0];
    const float* Wq = (const float*)d_in[1];
    const float* bq = (const float*)d_in[2];
    const float* Wk = (const float*)d_in[3];
    const float* bk = (const float*)d_in[4];
    const float* Wv = (const float*)d_in[5];
    const float* bv = (const float*)d_in[6];
    const float* Wp = (const float*)d_in[7];
    const float* bp = (const float*)d_in[8];
    float* out = (float*)d_out;

    float *Xp, *Op, *Wq32, *Wk32, *Wv32, *Wp32;
    __half *Qh, *Kh, *Vh;
    cudaGetSymbolAddress((void**)&Xp, g_X);
    cudaGetSymbolAddress((void**)&Qh, g_Qh);
    cudaGetSymbolAddress((void**)&Kh, g_Kh);
    cudaGetSymbolAddress((void**)&Vh, g_Vh);
    cudaGetSymbolAddress((void**)&Op, g_O);
    cudaGetSymbolAddress((void**)&Wq32, g_Wq32);
    cudaGetSymbolAddress((void**)&Wk32, g_Wk32);
    cudaGetSymbolAddress((void**)&Wv32, g_Wv32);
    cudaGetSymbolAddress((void**)&Wp32, g_Wp32);

    cudaFuncSetAttribute(gemm_qkv_kernel,
                         cudaFuncAttributeMaxDynamicSharedMemorySize, GEMM_SMEM_BYTES);
    cudaFuncSetAttribute(gemm_p_kernel,
                         cudaFuncAttributeMaxDynamicSharedMemorySize, GEMM_SMEM_BYTES);

    // tf32 rounding prepass: activations + weights
    cvt_tf32_kernel<<<(ROWS * CC / 4 + 255) / 256, 256>>>(x, Xp, ROWS * CC / 4);
    cvt_tf32_kernel<<<(CC * CC / 4 + 255) / 256, 256>>>(Wq, Wq32, CC * CC / 4);
    cvt_tf32_kernel<<<(CC * KV / 4 + 255) / 256, 256>>>(Wk, Wk32, CC * KV / 4);
    cvt_tf32_kernel<<<(CC * KV / 4 + 255) / 256, 256>>>(Wv, Wv32, CC * KV / 4);
    cvt_tf32_kernel<<<(CC * CC / 4 + 255) / 256, 256>>>(Wp, Wp32, CC * CC / 4);

    // Fused Q/K/V projections (emit fp16 in attention-native layouts)
    gemm_qkv_kernel<<<dim3(12, ROWS / 128), 128, GEMM_SMEM_BYTES>>>(
        Xp, Wq32, bq, Qh, Wk32, bk, Kh, Wv32, bv, Vh);

    // Causal GQA attention (fp16 tensor cores, fp32 softmax)
    attn_f16_kernel<<<dim3(TT / 128, HH, BB), 256>>>(Qh, Kh, Vh, Op);

    // Output projection (tf32)
    gemm_p_kernel<<<dim3(CC / 128, ROWS / 128), 128, GEMM_SMEM_BYTES>>>(
        Op, Wp32, bp, out);
}

// round 11
// speedup vs baseline: 6.0843x; 1.2895x over previous
#include <cuda_runtime.h>
#include <cuda_fp16.h>
#include <cstdint>

// Problem constants
#define BB 2
#define TT 2048
#define CC 1024
#define HH 16
#define GG 4
#define HD 64
#define KV 256
#define ROWS (BB * TT)  // 4096

// Q scale with folded log2(e) for exp2-based softmax
#define QSCALE (0.125f * 1.44269504088896f)

// Scratch (allocation-free rule: __device__ globals)
__device__ __half g_Xh[ROWS * CC];    // fp16 x
__device__ __half g_Qh[ROWS * CC];    // fp16 Q (pre-scaled by QSCALE)
__device__ __half g_Kh[ROWS * KV];    // fp16 K, row-major
__device__ __half g_Vh[ROWS * KV];    // fp16 V, key-pair-interleaved per (b,g)
__device__ __half g_Oh[ROWS * CC];    // fp16 attention output
__device__ __half g_Wqh[CC * CC];     // fp16 weights, k-pair-interleaved
__device__ __half g_Wkh[CC * KV];
__device__ __half g_Wvh[CC * KV];
__device__ __half g_Wph[CC * CC];

// ---------------------------------------------------------------------------
// helpers
// ---------------------------------------------------------------------------
__device__ __forceinline__ uint32_t smem_u32(const void* p) {
    uint32_t a;
    asm("{ .reg .u64 t; cvta.to.shared.u64 t, %1; cvt.u32.u64 %0, t; }"
        : "=r"(a) : "l"(p));
    return a;
}

__device__ __forceinline__ void cp_async16(uint32_t saddr, const void* g) {
    asm volatile("cp.async.cg.shared.global [%0], [%1], 16;"
                 :: "r"(saddr), "l"(g) : "memory");
}
#define CP_COMMIT() asm volatile("cp.async.commit_group;" ::: "memory")
#define CP_WAIT(n)  asm volatile("cp.async.wait_group %0;" :: "n"(n) : "memory")

// fp16 m16n8k16, fp32 accum
__device__ __forceinline__ void mma_f16(float* d, const unsigned* a,
                                        unsigned b0, unsigned b1) {
    asm volatile(
        "mma.sync.aligned.m16n8k16.row.col.f32.f16.f16.f32 "
        "{%0,%1,%2,%3}, {%4,%5,%6,%7}, {%8,%9}, {%0,%1,%2,%3};"
        : "+f"(d[0]), "+f"(d[1]), "+f"(d[2]), "+f"(d[3])
        : "r"(a[0]), "r"(a[1]), "r"(a[2]), "r"(a[3]),
          "r"(b0), "r"(b1));
}

// V interleaved index: per (b,g), token pairs adjacent per d
__device__ __forceinline__ size_t vh_index(int b, int g, int t, int d) {
    return ((size_t)(b * GG + g) * (TT / 2) + (t >> 1)) * (HD * 2) + d * 2 + (t & 1);
}

// ---------------------------------------------------------------------------
// Prepass 1: x -> fp16
// ---------------------------------------------------------------------------
__global__ void __launch_bounds__(256) cvt_x16_kernel(
    const float* __restrict__ in, __half* __restrict__ out, int n4)
{
    int i = blockIdx.x * 256 + threadIdx.x;
    if (i < n4) {
        float4 v = ((const float4*)in)[i];
        __half2 h0 = __floats2half2_rn(v.x, v.y);
        __half2 h1 = __floats2half2_rn(v.z, v.w);
        *(__half2*)&out[i * 4]     = h0;
        *(__half2*)&out[i * 4 + 2] = h1;
    }
}

// Prepass 2: all 4 weights -> fp16, k-pair-interleaved:
//   out[(k>>1)*2N + 2n + (k&1)] = in[k*N + n]
__global__ void __launch_bounds__(256) cvt_weights_kernel(
    const float* __restrict__ Wq, __half* __restrict__ Wqh,
    const float* __restrict__ Wk, __half* __restrict__ Wkh,
    const float* __restrict__ Wv, __half* __restrict__ Wvh,
    const float* __restrict__ Wp, __half* __restrict__ Wph)
{
    const int m = blockIdx.y;
    const float* in; __half* out; int N;
    if (m == 0)      { in = Wq; out = Wqh; N = CC; }
    else if (m == 1) { in = Wk; out = Wkh; N = KV; }
    else if (m == 2) { in = Wv; out = Wvh; N = KV; }
    else             { in = Wp; out = Wph; N = CC; }
    const int total = (CC / 2) * N;
    int idx = blockIdx.x * 256 + threadIdx.x;
    if (idx < total) {
        int kp = idx / N, n = idx % N;
        float a = in[(size_t)(2 * kp) * N + n];
        float b = in[(size_t)(2 * kp + 1) * N + n];
        *(__half2*)&out[(size_t)kp * 2 * N + 2 * n] = __floats2half2_rn(a, b);
    }
}

// ---------------------------------------------------------------------------
// FP16 mma.sync GEMM: C = A(MxK fp16) @ B(fp16 k-pair-interleaved) + bias
// 128x128 block tile, BK=32, 128 threads (4 warps 2x2), warp tile 64x64.
// 2-stage cp.async. Epilogue modes:
//   0: fp32 out (final projection)
//   1: fp16 Q out, scaled by QSCALE
//   2: fp16 K out, row-major
//   3: fp16 V out, key-pair-interleaved
// Smem strides (halves): A 40 (conflict-free a-frags), B 272 (conflict-free
// b-frags). Stage = 128*40 + 16*272 = 9472 halves = 18944 B; 2 stages 37.9KB.
// ---------------------------------------------------------------------------
#define A_ST 40
#define B_ST 272
#define STAGE_HALVES (128 * A_ST + 16 * B_ST)     // 9472
#define GEMM_SMEM_BYTES (2 * STAGE_HALVES * 2)    // 37888

__device__ __forceinline__ void gemm_issue16(
    __half* smem_h, int st, const __half* __restrict__ Ag,
    const __half* __restrict__ Bg, int Kdim, int N2, int k0, int tid)
{
    __half* dA = smem_h + st * STAGE_HALVES;
    __half* dB = dA + 128 * A_ST;
    // A: 128 rows x 32 halves = 512 x 16B chunks
#pragma unroll
    for (int t = 0; t < 4; t++) {
        int ch = tid + (t << 7);
        int r = ch >> 2;
        int c8 = (ch & 3) << 3;
        cp_async16(smem_u32(dA + r * A_ST + c8),
                   Ag + (size_t)r * Kdim + k0 + c8);
    }
    // B: 16 kp-rows x 256 halves = 512 x 16B chunks
#pragma unroll
    for (int t = 0; t < 4; t++) {
        int ch = tid + (t << 7);
        int kp = ch >> 5;
        int c8 = (ch & 31) << 3;
        cp_async16(smem_u32(dB + kp * B_ST + c8),
                   Bg + (size_t)((k0 >> 1) + kp) * N2 + c8);
    }
}

__device__ __forceinline__ void gemm_body16(
    const __half* __restrict__ A, const __half* __restrict__ Bw,
    const float* __restrict__ bias, void* __restrict__ Cd,
    int N, int Kdim, int bx, int by, __half* smem_h, int mode)
{
    const int tid = threadIdx.x;
    const int lane = tid & 31;
    const int warp = tid >> 5;
    const int gid = lane >> 2;
    const int tig = lane & 3;
    const int wm = (warp & 1) << 6;
    const int wn = (warp >> 1) << 6;
    const int bm = by << 7;
    const int bn = bx << 7;

    const __half* Ag = A + (size_t)bm * Kdim;
    const __half* Bg = Bw + bn * 2;   // interleaved: tile cols at bn*2 halves
    const int N2 = N * 2;             // interleaved row length (halves)
    const int ntiles = Kdim >> 5;

    float acc[4][8][4];
#pragma unroll
    for (int mi = 0; mi < 4; mi++)
#pragma unroll
        for (int ni = 0; ni < 8; ni++)
#pragma unroll
            for (int c = 0; c < 4; c++) acc[mi][ni][c] = 0.0f;

    gemm_issue16(smem_h, 0, Ag, Bg, Kdim, N2, 0, tid);
    CP_COMMIT();

    for (int kt = 0; kt < ntiles; kt++) {
        if (kt + 1 < ntiles) {
            gemm_issue16(smem_h, (kt + 1) & 1, Ag, Bg, Kdim, N2, (kt + 1) << 5, tid);
            CP_COMMIT();
            CP_WAIT(1);
        } else {
            CP_WAIT(0);
        }
        __syncthreads();

        const __half* As_ = smem_h + (kt & 1) * STAGE_HALVES;
        const __half* Bs_ = As_ + 128 * A_ST;
#pragma unroll
        for (int jj = 0; jj < 2; jj++) {   // two k16 steps per BK=32
            unsigned a[4][4];
#pragma unroll
            for (int mi = 0; mi < 4; mi++) {
                int base = (wm + (mi << 4) + gid) * A_ST + (jj << 4) + (tig << 1);
                a[mi][0] = *(const unsigned*)(As_ + base);
                a[mi][1] = *(const unsigned*)(As_ + base + 8 * A_ST);
                a[mi][2] = *(const unsigned*)(As_ + base + 8);
                a[mi][3] = *(const unsigned*)(As_ + base + 8 * A_ST + 8);
            }
#pragma unroll
            for (int ni = 0; ni < 8; ni++) {
                int n = wn + (ni << 3) + gid;
                int kp = (jj << 3) + tig;
                unsigned b0 = *(const unsigned*)(Bs_ + kp * B_ST + n * 2);
                unsigned b1 = *(const unsigned*)(Bs_ + (kp + 4) * B_ST + n * 2);
#pragma unroll
                for (int mi = 0; mi < 4; mi++)
                    mma_f16(acc[mi][ni], a[mi], b0, b1);
            }
        }
        __syncthreads();
    }

    // epilogue
#pragma unroll
    for (int mi = 0; mi < 4; mi++) {
        int r0 = bm + wm + (mi << 4) + gid;
#pragma unroll
        for (int ni = 0; ni < 8; ni++) {
            int c = bn + wn + (ni << 3) + (tig << 1);
            float2 bb = *(const float2*)&bias[c];
            float o00 = acc[mi][ni][0] + bb.x;
            float o01 = acc[mi][ni][1] + bb.y;
            float o10 = acc[mi][ni][2] + bb.x;
            float o11 = acc[mi][ni][3] + bb.y;
            if (mode == 0) {
                float* C = (float*)Cd;
                *(float2*)&C[(size_t)r0 * N + c] = make_float2(o00, o01);
                *(float2*)&C[(size_t)(r0 + 8) * N + c] = make_float2(o10, o11);
            } else if (mode == 1) {
                __half* C = (__half*)Cd;
                *(__half2*)&C[(size_t)r0 * N + c] =
                    __floats2half2_rn(o00 * QSCALE, o01 * QSCALE);
                *(__half2*)&C[(size_t)(r0 + 8) * N + c] =
                    __floats2half2_rn(o10 * QSCALE, o11 * QSCALE);
            } else if (mode == 2) {
                __half* C = (__half*)Cd;
                *(__half2*)&C[(size_t)r0 * N + c] = __floats2half2_rn(o00, o01);
                *(__half2*)&C[(size_t)(r0 + 8) * N + c] = __floats2half2_rn(o10, o11);
            } else {
                __half* C = (__half*)Cd;
                int gg = c >> 6, d = c & 63;
                int b0_ = r0 >> 11, t0 = r0 & 2047;
                int b1_ = (r0 + 8) >> 11, t1 = (r0 + 8) & 2047;
                C[vh_index(b0_, gg, t0, d)]     = __float2half_rn(o00);
                C[vh_index(b0_, gg, t0, d + 1)] = __float2half_rn(o01);
                C[vh_index(b1_, gg, t1, d)]     = __float2half_rn(o10);
                C[vh_index(b1_, gg, t1, d + 1)] = __float2half_rn(o11);
            }
        }
    }
}

// Fused QKV projections: grid.x = 12 (8 Q cols + 2 K + 2 V), grid.y = 32.
__global__ void __launch_bounds__(128, 3) gemm_qkv_kernel(
    const __half* __restrict__ Xh,
    const __half* __restrict__ Wq, const float* __restrict__ bq, __half* __restrict__ Qh,
    const __half* __restrict__ Wk, const float* __restrict__ bk, __half* __restrict__ Kh,
    const __half* __restrict__ Wv, const float* __restrict__ bv, __half* __restrict__ Vh)
{
    extern __shared__ __align__(16) __half smem_h[];
    const int bx = blockIdx.x;
    const __half* Bw; const float* bias; void* Cd; int N, bxx, mode;
    if (bx < 8)       { Bw = Wq; bias = bq; Cd = Qh; N = CC; bxx = bx;      mode = 1; }
    else if (bx < 10) { Bw = Wk; bias = bk; Cd = Kh; N = KV; bxx = bx - 8;  mode = 2; }
    else              { Bw = Wv; bias = bv; Cd = Vh; N = KV; bxx = bx - 10; mode = 3; }
    gemm_body16(Xh, Bw, bias, Cd, N, CC, bxx, blockIdx.y, smem_h, mode);
}

__global__ void __launch_bounds__(128, 3) gemm_p_kernel(
    const __half* __restrict__ A, const __half* __restrict__ Wp,
    const float* __restrict__ bp, float* __restrict__ out)
{
    extern __shared__ __align__(16) __half smem_h[];
    gemm_body16(A, Wp, bp, out, CC, CC, blockIdx.x, blockIdx.y, smem_h, 0);
}

// ---------------------------------------------------------------------------
// Causal GQA flash attention, fp16 m16n8k16, fp32 softmax/accum.
// Block = 128 q-rows x head. 8 warps; warp owns 16 q-rows. k-tile = 32.
// ---------------------------------------------------------------------------
__global__ void __launch_bounds__(256) attn_f16_kernel(
    const __half* __restrict__ Qh, const __half* __restrict__ Kh,
    const __half* __restrict__ Vh, __half* __restrict__ O)
{
    __shared__ __align__(16) __half sbh[18432];  // 36,864 B

    const int tid = threadIdx.x;
    const int lane = tid & 31;
    const int w = tid >> 5;
    const int gid = lane >> 2;
    const int tig = lane & 3;
    const int qt = gridDim.x - 1 - blockIdx.x;  // heavy tiles first
    const int q0 = qt << 7;
    const int h = blockIdx.y;
    const int b = blockIdx.z;
    const int g = h >> 2;

    const __half* Qg = Qh + (size_t)(b * TT + q0) * CC + h * HD;
    const __half* Kg = Kh + (size_t)(b * TT) * KV + g * HD;
    const __half* Vg = Vh + (size_t)(b * GG + g) * (TT / 2) * (HD * 2);

    // Prologue: stage Q fp16
#pragma unroll
    for (int t = 0; t < 4; t++) {
        int ch = tid + (t << 8);
        int r = ch >> 3;
        int c8 = (ch & 7) << 3;
        cp_async16(smem_u32(sbh + r * 72 + c8), Qg + (size_t)r * CC + c8);
    }
    CP_COMMIT();
    CP_WAIT(0);
    __syncthreads();

    const int rl = (w << 4) + gid;
    unsigned qa[4][4];
#pragma unroll
    for (int jj = 0; jj < 4; jj++) {
        int base = rl * 72 + (jj << 4) + (tig << 1);
        qa[jj][0] = *(const unsigned*)(sbh + base);
        qa[jj][1] = *(const unsigned*)(sbh + base + 8 * 72);
        qa[jj][2] = *(const unsigned*)(sbh + base + 8);
        qa[jj][3] = *(const unsigned*)(sbh + base + 8 * 72 + 8);
    }
    __syncthreads();  // Q staging dead -> K/V buffers live

    float m_lo = -1e30f, m_hi = -1e30f, l_lo = 0.0f, l_hi = 0.0f;
    float acc[8][4];
#pragma unroll
    for (int nd = 0; nd < 8; nd++)
#pragma unroll
        for (int c = 0; c < 4; c++) acc[nd][c] = 0.0f;

    const int row_lo = q0 + rl;
    const int row_hi = row_lo + 8;
    const int ktiles = (q0 >> 5) + 4;
    __half* Ps = sbh + 9216;

#define ATTN_ISSUE(kt_) do {                                                \
    int _st = (kt_) & 1;                                                    \
    int _k0 = (kt_) << 5;                                                   \
    {                                                                       \
        int _r = tid >> 3, _c8 = (tid & 7) << 3;                            \
        cp_async16(smem_u32(sbh + _st * 2304 + _r * 72 + _c8),              \
                   Kg + (size_t)(_k0 + _r) * KV + _c8);                     \
    }                                                                       \
    {                                                                       \
        int _tp = tid >> 4, _cc8 = (tid & 15) << 3;                         \
        cp_async16(smem_u32(sbh + 4608 + _st * 2304 + _tp * 144 + _cc8),    \
                   Vg + (size_t)((_k0 >> 1) + _tp) * 128 + _cc8);           \
    }                                                                       \
} while (0)

    ATTN_ISSUE(0);
    CP_COMMIT();

    for (int kt = 0; kt < ktiles; kt++) {
        if (kt + 1 < ktiles) {
            ATTN_ISSUE(kt + 1);
            CP_COMMIT();
            CP_WAIT(1);
        } else {
            CP_WAIT(0);
        }
        __syncthreads();

        const int st = kt & 1;
        const __half* Ks_ = sbh + st * 2304;          // [32][72]
        const __half* Vp_ = sbh + 4608 + st * 2304;   // [16][144]
        const int k0 = kt << 5;

        // S = Q @ K^T
        float s[4][4];
#pragma unroll
        for (int ni = 0; ni < 4; ni++)
#pragma unroll
            for (int c = 0; c < 4; c++) s[ni][c] = 0.0f;

#pragma unroll
        for (int jj = 0; jj < 4; jj++) {
#pragma unroll
            for (int ni = 0; ni < 4; ni++) {
                int key = (ni << 3) + gid;
                int koff = key * 72 + (jj << 4) + (tig << 1);
                unsigned b0 = *(const unsigned*)(Ks_ + koff);
                unsigned b1 = *(const unsigned*)(Ks_ + koff + 8);
                mma_f16(s[ni], qa[jj], b0, b1);
            }
        }

        // causal mask
        if (k0 + 31 > q0) {
#pragma unroll
            for (int ni = 0; ni < 4; ni++) {
                int cg = k0 + (ni << 3) + (tig << 1);
                if (cg > row_lo)     s[ni][0] = -1e30f;
                if (cg + 1 > row_lo) s[ni][1] = -1e30f;
                if (cg > row_hi)     s[ni][2] = -1e30f;
                if (cg + 1 > row_hi) s[ni][3] = -1e30f;
            }
        }

        // online softmax (base-2; scale folded into Q)
        float mx_lo = -1e30f, mx_hi = -1e30f;
#pragma unroll
        for (int ni = 0; ni < 4; ni++) {
            mx_lo = fmaxf(mx_lo, fmaxf(s[ni][0], s[ni][1]));
            mx_hi = fmaxf(mx_hi, fmaxf(s[ni][2], s[ni][3]));
        }
        mx_lo = fmaxf(mx_lo, __shfl_xor_sync(0xffffffffu, mx_lo, 1));
        mx_lo = fmaxf(mx_lo, __shfl_xor_sync(0xffffffffu, mx_lo, 2));
        mx_hi = fmaxf(mx_hi, __shfl_xor_sync(0xffffffffu, mx_hi, 1));
        mx_hi = fmaxf(mx_hi, __shfl_xor_sync(0xffffffffu, mx_hi, 2));

        float mn_lo = fmaxf(m_lo, mx_lo);
        float mn_hi = fmaxf(m_hi, mx_hi);
        float alpha_lo = exp2f(m_lo - mn_lo);
        float alpha_hi = exp2f(m_hi - mn_hi);
        m_lo = mn_lo; m_hi = mn_hi;

        float sum_lo = 0.0f, sum_hi = 0.0f;
#pragma unroll
        for (int ni = 0; ni < 4; ni++) {
            s[ni][0] = exp2f(s[ni][0] - mn_lo);
            s[ni][1] = exp2f(s[ni][1] - mn_lo);
            s[ni][2] = exp2f(s[ni][2] - mn_hi);
            s[ni][3] = exp2f(s[ni][3] - mn_hi);
            sum_lo += s[ni][0] + s[ni][1];
            sum_hi += s[ni][2] + s[ni][3];
        }
        sum_lo += __shfl_xor_sync(0xffffffffu, sum_lo, 1);
        sum_lo += __shfl_xor_sync(0xffffffffu, sum_lo, 2);
        sum_hi += __shfl_xor_sync(0xffffffffu, sum_hi, 1);
        sum_hi += __shfl_xor_sync(0xffffffffu, sum_hi, 2);
        l_lo = l_lo * alpha_lo + sum_lo;
        l_hi = l_hi * alpha_hi + sum_hi;

#pragma unroll
        for (int nd = 0; nd < 8; nd++) {
            acc[nd][0] *= alpha_lo; acc[nd][1] *= alpha_lo;
            acc[nd][2] *= alpha_hi; acc[nd][3] *= alpha_hi;
        }

        // stage P fp16
#pragma unroll
        for (int ni = 0; ni < 4; ni++) {
            int c = (ni << 3) + (tig << 1);
            *(__half2*)(Ps + rl * 72 + c)       = __floats2half2_rn(s[ni][0], s[ni][1]);
            *(__half2*)(Ps + (rl + 8) * 72 + c) = __floats2half2_rn(s[ni][2], s[ni][3]);
        }
        __syncwarp();

        // O += P @ V
        unsigned pa[2][4];
#pragma unroll
        for (int jj = 0; jj < 2; jj++) {
            int base = rl * 72 + (jj << 4) + (tig << 1);
            pa[jj][0] = *(const unsigned*)(Ps + base);
            pa[jj][1] = *(const unsigned*)(Ps + base + 8 * 72);
            pa[jj][2] = *(const unsigned*)(Ps + base + 8);
            pa[jj][3] = *(const unsigned*)(Ps + base + 8 * 72 + 8);
        }
#pragma unroll
        for (int jj = 0; jj < 2; jj++) {
#pragma unroll
            for (int nd = 0; nd < 8; nd++) {
                int d = (nd << 3) + gid;
                int voff = ((jj << 3) + tig) * 144 + (d << 1);
                unsigned b0 = *(const unsigned*)(Vp_ + voff);
                unsigned b1 = *(const unsigned*)(Vp_ + voff + 576);
                mma_f16(acc[nd], pa[jj], b0, b1);
            }
        }
        __syncthreads();
    }

    // epilogue: normalize, emit fp16 O (feeds fp16 final projection)
    float inv_lo = 1.0f / l_lo;
    float inv_hi = 1.0f / l_hi;
    __half* Og = O + (size_t)(b * TT + q0 + rl) * CC + h * HD;
#pragma unroll
    for (int nd = 0; nd < 8; nd++) {
        int c = (nd << 3) + (tig << 1);
        *(__half2*)&Og[c] =
            __floats2half2_rn(acc[nd][0] * inv_lo, acc[nd][1] * inv_lo);
        *(__half2*)&Og[(size_t)8 * CC + c] =
            __floats2half2_rn(acc[nd][2] * inv_hi, acc[nd][3] * inv_hi);
    }
#undef ATTN_ISSUE
}

// ---------------------------------------------------------------------------
extern "C" void kernel_launch(void* const* d_in, const int* in_sizes, int n_in,
                              void* d_out, int out_size)
{
    (void)in_sizes; (void)n_in; (void)out_size;
    const float* x  = (const float*)d_in[0];
    const float* Wq = (const float*)d_in[1];
    const float* bq = (const float*)d_in[2];
    const float* Wk = (const float*)d_in[3];
    const float* bk = (const float*)d_in[4];
    const float* Wv = (const float*)d_in[5];
    const float* bv = (const float*)d_in[6];
    const float* Wp = (const float*)d_in[7];
    const float* bp = (const float*)d_in[8];
    float* out = (float*)d_out;

    __half *Xh, *Qh, *Kh, *Vh, *Oh, *Wqh, *Wkh, *Wvh, *Wph;
    cudaGetSymbolAddress((void**)&Xh, g_Xh);
    cudaGetSymbolAddress((void**)&Qh, g_Qh);
    cudaGetSymbolAddress((void**)&Kh, g_Kh);
    cudaGetSymbolAddress((void**)&Vh, g_Vh);
    cudaGetSymbolAddress((void**)&Oh, g_Oh);
    cudaGetSymbolAddress((void**)&Wqh, g_Wqh);
    cudaGetSymbolAddress((void**)&Wkh, g_Wkh);
    cudaGetSymbolAddress((void**)&Wvh, g_Wvh);
    cudaGetSymbolAddress((void**)&Wph, g_Wph);

    cudaFuncSetAttribute(gemm_qkv_kernel,
                         cudaFuncAttributeMaxDynamicSharedMemorySize, GEMM_SMEM_BYTES);
    cudaFuncSetAttribute(gemm_p_kernel,
                         cudaFuncAttributeMaxDynamicSharedMemorySize, GEMM_SMEM_BYTES);

    // Prepass: x -> fp16; weights -> fp16 k-pair-interleaved (2 launches)
    cvt_x16_kernel<<<(ROWS * CC / 4 + 255) / 256, 256>>>(x, Xh, ROWS * CC / 4);
    cvt_weights_kernel<<<dim3((CC / 2 * CC + 255) / 256, 4), 256>>>(
        Wq, Wqh, Wk, Wkh, Wv, Wvh, Wp, Wph);

    // Fused Q/K/V projections (fp16 tensor cores, fp16 outputs)
    gemm_qkv_kernel<<<dim3(12, ROWS / 128), 128, GEMM_SMEM_BYTES>>>(
        Xh, Wqh, bq, Qh, Wkh, bk, Kh, Wvh, bv, Vh);

    // Causal GQA attention (fp16 tensor cores, fp32 softmax)
    attn_f16_kernel<<<dim3(TT / 128, HH, BB), 256>>>(Qh, Kh, Vh, Oh);

    // Output projection (fp16 in, fp32 out)
    gemm_p_kernel<<<dim3(CC / 128, ROWS / 128), 128, GEMM_SMEM_BYTES>>>(
        Oh, Wph, bp, out);
}

// round 13
// speedup vs baseline: 6.7570x; 1.1106x over previous
#include <cuda_runtime.h>
#include <cuda_fp16.h>
#include <cstdint>

// Problem constants
#define BB 2
#define TT 2048
#define CC 1024
#define HH 16
#define GG 4
#define HD 64
#define KV 256
#define ROWS (BB * TT)  // 4096

// Q scale with folded log2(e) for exp2-based softmax
#define QSCALE (0.125f * 1.44269504088896f)

// Scratch (allocation-free rule: __device__ globals)
__device__ __half g_Xh[ROWS * CC];    // fp16 x
__device__ __half g_Qh[ROWS * CC];    // fp16 Q (pre-scaled by QSCALE)
__device__ __half g_Kh[ROWS * KV];    // fp16 K, row-major
__device__ __half g_Vh[ROWS * KV];    // fp16 V, key-pair-interleaved per (b,g)
__device__ __half g_Oh[ROWS * CC];    // fp16 attention output
__device__ __half g_Wqh[CC * CC];     // fp16 weights, k-pair-interleaved
__device__ __half g_Wkh[CC * KV];
__device__ __half g_Wvh[CC * KV];
__device__ __half g_Wph[CC * CC];

// ---------------------------------------------------------------------------
// helpers
// ---------------------------------------------------------------------------
__device__ __forceinline__ uint32_t smem_u32(const void* p) {
    uint32_t a;
    asm("{ .reg .u64 t; cvta.to.shared.u64 t, %1; cvt.u32.u64 %0, t; }"
        : "=r"(a) : "l"(p));
    return a;
}

__device__ __forceinline__ void cp_async16(uint32_t saddr, const void* g) {
    asm volatile("cp.async.cg.shared.global [%0], [%1], 16;"
                 :: "r"(saddr), "l"(g) : "memory");
}
#define CP_COMMIT() asm volatile("cp.async.commit_group;" ::: "memory")
#define CP_WAIT(n)  asm volatile("cp.async.wait_group %0;" :: "n"(n) : "memory")

// fp16 m16n8k16, fp32 accum
__device__ __forceinline__ void mma_f16(float* d, const unsigned* a,
                                        unsigned b0, unsigned b1) {
    asm volatile(
        "mma.sync.aligned.m16n8k16.row.col.f32.f16.f16.f32 "
        "{%0,%1,%2,%3}, {%4,%5,%6,%7}, {%8,%9}, {%0,%1,%2,%3};"
        : "+f"(d[0]), "+f"(d[1]), "+f"(d[2]), "+f"(d[3])
        : "r"(a[0]), "r"(a[1]), "r"(a[2]), "r"(a[3]),
          "r"(b0), "r"(b1));
}

// single-instruction MUFU exp2 (independent of host math flags)
__device__ __forceinline__ float ex2(float x) {
    float y;
    asm("ex2.approx.ftz.f32 %0, %1;" : "=f"(y) : "f"(x));
    return y;
}

// pack two floats into one fp16x2 register (FULL 32 bits)
__device__ __forceinline__ unsigned pack_half2(float a, float b) {
    __half2 h = __floats2half2_rn(a, b);
    return *reinterpret_cast<unsigned*>(&h);
}

// V interleaved index: per (b,g), token pairs adjacent per d
__device__ __forceinline__ size_t vh_index(int b, int g, int t, int d) {
    return ((size_t)(b * GG + g) * (TT / 2) + (t >> 1)) * (HD * 2) + d * 2 + (t & 1);
}

// ---------------------------------------------------------------------------
// Prepass 1: x -> fp16
// ---------------------------------------------------------------------------
__global__ void __launch_bounds__(256) cvt_x16_kernel(
    const float* __restrict__ in, __half* __restrict__ out, int n4)
{
    int i = blockIdx.x * 256 + threadIdx.x;
    if (i < n4) {
        float4 v = ((const float4*)in)[i];
        __half2 h0 = __floats2half2_rn(v.x, v.y);
        __half2 h1 = __floats2half2_rn(v.z, v.w);
        *(__half2*)&out[i * 4]     = h0;
        *(__half2*)&out[i * 4 + 2] = h1;
    }
}

// Prepass 2: all 4 weights -> fp16, k-pair-interleaved:
//   out[(k>>1)*2N + 2n + (k&1)] = in[k*N + n]
__global__ void __launch_bounds__(256) cvt_weights_kernel(
    const float* __restrict__ Wq, __half* __restrict__ Wqh,
    const float* __restrict__ Wk, __half* __restrict__ Wkh,
    const float* __restrict__ Wv, __half* __restrict__ Wvh,
    const float* __restrict__ Wp, __half* __restrict__ Wph)
{
    const int m = blockIdx.y;
    const float* in; __half* out; int N;
    if (m == 0)      { in = Wq; out = Wqh; N = CC; }
    else if (m == 1) { in = Wk; out = Wkh; N = KV; }
    else if (m == 2) { in = Wv; out = Wvh; N = KV; }
    else             { in = Wp; out = Wph; N = CC; }
    const int total = (CC / 2) * N;
    int idx = blockIdx.x * 256 + threadIdx.x;
    if (idx < total) {
        int kp = idx / N, n = idx % N;
        float a = in[(size_t)(2 * kp) * N + n];
        float b = in[(size_t)(2 * kp + 1) * N + n];
        *(__half2*)&out[(size_t)kp * 2 * N + 2 * n] = __floats2half2_rn(a, b);
    }
}

// ---------------------------------------------------------------------------
// FP16 mma.sync GEMM (unchanged from R11): 128x128 tile, BK=32, 128 thr.
// ---------------------------------------------------------------------------
#define A_ST 40
#define B_ST 272
#define STAGE_HALVES (128 * A_ST + 16 * B_ST)     // 9472
#define GEMM_SMEM_BYTES (2 * STAGE_HALVES * 2)    // 37888

__device__ __forceinline__ void gemm_issue16(
    __half* smem_h, int st, const __half* __restrict__ Ag,
    const __half* __restrict__ Bg, int Kdim, int N2, int k0, int tid)
{
    __half* dA = smem_h + st * STAGE_HALVES;
    __half* dB = dA + 128 * A_ST;
#pragma unroll
    for (int t = 0; t < 4; t++) {
        int ch = tid + (t << 7);
        int r = ch >> 2;
        int c8 = (ch & 3) << 3;
        cp_async16(smem_u32(dA + r * A_ST + c8),
                   Ag + (size_t)r * Kdim + k0 + c8);
    }
#pragma unroll
    for (int t = 0; t < 4; t++) {
        int ch = tid + (t << 7);
        int kp = ch >> 5;
        int c8 = (ch & 31) << 3;
        cp_async16(smem_u32(dB + kp * B_ST + c8),
                   Bg + (size_t)((k0 >> 1) + kp) * N2 + c8);
    }
}

__device__ __forceinline__ void gemm_body16(
    const __half* __restrict__ A, const __half* __restrict__ Bw,
    const float* __restrict__ bias, void* __restrict__ Cd,
    int N, int Kdim, int bx, int by, __half* smem_h, int mode)
{
    const int tid = threadIdx.x;
    const int lane = tid & 31;
    const int warp = tid >> 5;
    const int gid = lane >> 2;
    const int tig = lane & 3;
    const int wm = (warp & 1) << 6;
    const int wn = (warp >> 1) << 6;
    const int bm = by << 7;
    const int bn = bx << 7;

    const __half* Ag = A + (size_t)bm * Kdim;
    const __half* Bg = Bw + bn * 2;
    const int N2 = N * 2;
    const int ntiles = Kdim >> 5;

    float acc[4][8][4];
#pragma unroll
    for (int mi = 0; mi < 4; mi++)
#pragma unroll
        for (int ni = 0; ni < 8; ni++)
#pragma unroll
            for (int c = 0; c < 4; c++) acc[mi][ni][c] = 0.0f;

    gemm_issue16(smem_h, 0, Ag, Bg, Kdim, N2, 0, tid);
    CP_COMMIT();

    for (int kt = 0; kt < ntiles; kt++) {
        if (kt + 1 < ntiles) {
            gemm_issue16(smem_h, (kt + 1) & 1, Ag, Bg, Kdim, N2, (kt + 1) << 5, tid);
            CP_COMMIT();
            CP_WAIT(1);
        } else {
            CP_WAIT(0);
        }
        __syncthreads();

        const __half* As_ = smem_h + (kt & 1) * STAGE_HALVES;
        const __half* Bs_ = As_ + 128 * A_ST;
#pragma unroll
        for (int jj = 0; jj < 2; jj++) {
            unsigned a[4][4];
#pragma unroll
            for (int mi = 0; mi < 4; mi++) {
                int base = (wm + (mi << 4) + gid) * A_ST + (jj << 4) + (tig << 1);
                a[mi][0] = *(const unsigned*)(As_ + base);
                a[mi][1] = *(const unsigned*)(As_ + base + 8 * A_ST);
                a[mi][2] = *(const unsigned*)(As_ + base + 8);
                a[mi][3] = *(const unsigned*)(As_ + base + 8 * A_ST + 8);
            }
#pragma unroll
            for (int ni = 0; ni < 8; ni++) {
                int n = wn + (ni << 3) + gid;
                int kp = (jj << 3) + tig;
                unsigned b0 = *(const unsigned*)(Bs_ + kp * B_ST + n * 2);
                unsigned b1 = *(const unsigned*)(Bs_ + (kp + 4) * B_ST + n * 2);
#pragma unroll
                for (int mi = 0; mi < 4; mi++)
                    mma_f16(acc[mi][ni], a[mi], b0, b1);
            }
        }
        __syncthreads();
    }

#pragma unroll
    for (int mi = 0; mi < 4; mi++) {
        int r0 = bm + wm + (mi << 4) + gid;
#pragma unroll
        for (int ni = 0; ni < 8; ni++) {
            int c = bn + wn + (ni << 3) + (tig << 1);
            float2 bb = *(const float2*)&bias[c];
            float o00 = acc[mi][ni][0] + bb.x;
            float o01 = acc[mi][ni][1] + bb.y;
            float o10 = acc[mi][ni][2] + bb.x;
            float o11 = acc[mi][ni][3] + bb.y;
            if (mode == 0) {
                float* C = (float*)Cd;
                *(float2*)&C[(size_t)r0 * N + c] = make_float2(o00, o01);
                *(float2*)&C[(size_t)(r0 + 8) * N + c] = make_float2(o10, o11);
            } else if (mode == 1) {
                __half* C = (__half*)Cd;
                *(__half2*)&C[(size_t)r0 * N + c] =
                    __floats2half2_rn(o00 * QSCALE, o01 * QSCALE);
                *(__half2*)&C[(size_t)(r0 + 8) * N + c] =
                    __floats2half2_rn(o10 * QSCALE, o11 * QSCALE);
            } else if (mode == 2) {
                __half* C = (__half*)Cd;
                *(__half2*)&C[(size_t)r0 * N + c] = __floats2half2_rn(o00, o01);
                *(__half2*)&C[(size_t)(r0 + 8) * N + c] = __floats2half2_rn(o10, o11);
            } else {
                __half* C = (__half*)Cd;
                int gg = c >> 6, d = c & 63;
                int b0_ = r0 >> 11, t0 = r0 & 2047;
                int b1_ = (r0 + 8) >> 11, t1 = (r0 + 8) & 2047;
                C[vh_index(b0_, gg, t0, d)]     = __float2half_rn(o00);
                C[vh_index(b0_, gg, t0, d + 1)] = __float2half_rn(o01);
                C[vh_index(b1_, gg, t1, d)]     = __float2half_rn(o10);
                C[vh_index(b1_, gg, t1, d + 1)] = __float2half_rn(o11);
            }
        }
    }
}

__global__ void __launch_bounds__(128, 3) gemm_qkv_kernel(
    const __half* __restrict__ Xh,
    const __half* __restrict__ Wq, const float* __restrict__ bq, __half* __restrict__ Qh,
    const __half* __restrict__ Wk, const float* __restrict__ bk, __half* __restrict__ Kh,
    const __half* __restrict__ Wv, const float* __restrict__ bv, __half* __restrict__ Vh)
{
    extern __shared__ __align__(16) __half smem_h[];
    const int bx = blockIdx.x;
    const __half* Bw; const float* bias; void* Cd; int N, bxx, mode;
    if (bx < 8)       { Bw = Wq; bias = bq; Cd = Qh; N = CC; bxx = bx;      mode = 1; }
    else if (bx < 10) { Bw = Wk; bias = bk; Cd = Kh; N = KV; bxx = bx - 8;  mode = 2; }
    else              { Bw = Wv; bias = bv; Cd = Vh; N = KV; bxx = bx - 10; mode = 3; }
    gemm_body16(Xh, Bw, bias, Cd, N, CC, bxx, blockIdx.y, smem_h, mode);
}

__global__ void __launch_bounds__(128, 3) gemm_p_kernel(
    const __half* __restrict__ A, const __half* __restrict__ Wp,
    const float* __restrict__ bp, float* __restrict__ out)
{
    extern __shared__ __align__(16) __half smem_h[];
    gemm_body16(A, Wp, bp, out, CC, CC, blockIdx.x, blockIdx.y, smem_h, 0);
}

// ---------------------------------------------------------------------------
// Causal GQA flash attention v3: fp16 m16n8k16, fp32 softmax/accum.
// Block = 128 q-rows x head. 8 warps; warp owns 16 q-rows. k-tile = 64.
// P kept entirely in registers (C-frag of S == A-frag for PV), conditional
// acc rescale, raw MUFU exp2.
// Smem (halves): K bufs @ st*4608 [64][72]; V bufs @ 9216+st*4608 [32][144].
// Q staging overlays the K region during prologue. Total 36,864 B (static).
// ---------------------------------------------------------------------------
__global__ void __launch_bounds__(256, 2) attn_f16_kernel(
    const __half* __restrict__ Qh, const __half* __restrict__ Kh,
    const __half* __restrict__ Vh, __half* __restrict__ O)
{
    __shared__ __align__(16) __half sbh[18432];  // 36,864 B

    const int tid = threadIdx.x;
    const int lane = tid & 31;
    const int w = tid >> 5;
    const int gid = lane >> 2;
    const int tig = lane & 3;
    const int qt = gridDim.x - 1 - blockIdx.x;  // heavy tiles first
    const int q0 = qt << 7;
    const int h = blockIdx.y;
    const int b = blockIdx.z;
    const int g = h >> 2;

    const __half* Qg = Qh + (size_t)(b * TT + q0) * CC + h * HD;
    const __half* Kg = Kh + (size_t)(b * TT) * KV + g * HD;
    const __half* Vg = Vh + (size_t)(b * GG + g) * (TT / 2) * (HD * 2);

    // Prologue: stage Q fp16 into [128][72] (overlays K buffers)
#pragma unroll
    for (int t = 0; t < 4; t++) {
        int ch = tid + (t << 8);
        int r = ch >> 3;
        int c8 = (ch & 7) << 3;
        cp_async16(smem_u32(sbh + r * 72 + c8), Qg + (size_t)r * CC + c8);
    }
    CP_COMMIT();
    CP_WAIT(0);
    __syncthreads();

    const int rl = (w << 4) + gid;
    unsigned qa[4][4];
#pragma unroll
    for (int jj = 0; jj < 4; jj++) {
        int base = rl * 72 + (jj << 4) + (tig << 1);
        qa[jj][0] = *(const unsigned*)(sbh + base);
        qa[jj][1] = *(const unsigned*)(sbh + base + 8 * 72);
        qa[jj][2] = *(const unsigned*)(sbh + base + 8);
        qa[jj][3] = *(const unsigned*)(sbh + base + 8 * 72 + 8);
    }
    __syncthreads();  // Q staging dead -> K/V buffers live

    float m_lo = -1e30f, m_hi = -1e30f, l_lo = 0.0f, l_hi = 0.0f;
    float acc[8][4];
#pragma unroll
    for (int nd = 0; nd < 8; nd++)
#pragma unroll
        for (int c = 0; c < 4; c++) acc[nd][c] = 0.0f;

    const int row_lo = q0 + rl;
    const int row_hi = row_lo + 8;
    const int ktiles = (q0 >> 6) + 2;   // 64-key tiles; diagonal span 128

    // cp.async per 64-key tile: K 512 chunks + V 512 chunks -> 2+2 per thread
#define ATTN_ISSUE(kt_) do {                                                \
    int _st = (kt_) & 1;                                                    \
    int _k0 = (kt_) << 6;                                                   \
    _Pragma("unroll")                                                       \
    for (int _t = 0; _t < 2; _t++) {                                        \
        int _ch = tid + (_t << 8);                                          \
        int _r = _ch >> 3, _c8 = (_ch & 7) << 3;                            \
        cp_async16(smem_u32(sbh + _st * 4608 + _r * 72 + _c8),              \
                   Kg + (size_t)(_k0 + _r) * KV + _c8);                     \
        int _tp = _ch >> 4, _cc8 = (_ch & 15) << 3;                         \
        cp_async16(smem_u32(sbh + 9216 + _st * 4608 + _tp * 144 + _cc8),    \
                   Vg + (size_t)((_k0 >> 1) + _tp) * 128 + _cc8);           \
    }                                                                       \
} while (0)

    ATTN_ISSUE(0);
    CP_COMMIT();

    for (int kt = 0; kt < ktiles; kt++) {
        if (kt + 1 < ktiles) {
            ATTN_ISSUE(kt + 1);
            CP_COMMIT();
            CP_WAIT(1);
        } else {
            CP_WAIT(0);
        }
        __syncthreads();

        const int st = kt & 1;
        const __half* Ks_ = sbh + st * 4608;          // [64][72]
        const __half* Vp_ = sbh + 9216 + st * 4608;   // [32][144]
        const int k0 = kt << 6;

        // S = Q @ K^T : 4 d-steps x 8 key-tiles = 32 mmas
        float s[8][4];
#pragma unroll
        for (int ni = 0; ni < 8; ni++)
#pragma unroll
            for (int c = 0; c < 4; c++) s[ni][c] = 0.0f;

#pragma unroll
        for (int jj = 0; jj < 4; jj++) {
#pragma unroll
            for (int ni = 0; ni < 8; ni++) {
                int key = (ni << 3) + gid;
                int koff = key * 72 + (jj << 4) + (tig << 1);
                unsigned b0 = *(const unsigned*)(Ks_ + koff);
                unsigned b1 = *(const unsigned*)(Ks_ + koff + 8);
                mma_f16(s[ni], qa[jj], b0, b1);
            }
        }

        // causal mask (only diagonal-overlapping tiles)
        if (k0 + 63 > q0) {
#pragma unroll
            for (int ni = 0; ni < 8; ni++) {
                int cg = k0 + (ni << 3) + (tig << 1);
                if (cg > row_lo)     s[ni][0] = -1e30f;
                if (cg + 1 > row_lo) s[ni][1] = -1e30f;
                if (cg > row_hi)     s[ni][2] = -1e30f;
                if (cg + 1 > row_hi) s[ni][3] = -1e30f;
            }
        }

        // online softmax (base-2; scale folded into Q)
        float mx_lo = -1e30f, mx_hi = -1e30f;
#pragma unroll
        for (int ni = 0; ni < 8; ni++) {
            mx_lo = fmaxf(mx_lo, fmaxf(s[ni][0], s[ni][1]));
            mx_hi = fmaxf(mx_hi, fmaxf(s[ni][2], s[ni][3]));
        }
        mx_lo = fmaxf(mx_lo, __shfl_xor_sync(0xffffffffu, mx_lo, 1));
        mx_lo = fmaxf(mx_lo, __shfl_xor_sync(0xffffffffu, mx_lo, 2));
        mx_hi = fmaxf(mx_hi, __shfl_xor_sync(0xffffffffu, mx_hi, 1));
        mx_hi = fmaxf(mx_hi, __shfl_xor_sync(0xffffffffu, mx_hi, 2));

        float mn_lo = fmaxf(m_lo, mx_lo);
        float mn_hi = fmaxf(m_hi, mx_hi);
        bool rescale = (mn_lo > m_lo) || (mn_hi > m_hi);
        float alpha_lo = ex2(m_lo - mn_lo);
        float alpha_hi = ex2(m_hi - mn_hi);
        m_lo = mn_lo; m_hi = mn_hi;

        float sum_lo = 0.0f, sum_hi = 0.0f;
#pragma unroll
        for (int ni = 0; ni < 8; ni++) {
            s[ni][0] = ex2(s[ni][0] - mn_lo);
            s[ni][1] = ex2(s[ni][1] - mn_lo);
            s[ni][2] = ex2(s[ni][2] - mn_hi);
            s[ni][3] = ex2(s[ni][3] - mn_hi);
            sum_lo += s[ni][0] + s[ni][1];
            sum_hi += s[ni][2] + s[ni][3];
        }
        sum_lo += __shfl_xor_sync(0xffffffffu, sum_lo, 1);
        sum_lo += __shfl_xor_sync(0xffffffffu, sum_lo, 2);
        sum_hi += __shfl_xor_sync(0xffffffffu, sum_hi, 1);
        sum_hi += __shfl_xor_sync(0xffffffffu, sum_hi, 2);
        l_lo = l_lo * alpha_lo + sum_lo;
        l_hi = l_hi * alpha_hi + sum_hi;

        if (rescale) {
#pragma unroll
            for (int nd = 0; nd < 8; nd++) {
                acc[nd][0] *= alpha_lo; acc[nd][1] *= alpha_lo;
                acc[nd][2] *= alpha_hi; acc[nd][3] *= alpha_hi;
            }
        }

        // P: C-fragment of S == A-fragment for PV; pack in registers.
        unsigned pa[4][4];
#pragma unroll
        for (int jj2 = 0; jj2 < 4; jj2++) {
            pa[jj2][0] = pack_half2(s[2*jj2][0],   s[2*jj2][1]);
            pa[jj2][1] = pack_half2(s[2*jj2][2],   s[2*jj2][3]);
            pa[jj2][2] = pack_half2(s[2*jj2+1][0], s[2*jj2+1][1]);
            pa[jj2][3] = pack_half2(s[2*jj2+1][2], s[2*jj2+1][3]);
        }

        // O += P @ V : 4 key16-steps x 8 d-tiles = 32 mmas
#pragma unroll
        for (int jj2 = 0; jj2 < 4; jj2++) {
#pragma unroll
            for (int nd = 0; nd < 8; nd++) {
                int d = (nd << 3) + gid;
                int voff = ((jj2 << 3) + tig) * 144 + (d << 1);
                unsigned b0 = *(const unsigned*)(Vp_ + voff);
                unsigned b1 = *(const unsigned*)(Vp_ + voff + 576);
                mma_f16(acc[nd], pa[jj2], b0, b1);
            }
        }
        __syncthreads();
    }

    // epilogue: normalize, emit fp16 O (feeds fp16 final projection)
    float inv_lo = 1.0f / l_lo;
    float inv_hi = 1.0f / l_hi;
    __half* Og = O + (size_t)(b * TT + q0 + rl) * CC + h * HD;
#pragma unroll
    for (int nd = 0; nd < 8; nd++) {
        int c = (nd << 3) + (tig << 1);
        *(__half2*)&Og[c] =
            __floats2half2_rn(acc[nd][0] * inv_lo, acc[nd][1] * inv_lo);
        *(__half2*)&Og[(size_t)8 * CC + c] =
            __floats2half2_rn(acc[nd][2] * inv_hi, acc[nd][3] * inv_hi);
    }
#undef ATTN_ISSUE
}

// ---------------------------------------------------------------------------
extern "C" void kernel_launch(void* const* d_in, const int* in_sizes, int n_in,
                              void* d_out, int out_size)
{
    (void)in_sizes; (void)n_in; (void)out_size;
    const float* x  = (const float*)d_in[0];
    const float* Wq = (const float*)d_in[1];
    const float* bq = (const float*)d_in[2];
    const float* Wk = (const float*)d_in[3];
    const float* bk = (const float*)d_in[4];
    const float* Wv = (const float*)d_in[5];
    const float* bv = (const float*)d_in[6];
    const float* Wp = (const float*)d_in[7];
    const float* bp = (const float*)d_in[8];
    float* out = (float*)d_out;

    __half *Xh, *Qh, *Kh, *Vh, *Oh, *Wqh, *Wkh, *Wvh, *Wph;
    cudaGetSymbolAddress((void**)&Xh, g_Xh);
    cudaGetSymbolAddress((void**)&Qh, g_Qh);
    cudaGetSymbolAddress((void**)&Kh, g_Kh);
    cudaGetSymbolAddress((void**)&Vh, g_Vh);
    cudaGetSymbolAddress((void**)&Oh, g_Oh);
    cudaGetSymbolAddress((void**)&Wqh, g_Wqh);
    cudaGetSymbolAddress((void**)&Wkh, g_Wkh);
    cudaGetSymbolAddress((void**)&Wvh, g_Wvh);
    cudaGetSymbolAddress((void**)&Wph, g_Wph);

    cudaFuncSetAttribute(gemm_qkv_kernel,
                         cudaFuncAttributeMaxDynamicSharedMemorySize, GEMM_SMEM_BYTES);
    cudaFuncSetAttribute(gemm_p_kernel,
                         cudaFuncAttributeMaxDynamicSharedMemorySize, GEMM_SMEM_BYTES);

    // Prepass: x -> fp16; weights -> fp16 k-pair-interleaved (2 launches)
    cvt_x16_kernel<<<(ROWS * CC / 4 + 255) / 256, 256>>>(x, Xh, ROWS * CC / 4);
    cvt_weights_kernel<<<dim3((CC / 2 * CC + 255) / 256, 4), 256>>>(
        Wq, Wqh, Wk, Wkh, Wv, Wvh, Wp, Wph);

    // Fused Q/K/V projections (fp16 tensor cores, fp16 outputs)
    gemm_qkv_kernel<<<dim3(12, ROWS / 128), 128, GEMM_SMEM_BYTES>>>(
        Xh, Wqh, bq, Qh, Wkh, bk, Kh, Wvh, bv, Vh);

    // Causal GQA attention (fp16 tensor cores, register-resident P)
    attn_f16_kernel<<<dim3(TT / 128, HH, BB), 256>>>(Qh, Kh, Vh, Oh);

    // Output projection (fp16 in, fp32 out)
    gemm_p_kernel<<<dim3(CC / 128, ROWS / 128), 128, GEMM_SMEM_BYTES>>>(
        Oh, Wph, bp, out);
}

// round 14
// speedup vs baseline: 7.0242x; 1.0395x over previous
#include <cuda_runtime.h>
#include <cuda_fp16.h>
#include <cstdint>

// Problem constants
#define BB 2
#define TT 2048
#define CC 1024
#define HH 16
#define GG 4
#define HD 64
#define KV 256
#define ROWS (BB * TT)  // 4096

// Q scale with folded log2(e) for exp2-based softmax
#define QSCALE (0.125f * 1.44269504088896f)

// Scratch (allocation-free rule: __device__ globals)
__device__ __half g_Xh[ROWS * CC];    // fp16 x
__device__ __half g_Qh[ROWS * CC];    // fp16 Q (pre-scaled by QSCALE)
__device__ __half g_Kh[ROWS * KV];    // fp16 K, row-major
__device__ __half g_Vt[ROWS * KV];    // fp16 V TRANSPOSED: [b][g][d=64][t=2048]
__device__ __half g_Oh[ROWS * CC];    // fp16 attention output
__device__ __half g_Wqh[CC * CC];     // fp16 weights, k-pair-interleaved
__device__ __half g_Wkh[CC * KV];
__device__ __half g_Wvh[CC * KV];
__device__ __half g_Wph[CC * CC];

// ---------------------------------------------------------------------------
// helpers
// ---------------------------------------------------------------------------
__device__ __forceinline__ uint32_t smem_u32(const void* p) {
    uint32_t a;
    asm("{ .reg .u64 t; cvta.to.shared.u64 t, %1; cvt.u32.u64 %0, t; }"
        : "=r"(a) : "l"(p));
    return a;
}

__device__ __forceinline__ void cp_async16(uint32_t saddr, const void* g) {
    asm volatile("cp.async.cg.shared.global [%0], [%1], 16;"
                 :: "r"(saddr), "l"(g) : "memory");
}
#define CP_COMMIT() asm volatile("cp.async.commit_group;" ::: "memory")
#define CP_WAIT(n)  asm volatile("cp.async.wait_group %0;" :: "n"(n) : "memory")

// fp16 m16n8k16, fp32 accum
__device__ __forceinline__ void mma_f16(float* d, const unsigned* a,
                                        unsigned b0, unsigned b1) {
    asm volatile(
        "mma.sync.aligned.m16n8k16.row.col.f32.f16.f16.f32 "
        "{%0,%1,%2,%3}, {%4,%5,%6,%7}, {%8,%9}, {%0,%1,%2,%3};"
        : "+f"(d[0]), "+f"(d[1]), "+f"(d[2]), "+f"(d[3])
        : "r"(a[0]), "r"(a[1]), "r"(a[2]), "r"(a[3]),
          "r"(b0), "r"(b1));
}

// ldmatrix x4: 4 8x8 b16 tiles, lane r supplies row r%8 of tile r/8
__device__ __forceinline__ void ldsm_x4(unsigned& r0, unsigned& r1,
                                        unsigned& r2, unsigned& r3,
                                        uint32_t addr) {
    asm volatile("ldmatrix.sync.aligned.m8n8.x4.shared.b16 {%0,%1,%2,%3}, [%4];"
                 : "=r"(r0), "=r"(r1), "=r"(r2), "=r"(r3) : "r"(addr));
}

// single-instruction MUFU exp2
__device__ __forceinline__ float ex2(float x) {
    float y;
    asm("ex2.approx.ftz.f32 %0, %1;" : "=f"(y) : "f"(x));
    return y;
}

// pack two floats into one fp16x2 register (FULL 32 bits)
__device__ __forceinline__ unsigned pack_half2(float a, float b) {
    __half2 h = __floats2half2_rn(a, b);
    return *reinterpret_cast<unsigned*>(&h);
}

// ---------------------------------------------------------------------------
// Prepass 1: x -> fp16
// ---------------------------------------------------------------------------
__global__ void __launch_bounds__(256) cvt_x16_kernel(
    const float* __restrict__ in, __half* __restrict__ out, int n4)
{
    int i = blockIdx.x * 256 + threadIdx.x;
    if (i < n4) {
        float4 v = ((const float4*)in)[i];
        __half2 h0 = __floats2half2_rn(v.x, v.y);
        __half2 h1 = __floats2half2_rn(v.z, v.w);
        *(__half2*)&out[i * 4]     = h0;
        *(__half2*)&out[i * 4 + 2] = h1;
    }
}

// Prepass 2: all 4 weights -> fp16, k-pair-interleaved:
//   out[(k>>1)*2N + 2n + (k&1)] = in[k*N + n]
__global__ void __launch_bounds__(256) cvt_weights_kernel(
    const float* __restrict__ Wq, __half* __restrict__ Wqh,
    const float* __restrict__ Wk, __half* __restrict__ Wkh,
    const float* __restrict__ Wv, __half* __restrict__ Wvh,
    const float* __restrict__ Wp, __half* __restrict__ Wph)
{
    const int m = blockIdx.y;
    const float* in; __half* out; int N;
    if (m == 0)      { in = Wq; out = Wqh; N = CC; }
    else if (m == 1) { in = Wk; out = Wkh; N = KV; }
    else if (m == 2) { in = Wv; out = Wvh; N = KV; }
    else             { in = Wp; out = Wph; N = CC; }
    const int total = (CC / 2) * N;
    int idx = blockIdx.x * 256 + threadIdx.x;
    if (idx < total) {
        int kp = idx / N, n = idx % N;
        float a = in[(size_t)(2 * kp) * N + n];
        float b = in[(size_t)(2 * kp + 1) * N + n];
        *(__half2*)&out[(size_t)kp * 2 * N + 2 * n] = __floats2half2_rn(a, b);
    }
}

// ---------------------------------------------------------------------------
// FP16 mma.sync GEMM (unchanged): 128x128 tile, BK=32, 128 thr.
// Epilogue mode 3 now writes V TRANSPOSED: Vt[(b*G+g)*64 + d][t].
// ---------------------------------------------------------------------------
#define A_ST 40
#define B_ST 272
#define STAGE_HALVES (128 * A_ST + 16 * B_ST)     // 9472
#define GEMM_SMEM_BYTES (2 * STAGE_HALVES * 2)    // 37888

__device__ __forceinline__ void gemm_issue16(
    __half* smem_h, int st, const __half* __restrict__ Ag,
    const __half* __restrict__ Bg, int Kdim, int N2, int k0, int tid)
{
    __half* dA = smem_h + st * STAGE_HALVES;
    __half* dB = dA + 128 * A_ST;
#pragma unroll
    for (int t = 0; t < 4; t++) {
        int ch = tid + (t << 7);
        int r = ch >> 2;
        int c8 = (ch & 3) << 3;
        cp_async16(smem_u32(dA + r * A_ST + c8),
                   Ag + (size_t)r * Kdim + k0 + c8);
    }
#pragma unroll
    for (int t = 0; t < 4; t++) {
        int ch = tid + (t << 7);
        int kp = ch >> 5;
        int c8 = (ch & 31) << 3;
        cp_async16(smem_u32(dB + kp * B_ST + c8),
                   Bg + (size_t)((k0 >> 1) + kp) * N2 + c8);
    }
}

__device__ __forceinline__ void gemm_body16(
    const __half* __restrict__ A, const __half* __restrict__ Bw,
    const float* __restrict__ bias, void* __restrict__ Cd,
    int N, int Kdim, int bx, int by, __half* smem_h, int mode)
{
    const int tid = threadIdx.x;
    const int lane = tid & 31;
    const int warp = tid >> 5;
    const int gid = lane >> 2;
    const int tig = lane & 3;
    const int wm = (warp & 1) << 6;
    const int wn = (warp >> 1) << 6;
    const int bm = by << 7;
    const int bn = bx << 7;

    const __half* Ag = A + (size_t)bm * Kdim;
    const __half* Bg = Bw + bn * 2;
    const int N2 = N * 2;
    const int ntiles = Kdim >> 5;

    float acc[4][8][4];
#pragma unroll
    for (int mi = 0; mi < 4; mi++)
#pragma unroll
        for (int ni = 0; ni < 8; ni++)
#pragma unroll
            for (int c = 0; c < 4; c++) acc[mi][ni][c] = 0.0f;

    gemm_issue16(smem_h, 0, Ag, Bg, Kdim, N2, 0, tid);
    CP_COMMIT();

    for (int kt = 0; kt < ntiles; kt++) {
        if (kt + 1 < ntiles) {
            gemm_issue16(smem_h, (kt + 1) & 1, Ag, Bg, Kdim, N2, (kt + 1) << 5, tid);
            CP_COMMIT();
            CP_WAIT(1);
        } else {
            CP_WAIT(0);
        }
        __syncthreads();

        const __half* As_ = smem_h + (kt & 1) * STAGE_HALVES;
        const __half* Bs_ = As_ + 128 * A_ST;
#pragma unroll
        for (int jj = 0; jj < 2; jj++) {
            unsigned a[4][4];
#pragma unroll
            for (int mi = 0; mi < 4; mi++) {
                int base = (wm + (mi << 4) + gid) * A_ST + (jj << 4) + (tig << 1);
                a[mi][0] = *(const unsigned*)(As_ + base);
                a[mi][1] = *(const unsigned*)(As_ + base + 8 * A_ST);
                a[mi][2] = *(const unsigned*)(As_ + base + 8);
                a[mi][3] = *(const unsigned*)(As_ + base + 8 * A_ST + 8);
            }
#pragma unroll
            for (int ni = 0; ni < 8; ni++) {
                int n = wn + (ni << 3) + gid;
                int kp = (jj << 3) + tig;
                unsigned b0 = *(const unsigned*)(Bs_ + kp * B_ST + n * 2);
                unsigned b1 = *(const unsigned*)(Bs_ + (kp + 4) * B_ST + n * 2);
#pragma unroll
                for (int mi = 0; mi < 4; mi++)
                    mma_f16(acc[mi][ni], a[mi], b0, b1);
            }
        }
        __syncthreads();
    }

#pragma unroll
    for (int mi = 0; mi < 4; mi++) {
        int r0 = bm + wm + (mi << 4) + gid;
#pragma unroll
        for (int ni = 0; ni < 8; ni++) {
            int c = bn + wn + (ni << 3) + (tig << 1);
            float2 bb = *(const float2*)&bias[c];
            float o00 = acc[mi][ni][0] + bb.x;
            float o01 = acc[mi][ni][1] + bb.y;
            float o10 = acc[mi][ni][2] + bb.x;
            float o11 = acc[mi][ni][3] + bb.y;
            if (mode == 0) {
                float* C = (float*)Cd;
                *(float2*)&C[(size_t)r0 * N + c] = make_float2(o00, o01);
                *(float2*)&C[(size_t)(r0 + 8) * N + c] = make_float2(o10, o11);
            } else if (mode == 1) {
                __half* C = (__half*)Cd;
                *(__half2*)&C[(size_t)r0 * N + c] =
                    __floats2half2_rn(o00 * QSCALE, o01 * QSCALE);
                *(__half2*)&C[(size_t)(r0 + 8) * N + c] =
                    __floats2half2_rn(o10 * QSCALE, o11 * QSCALE);
            } else if (mode == 2) {
                __half* C = (__half*)Cd;
                *(__half2*)&C[(size_t)r0 * N + c] = __floats2half2_rn(o00, o01);
                *(__half2*)&C[(size_t)(r0 + 8) * N + c] = __floats2half2_rn(o10, o11);
            } else {
                // V transposed: Vt[((b*G+g)*64 + d) * TT + t]
                __half* C = (__half*)Cd;
                int gg = c >> 6, d = c & 63;
                int b0_ = r0 >> 11, t0 = r0 & 2047;
                int b1_ = (r0 + 8) >> 11, t1 = (r0 + 8) & 2047;
                size_t base0 = (size_t)(b0_ * GG + gg) * HD;
                size_t base1 = (size_t)(b1_ * GG + gg) * HD;
                C[(base0 + d) * TT + t0]     = __float2half_rn(o00);
                C[(base0 + d + 1) * TT + t0] = __float2half_rn(o01);
                C[(base1 + d) * TT + t1]     = __float2half_rn(o10);
                C[(base1 + d + 1) * TT + t1] = __float2half_rn(o11);
            }
        }
    }
}

__global__ void __launch_bounds__(128, 3) gemm_qkv_kernel(
    const __half* __restrict__ Xh,
    const __half* __restrict__ Wq, const float* __restrict__ bq, __half* __restrict__ Qh,
    const __half* __restrict__ Wk, const float* __restrict__ bk, __half* __restrict__ Kh,
    const __half* __restrict__ Wv, const float* __restrict__ bv, __half* __restrict__ Vt)
{
    extern __shared__ __align__(16) __half smem_h[];
    const int bx = blockIdx.x;
    const __half* Bw; const float* bias; void* Cd; int N, bxx, mode;
    if (bx < 8)       { Bw = Wq; bias = bq; Cd = Qh; N = CC; bxx = bx;      mode = 1; }
    else if (bx < 10) { Bw = Wk; bias = bk; Cd = Kh; N = KV; bxx = bx - 8;  mode = 2; }
    else              { Bw = Wv; bias = bv; Cd = Vt; N = KV; bxx = bx - 10; mode = 3; }
    gemm_body16(Xh, Bw, bias, Cd, N, CC, bxx, blockIdx.y, smem_h, mode);
}

__global__ void __launch_bounds__(128, 3) gemm_p_kernel(
    const __half* __restrict__ A, const __half* __restrict__ Wp,
    const float* __restrict__ bp, float* __restrict__ out)
{
    extern __shared__ __align__(16) __half smem_h[];
    gemm_body16(A, Wp, bp, out, CC, CC, blockIdx.x, blockIdx.y, smem_h, 0);
}

// ---------------------------------------------------------------------------
// Causal GQA flash attention v4: fp16 m16n8k16, fp32 softmax/accum.
// Block = 128 q-rows x head. 8 warps; warp owns 16 q-rows. k-tile = 64.
// K AND V fragments via ldmatrix.x4 (4x fewer operand-load instructions).
// V global layout transposed [b][g][d][t]; smem V stage [64 d][72] halves.
// Register-resident P, conditional rescale, MUFU exp2.
// Smem (halves): K st @ st*4608 [64][72]; V st @ 9216+st*4608 [64][72].
// Q staging overlays K region during prologue. Total 36,864 B (static).
// ---------------------------------------------------------------------------
__global__ void __launch_bounds__(256, 2) attn_f16_kernel(
    const __half* __restrict__ Qh, const __half* __restrict__ Kh,
    const __half* __restrict__ Vt, __half* __restrict__ O)
{
    __shared__ __align__(16) __half sbh[18432];  // 36,864 B

    const int tid = threadIdx.x;
    const int lane = tid & 31;
    const int w = tid >> 5;
    const int gid = lane >> 2;
    const int tig = lane & 3;
    const int qt = gridDim.x - 1 - blockIdx.x;  // heavy tiles first
    const int q0 = qt << 7;
    const int h = blockIdx.y;
    const int b = blockIdx.z;
    const int g = h >> 2;

    const __half* Qg = Qh + (size_t)(b * TT + q0) * CC + h * HD;
    const __half* Kg = Kh + (size_t)(b * TT) * KV + g * HD;
    const __half* Vg = Vt + (size_t)(b * GG + g) * HD * TT;

    // Prologue: stage Q fp16 into [128][72] (overlays K buffers)
#pragma unroll
    for (int t = 0; t < 4; t++) {
        int ch = tid + (t << 8);
        int r = ch >> 3;
        int c8 = (ch & 7) << 3;
        cp_async16(smem_u32(sbh + r * 72 + c8), Qg + (size_t)r * CC + c8);
    }
    CP_COMMIT();
    CP_WAIT(0);
    __syncthreads();

    const int rl = (w << 4) + gid;
    unsigned qa[4][4];
#pragma unroll
    for (int jj = 0; jj < 4; jj++) {
        int base = rl * 72 + (jj << 4) + (tig << 1);
        qa[jj][0] = *(const unsigned*)(sbh + base);
        qa[jj][1] = *(const unsigned*)(sbh + base + 8 * 72);
        qa[jj][2] = *(const unsigned*)(sbh + base + 8);
        qa[jj][3] = *(const unsigned*)(sbh + base + 8 * 72 + 8);
    }
    __syncthreads();  // Q staging dead -> K/V buffers live

    float m_lo = -1e30f, m_hi = -1e30f, l_lo = 0.0f, l_hi = 0.0f;
    float acc[8][4];
#pragma unroll
    for (int nd = 0; nd < 8; nd++)
#pragma unroll
        for (int c = 0; c < 4; c++) acc[nd][c] = 0.0f;

    const int row_lo = q0 + rl;
    const int row_hi = row_lo + 8;
    const int ktiles = (q0 >> 6) + 2;   // 64-key tiles; diagonal span 128

    // ldmatrix lane offset: tile row (lane&7) + tile-pair select (lane>>3):
    //   bit0 -> +8 cols (k-halves), bit1 -> +8 rows
    const int mrow = lane & 7;
    const int msel = lane >> 3;
    const int laneoff = (((msel >> 1) << 3) + mrow) * 72 + ((msel & 1) << 3);
    const uint32_t sb32 = smem_u32(sbh);

    // cp.async per 64-key tile: K 512 chunks + V 512 chunks -> 2+2 per thread
#define ATTN_ISSUE(kt_) do {                                                \
    int _st = (kt_) & 1;                                                    \
    int _k0 = (kt_) << 6;                                                   \
    _Pragma("unroll")                                                       \
    for (int _t = 0; _t < 2; _t++) {                                        \
        int _ch = tid + (_t << 8);                                          \
        int _r = _ch >> 3, _c8 = (_ch & 7) << 3;                            \
        cp_async16(smem_u32(sbh + _st * 4608 + _r * 72 + _c8),              \
                   Kg + (size_t)(_k0 + _r) * KV + _c8);                     \
        cp_async16(smem_u32(sbh + 9216 + _st * 4608 + _r * 72 + _c8),       \
                   Vg + (size_t)_r * TT + _k0 + _c8);                       \
    }                                                                       \
} while (0)

    ATTN_ISSUE(0);
    CP_COMMIT();

    for (int kt = 0; kt < ktiles; kt++) {
        if (kt + 1 < ktiles) {
            ATTN_ISSUE(kt + 1);
            CP_COMMIT();
            CP_WAIT(1);
        } else {
            CP_WAIT(0);
        }
        __syncthreads();

        const int st = kt & 1;
        const uint32_t kbase = sb32 + ((st * 4608 + laneoff) << 1);
        const uint32_t vbase = sb32 + ((9216 + st * 4608 + laneoff) << 1);
        const int k0 = kt << 6;

        // S = Q @ K^T : 4 d16-steps x 4 key16-pairs, ldmatrix.x4 per pair
        float s[8][4];
#pragma unroll
        for (int ni = 0; ni < 8; ni++)
#pragma unroll
            for (int c = 0; c < 4; c++) s[ni][c] = 0.0f;

#pragma unroll
        for (int jj = 0; jj < 4; jj++) {
#pragma unroll
            for (int nip = 0; nip < 4; nip++) {
                unsigned b00, b01, b10, b11;
                ldsm_x4(b00, b01, b10, b11,
                        kbase + ((nip * 1152 + jj * 16) << 1));
                mma_f16(s[2 * nip],     qa[jj], b00, b01);
                mma_f16(s[2 * nip + 1], qa[jj], b10, b11);
            }
        }

        // causal mask (only diagonal-overlapping tiles)
        if (k0 + 63 > q0) {
#pragma unroll
            for (int ni = 0; ni < 8; ni++) {
                int cg = k0 + (ni << 3) + (tig << 1);
                if (cg > row_lo)     s[ni][0] = -1e30f;
                if (cg + 1 > row_lo) s[ni][1] = -1e30f;
                if (cg > row_hi)     s[ni][2] = -1e30f;
                if (cg + 1 > row_hi) s[ni][3] = -1e30f;
            }
        }

        // online softmax (base-2; scale folded into Q)
        float mx_lo = -1e30f, mx_hi = -1e30f;
#pragma unroll
        for (int ni = 0; ni < 8; ni++) {
            mx_lo = fmaxf(mx_lo, fmaxf(s[ni][0], s[ni][1]));
            mx_hi = fmaxf(mx_hi, fmaxf(s[ni][2], s[ni][3]));
        }
        mx_lo = fmaxf(mx_lo, __shfl_xor_sync(0xffffffffu, mx_lo, 1));
        mx_lo = fmaxf(mx_lo, __shfl_xor_sync(0xffffffffu, mx_lo, 2));
        mx_hi = fmaxf(mx_hi, __shfl_xor_sync(0xffffffffu, mx_hi, 1));
        mx_hi = fmaxf(mx_hi, __shfl_xor_sync(0xffffffffu, mx_hi, 2));

        float mn_lo = fmaxf(m_lo, mx_lo);
        float mn_hi = fmaxf(m_hi, mx_hi);
        bool rescale = (mn_lo > m_lo) || (mn_hi > m_hi);
        float alpha_lo = ex2(m_lo - mn_lo);
        float alpha_hi = ex2(m_hi - mn_hi);
        m_lo = mn_lo; m_hi = mn_hi;

        float sum_lo = 0.0f, sum_hi = 0.0f;
#pragma unroll
        for (int ni = 0; ni < 8; ni++) {
            s[ni][0] = ex2(s[ni][0] - mn_lo);
            s[ni][1] = ex2(s[ni][1] - mn_lo);
            s[ni][2] = ex2(s[ni][2] - mn_hi);
            s[ni][3] = ex2(s[ni][3] - mn_hi);
            sum_lo += s[ni][0] + s[ni][1];
            sum_hi += s[ni][2] + s[ni][3];
        }
        sum_lo += __shfl_xor_sync(0xffffffffu, sum_lo, 1);
        sum_lo += __shfl_xor_sync(0xffffffffu, sum_lo, 2);
        sum_hi += __shfl_xor_sync(0xffffffffu, sum_hi, 1);
        sum_hi += __shfl_xor_sync(0xffffffffu, sum_hi, 2);
        l_lo = l_lo * alpha_lo + sum_lo;
        l_hi = l_hi * alpha_hi + sum_hi;

        if (rescale) {
#pragma unroll
            for (int nd = 0; nd < 8; nd++) {
                acc[nd][0] *= alpha_lo; acc[nd][1] *= alpha_lo;
                acc[nd][2] *= alpha_hi; acc[nd][3] *= alpha_hi;
            }
        }

        // P: C-fragment of S == A-fragment for PV; pack in registers.
        unsigned pa[4][4];
#pragma unroll
        for (int jj2 = 0; jj2 < 4; jj2++) {
            pa[jj2][0] = pack_half2(s[2*jj2][0],   s[2*jj2][1]);
            pa[jj2][1] = pack_half2(s[2*jj2][2],   s[2*jj2][3]);
            pa[jj2][2] = pack_half2(s[2*jj2+1][0], s[2*jj2+1][1]);
            pa[jj2][3] = pack_half2(s[2*jj2+1][2], s[2*jj2+1][3]);
        }

        // O += P @ V : 4 key16-steps x 4 d16-pairs, ldmatrix.x4 per pair
#pragma unroll
        for (int jj2 = 0; jj2 < 4; jj2++) {
#pragma unroll
            for (int ndp = 0; ndp < 4; ndp++) {
                unsigned v00, v01, v10, v11;
                ldsm_x4(v00, v01, v10, v11,
                        vbase + ((ndp * 1152 + jj2 * 16) << 1));
                mma_f16(acc[2 * ndp],     pa[jj2], v00, v01);
                mma_f16(acc[2 * ndp + 1], pa[jj2], v10, v11);
            }
        }
        __syncthreads();
    }

    // epilogue: normalize, emit fp16 O (feeds fp16 final projection)
    float inv_lo = 1.0f / l_lo;
    float inv_hi = 1.0f / l_hi;
    __half* Og = O + (size_t)(b * TT + q0 + rl) * CC + h * HD;
#pragma unroll
    for (int nd = 0; nd < 8; nd++) {
        int c = (nd << 3) + (tig << 1);
        *(__half2*)&Og[c] =
            __floats2half2_rn(acc[nd][0] * inv_lo, acc[nd][1] * inv_lo);
        *(__half2*)&Og[(size_t)8 * CC + c] =
            __floats2half2_rn(acc[nd][2] * inv_hi, acc[nd][3] * inv_hi);
    }
#undef ATTN_ISSUE
}

// ---------------------------------------------------------------------------
extern "C" void kernel_launch(void* const* d_in, const int* in_sizes, int n_in,
                              void* d_out, int out_size)
{
    (void)in_sizes; (void)n_in; (void)out_size;
    const float* x  = (const float*)d_in[0];
    const float* Wq = (const float*)d_in[1];
    const float* bq = (const float*)d_in[2];
    const float* Wk = (const float*)d_in[3];
    const float* bk = (const float*)d_in[4];
    const float* Wv = (const float*)d_in[5];
    const float* bv = (const float*)d_in[6];
    const float* Wp = (const float*)d_in[7];
    const float* bp = (const float*)d_in[8];
    float* out = (float*)d_out;

    __half *Xh, *Qh, *Kh, *Vtp, *Oh, *Wqh, *Wkh, *Wvh, *Wph;
    cudaGetSymbolAddress((void**)&Xh, g_Xh);
    cudaGetSymbolAddress((void**)&Qh, g_Qh);
    cudaGetSymbolAddress((void**)&Kh, g_Kh);
    cudaGetSymbolAddress((void**)&Vtp, g_Vt);
    cudaGetSymbolAddress((void**)&Oh, g_Oh);
    cudaGetSymbolAddress((void**)&Wqh, g_Wqh);
    cudaGetSymbolAddress((void**)&Wkh, g_Wkh);
    cudaGetSymbolAddress((void**)&Wvh, g_Wvh);
    cudaGetSymbolAddress((void**)&Wph, g_Wph);

    cudaFuncSetAttribute(gemm_qkv_kernel,
                         cudaFuncAttributeMaxDynamicSharedMemorySize, GEMM_SMEM_BYTES);
    cudaFuncSetAttribute(gemm_p_kernel,
                         cudaFuncAttributeMaxDynamicSharedMemorySize, GEMM_SMEM_BYTES);

    // Prepass: x -> fp16; weights -> fp16 k-pair-interleaved (2 launches)
    cvt_x16_kernel<<<(ROWS * CC / 4 + 255) / 256, 256>>>(x, Xh, ROWS * CC / 4);
    cvt_weights_kernel<<<dim3((CC / 2 * CC + 255) / 256, 4), 256>>>(
        Wq, Wqh, Wk, Wkh, Wv, Wvh, Wp, Wph);

    // Fused Q/K/V projections (V emitted transposed)
    gemm_qkv_kernel<<<dim3(12, ROWS / 128), 128, GEMM_SMEM_BYTES>>>(
        Xh, Wqh, bq, Qh, Wkh, bk, Kh, Wvh, bv, Vtp);

    // Causal GQA attention (ldmatrix operand loads, register-resident P)
    attn_f16_kernel<<<dim3(TT / 128, HH, BB), 256>>>(Qh, Kh, Vtp, Oh);

    // Output projection (fp16 in, fp32 out)
    gemm_p_kernel<<<dim3(CC / 128, ROWS / 128), 128, GEMM_SMEM_BYTES>>>(
        Oh, Wph, bp, out);
}

// round 15
// speedup vs baseline: 7.1614x; 1.0195x over previous
#include <cuda_runtime.h>
#include <cuda_fp16.h>
#include <cstdint>

// Problem constants
#define BB 2
#define TT 2048
#define CC 1024
#define HH 16
#define GG 4
#define HD 64
#define KV 256
#define ROWS (BB * TT)  // 4096

// Q scale with folded log2(e) for exp2-based softmax
#define QSCALE (0.125f * 1.44269504088896f)

// Scratch (allocation-free rule: __device__ globals)
__device__ __half g_Xh[ROWS * CC];    // fp16 x
__device__ __half g_Qh[ROWS * CC];    // fp16 Q (pre-scaled by QSCALE)
__device__ __half g_Kh[ROWS * KV];    // fp16 K, row-major
__device__ __half g_Vt[ROWS * KV];    // fp16 V TRANSPOSED: [b][g][d=64][t=2048]
__device__ __half g_Oh[ROWS * CC];    // fp16 attention output
__device__ __half g_Wqh[CC * CC];     // fp16 weights, k-pair-interleaved
__device__ __half g_Wkh[CC * KV];
__device__ __half g_Wvh[CC * KV];
__device__ __half g_Wph[CC * CC];

// ---------------------------------------------------------------------------
// helpers
// ---------------------------------------------------------------------------
__device__ __forceinline__ uint32_t smem_u32(const void* p) {
    uint32_t a;
    asm("{ .reg .u64 t; cvta.to.shared.u64 t, %1; cvt.u32.u64 %0, t; }"
        : "=r"(a) : "l"(p));
    return a;
}

__device__ __forceinline__ void cp_async16(uint32_t saddr, const void* g) {
    asm volatile("cp.async.cg.shared.global [%0], [%1], 16;"
                 :: "r"(saddr), "l"(g) : "memory");
}
#define CP_COMMIT() asm volatile("cp.async.commit_group;" ::: "memory")
#define CP_WAIT(n)  asm volatile("cp.async.wait_group %0;" :: "n"(n) : "memory")

// fp16 m16n8k16, fp32 accum
__device__ __forceinline__ void mma_f16(float* d, const unsigned* a,
                                        unsigned b0, unsigned b1) {
    asm volatile(
        "mma.sync.aligned.m16n8k16.row.col.f32.f16.f16.f32 "
        "{%0,%1,%2,%3}, {%4,%5,%6,%7}, {%8,%9}, {%0,%1,%2,%3};"
        : "+f"(d[0]), "+f"(d[1]), "+f"(d[2]), "+f"(d[3])
        : "r"(a[0]), "r"(a[1]), "r"(a[2]), "r"(a[3]),
          "r"(b0), "r"(b1));
}

// ldmatrix x4: 4 8x8 b16 tiles, lane r supplies row r%8 of tile r/8
__device__ __forceinline__ void ldsm_x4(unsigned& r0, unsigned& r1,
                                        unsigned& r2, unsigned& r3,
                                        uint32_t addr) {
    asm volatile("ldmatrix.sync.aligned.m8n8.x4.shared.b16 {%0,%1,%2,%3}, [%4];"
                 : "=r"(r0), "=r"(r1), "=r"(r2), "=r"(r3) : "r"(addr));
}

// single-instruction MUFU exp2
__device__ __forceinline__ float ex2(float x) {
    float y;
    asm("ex2.approx.ftz.f32 %0, %1;" : "=f"(y) : "f"(x));
    return y;
}

// pack two floats into one fp16x2 register (FULL 32 bits)
__device__ __forceinline__ unsigned pack_half2(float a, float b) {
    __half2 h = __floats2half2_rn(a, b);
    return *reinterpret_cast<unsigned*>(&h);
}

// ---------------------------------------------------------------------------
// Prepass 1: x -> fp16
// ---------------------------------------------------------------------------
__global__ void __launch_bounds__(256) cvt_x16_kernel(
    const float* __restrict__ in, __half* __restrict__ out, int n4)
{
    int i = blockIdx.x * 256 + threadIdx.x;
    if (i < n4) {
        float4 v = ((const float4*)in)[i];
        __half2 h0 = __floats2half2_rn(v.x, v.y);
        __half2 h1 = __floats2half2_rn(v.z, v.w);
        *(__half2*)&out[i * 4]     = h0;
        *(__half2*)&out[i * 4 + 2] = h1;
    }
}

// Prepass 2: all 4 weights -> fp16, k-pair-interleaved:
//   out[(k>>1)*2N + 2n + (k&1)] = in[k*N + n]
__global__ void __launch_bounds__(256) cvt_weights_kernel(
    const float* __restrict__ Wq, __half* __restrict__ Wqh,
    const float* __restrict__ Wk, __half* __restrict__ Wkh,
    const float* __restrict__ Wv, __half* __restrict__ Wvh,
    const float* __restrict__ Wp, __half* __restrict__ Wph)
{
    const int m = blockIdx.y;
    const float* in; __half* out; int N;
    if (m == 0)      { in = Wq; out = Wqh; N = CC; }
    else if (m == 1) { in = Wk; out = Wkh; N = KV; }
    else if (m == 2) { in = Wv; out = Wvh; N = KV; }
    else             { in = Wp; out = Wph; N = CC; }
    const int total = (CC / 2) * N;
    int idx = blockIdx.x * 256 + threadIdx.x;
    if (idx < total) {
        int kp = idx / N, n = idx % N;
        float a = in[(size_t)(2 * kp) * N + n];
        float b = in[(size_t)(2 * kp + 1) * N + n];
        *(__half2*)&out[(size_t)kp * 2 * N + 2 * n] = __floats2half2_rn(a, b);
    }
}

// ---------------------------------------------------------------------------
// FP16 mma.sync GEMM (unchanged): 128x128 tile, BK=32, 128 thr.
// Epilogue mode 3 now writes V TRANSPOSED: Vt[(b*G+g)*64 + d][t].
// ---------------------------------------------------------------------------
#define A_ST 40
#define B_ST 272
#define STAGE_HALVES (128 * A_ST + 16 * B_ST)     // 9472
#define GEMM_SMEM_BYTES (2 * STAGE_HALVES * 2)    // 37888

__device__ __forceinline__ void gemm_issue16(
    __half* smem_h, int st, const __half* __restrict__ Ag,
    const __half* __restrict__ Bg, int Kdim, int N2, int k0, int tid)
{
    __half* dA = smem_h + st * STAGE_HALVES;
    __half* dB = dA + 128 * A_ST;
#pragma unroll
    for (int t = 0; t < 4; t++) {
        int ch = tid + (t << 7);
        int r = ch >> 2;
        int c8 = (ch & 3) << 3;
        cp_async16(smem_u32(dA + r * A_ST + c8),
                   Ag + (size_t)r * Kdim + k0 + c8);
    }
#pragma unroll
    for (int t = 0; t < 4; t++) {
        int ch = tid + (t << 7);
        int kp = ch >> 5;
        int c8 = (ch & 31) << 3;
        cp_async16(smem_u32(dB + kp * B_ST + c8),
                   Bg + (size_t)((k0 >> 1) + kp) * N2 + c8);
    }
}

__device__ __forceinline__ void gemm_body16(
    const __half* __restrict__ A, const __half* __restrict__ Bw,
    const float* __restrict__ bias, void* __restrict__ Cd,
    int N, int Kdim, int bx, int by, __half* smem_h, int mode)
{
    const int tid = threadIdx.x;
    const int lane = tid & 31;
    const int warp = tid >> 5;
    const int gid = lane >> 2;
    const int tig = lane & 3;
    const int wm = (warp & 1) << 6;
    const int wn = (warp >> 1) << 6;
    const int bm = by << 7;
    const int bn = bx << 7;

    const __half* Ag = A + (size_t)bm * Kdim;
    const __half* Bg = Bw + bn * 2;
    const int N2 = N * 2;
    const int ntiles = Kdim >> 5;

    float acc[4][8][4];
#pragma unroll
    for (int mi = 0; mi < 4; mi++)
#pragma unroll
        for (int ni = 0; ni < 8; ni++)
#pragma unroll
            for (int c = 0; c < 4; c++) acc[mi][ni][c] = 0.0f;

    gemm_issue16(smem_h, 0, Ag, Bg, Kdim, N2, 0, tid);
    CP_COMMIT();

    for (int kt = 0; kt < ntiles; kt++) {
        if (kt + 1 < ntiles) {
            gemm_issue16(smem_h, (kt + 1) & 1, Ag, Bg, Kdim, N2, (kt + 1) << 5, tid);
            CP_COMMIT();
            CP_WAIT(1);
        } else {
            CP_WAIT(0);
        }
        __syncthreads();

        const __half* As_ = smem_h + (kt & 1) * STAGE_HALVES;
        const __half* Bs_ = As_ + 128 * A_ST;
#pragma unroll
        for (int jj = 0; jj < 2; jj++) {
            unsigned a[4][4];
#pragma unroll
            for (int mi = 0; mi < 4; mi++) {
                int base = (wm + (mi << 4) + gid) * A_ST + (jj << 4) + (tig << 1);
                a[mi][0] = *(const unsigned*)(As_ + base);
                a[mi][1] = *(const unsigned*)(As_ + base + 8 * A_ST);
                a[mi][2] = *(const unsigned*)(As_ + base + 8);
                a[mi][3] = *(const unsigned*)(As_ + base + 8 * A_ST + 8);
            }
#pragma unroll
            for (int ni = 0; ni < 8; ni++) {
                int n = wn + (ni << 3) + gid;
                int kp = (jj << 3) + tig;
                unsigned b0 = *(const unsigned*)(Bs_ + kp * B_ST + n * 2);
                unsigned b1 = *(const unsigned*)(Bs_ + (kp + 4) * B_ST + n * 2);
#pragma unroll
                for (int mi = 0; mi < 4; mi++)
                    mma_f16(acc[mi][ni], a[mi], b0, b1);
            }
        }
        __syncthreads();
    }

#pragma unroll
    for (int mi = 0; mi < 4; mi++) {
        int r0 = bm + wm + (mi << 4) + gid;
#pragma unroll
        for (int ni = 0; ni < 8; ni++) {
            int c = bn + wn + (ni << 3) + (tig << 1);
            float2 bb = *(const float2*)&bias[c];
            float o00 = acc[mi][ni][0] + bb.x;
            float o01 = acc[mi][ni][1] + bb.y;
            float o10 = acc[mi][ni][2] + bb.x;
            float o11 = acc[mi][ni][3] + bb.y;
            if (mode == 0) {
                float* C = (float*)Cd;
                *(float2*)&C[(size_t)r0 * N + c] = make_float2(o00, o01);
                *(float2*)&C[(size_t)(r0 + 8) * N + c] = make_float2(o10, o11);
            } else if (mode == 1) {
                __half* C = (__half*)Cd;
                *(__half2*)&C[(size_t)r0 * N + c] =
                    __floats2half2_rn(o00 * QSCALE, o01 * QSCALE);
                *(__half2*)&C[(size_t)(r0 + 8) * N + c] =
                    __floats2half2_rn(o10 * QSCALE, o11 * QSCALE);
            } else if (mode == 2) {
                __half* C = (__half*)Cd;
                *(__half2*)&C[(size_t)r0 * N + c] = __floats2half2_rn(o00, o01);
                *(__half2*)&C[(size_t)(r0 + 8) * N + c] = __floats2half2_rn(o10, o11);
            } else {
                // V transposed: Vt[((b*G+g)*64 + d) * TT + t]
                __half* C = (__half*)Cd;
                int gg = c >> 6, d = c & 63;
                int b0_ = r0 >> 11, t0 = r0 & 2047;
                int b1_ = (r0 + 8) >> 11, t1 = (r0 + 8) & 2047;
                size_t base0 = (size_t)(b0_ * GG + gg) * HD;
                size_t base1 = (size_t)(b1_ * GG + gg) * HD;
                C[(base0 + d) * TT + t0]     = __float2half_rn(o00);
                C[(base0 + d + 1) * TT + t0] = __float2half_rn(o01);
                C[(base1 + d) * TT + t1]     = __float2half_rn(o10);
                C[(base1 + d + 1) * TT + t1] = __float2half_rn(o11);
            }
        }
    }
}

__global__ void __launch_bounds__(128, 3) gemm_qkv_kernel(
    const __half* __restrict__ Xh,
    const __half* __restrict__ Wq, const float* __restrict__ bq, __half* __restrict__ Qh,
    const __half* __restrict__ Wk, const float* __restrict__ bk, __half* __restrict__ Kh,
    const __half* __restrict__ Wv, const float* __restrict__ bv, __half* __restrict__ Vt)
{
    extern __shared__ __align__(16) __half smem_h[];
    const int bx = blockIdx.x;
    const __half* Bw; const float* bias; void* Cd; int N, bxx, mode;
    if (bx < 8)       { Bw = Wq; bias = bq; Cd = Qh; N = CC; bxx = bx;      mode = 1; }
    else if (bx < 10) { Bw = Wk; bias = bk; Cd = Kh; N = KV; bxx = bx - 8;  mode = 2; }
    else              { Bw = Wv; bias = bv; Cd = Vt; N = KV; bxx = bx - 10; mode = 3; }
    gemm_body16(Xh, Bw, bias, Cd, N, CC, bxx, blockIdx.y, smem_h, mode);
}

__global__ void __launch_bounds__(128, 3) gemm_p_kernel(
    const __half* __restrict__ A, const __half* __restrict__ Wp,
    const float* __restrict__ bp, float* __restrict__ out)
{
    extern __shared__ __align__(16) __half smem_h[];
    gemm_body16(A, Wp, bp, out, CC, CC, blockIdx.x, blockIdx.y, smem_h, 0);
}

// ---------------------------------------------------------------------------
// Causal GQA flash attention v4: fp16 m16n8k16, fp32 softmax/accum.
// Block = 128 q-rows x head. 8 warps; warp owns 16 q-rows. k-tile = 64.
// K AND V fragments via ldmatrix.x4 (4x fewer operand-load instructions).
// V global layout transposed [b][g][d][t]; smem V stage [64 d][72] halves.
// Register-resident P, conditional rescale, MUFU exp2.
// Smem (halves): K st @ st*4608 [64][72]; V st @ 9216+st*4608 [64][72].
// Q staging overlays K region during prologue. Total 36,864 B (static).
// ---------------------------------------------------------------------------
__global__ void __launch_bounds__(256, 2) attn_f16_kernel(
    const __half* __restrict__ Qh, const __half* __restrict__ Kh,
    const __half* __restrict__ Vt, __half* __restrict__ O)
{
    __shared__ __align__(16) __half sbh[18432];  // 36,864 B

    const int tid = threadIdx.x;
    const int lane = tid & 31;
    const int w = tid >> 5;
    const int gid = lane >> 2;
    const int tig = lane & 3;
    const int qt = gridDim.x - 1 - blockIdx.x;  // heavy tiles first
    const int q0 = qt << 7;
    const int h = blockIdx.y;
    const int b = blockIdx.z;
    const int g = h >> 2;

    const __half* Qg = Qh + (size_t)(b * TT + q0) * CC + h * HD;
    const __half* Kg = Kh + (size_t)(b * TT) * KV + g * HD;
    const __half* Vg = Vt + (size_t)(b * GG + g) * HD * TT;

    // Prologue: stage Q fp16 into [128][72] (overlays K buffers)
#pragma unroll
    for (int t = 0; t < 4; t++) {
        int ch = tid + (t << 8);
        int r = ch >> 3;
        int c8 = (ch & 7) << 3;
        cp_async16(smem_u32(sbh + r * 72 + c8), Qg + (size_t)r * CC + c8);
    }
    CP_COMMIT();
    CP_WAIT(0);
    __syncthreads();

    const int rl = (w << 4) + gid;
    unsigned qa[4][4];
#pragma unroll
    for (int jj = 0; jj < 4; jj++) {
        int base = rl * 72 + (jj << 4) + (tig << 1);
        qa[jj][0] = *(const unsigned*)(sbh + base);
        qa[jj][1] = *(const unsigned*)(sbh + base + 8 * 72);
        qa[jj][2] = *(const unsigned*)(sbh + base + 8);
        qa[jj][3] = *(const unsigned*)(sbh + base + 8 * 72 + 8);
    }
    __syncthreads();  // Q staging dead -> K/V buffers live

    float m_lo = -1e30f, m_hi = -1e30f, l_lo = 0.0f, l_hi = 0.0f;
    float acc[8][4];
#pragma unroll
    for (int nd = 0; nd < 8; nd++)
#pragma unroll
        for (int c = 0; c < 4; c++) acc[nd][c] = 0.0f;

    const int row_lo = q0 + rl;
    const int row_hi = row_lo + 8;
    const int ktiles = (q0 >> 6) + 2;   // 64-key tiles; diagonal span 128

    // ldmatrix lane offset: tile row (lane&7) + tile-pair select (lane>>3):
    //   bit0 -> +8 cols (k-halves), bit1 -> +8 rows
    const int mrow = lane & 7;
    const int msel = lane >> 3;
    const int laneoff = (((msel >> 1) << 3) + mrow) * 72 + ((msel & 1) << 3);
    const uint32_t sb32 = smem_u32(sbh);

    // cp.async per 64-key tile: K 512 chunks + V 512 chunks -> 2+2 per thread
#define ATTN_ISSUE(kt_) do {                                                \
    int _st = (kt_) & 1;                                                    \
    int _k0 = (kt_) << 6;                                                   \
    _Pragma("unroll")                                                       \
    for (int _t = 0; _t < 2; _t++) {                                        \
        int _ch = tid + (_t << 8);                                          \
        int _r = _ch >> 3, _c8 = (_ch & 7) << 3;                            \
        cp_async16(smem_u32(sbh + _st * 4608 + _r * 72 + _c8),              \
                   Kg + (size_t)(_k0 + _r) * KV + _c8);                     \
        cp_async16(smem_u32(sbh + 9216 + _st * 4608 + _r * 72 + _c8),       \
                   Vg + (size_t)_r * TT + _k0 + _c8);                       \
    }                                                                       \
} while (0)

    ATTN_ISSUE(0);
    CP_COMMIT();

    for (int kt = 0; kt < ktiles; kt++) {
        if (kt + 1 < ktiles) {
            ATTN_ISSUE(kt + 1);
            CP_COMMIT();
            CP_WAIT(1);
        } else {
            CP_WAIT(0);
        }
        __syncthreads();

        const int st = kt & 1;
        const uint32_t kbase = sb32 + ((st * 4608 + laneoff) << 1);
        const uint32_t vbase = sb32 + ((9216 + st * 4608 + laneoff) << 1);
        const int k0 = kt << 6;

        // S = Q @ K^T : 4 d16-steps x 4 key16-pairs, ldmatrix.x4 per pair
        float s[8][4];
#pragma unroll
        for (int ni = 0; ni < 8; ni++)
#pragma unroll
            for (int c = 0; c < 4; c++) s[ni][c] = 0.0f;

#pragma unroll
        for (int jj = 0; jj < 4; jj++) {
#pragma unroll
            for (int nip = 0; nip < 4; nip++) {
                unsigned b00, b01, b10, b11;
                ldsm_x4(b00, b01, b10, b11,
                        kbase + ((nip * 1152 + jj * 16) << 1));
                mma_f16(s[2 * nip],     qa[jj], b00, b01);
                mma_f16(s[2 * nip + 1], qa[jj], b10, b11);
            }
        }

        // causal mask (only diagonal-overlapping tiles)
        if (k0 + 63 > q0) {
#pragma unroll
            for (int ni = 0; ni < 8; ni++) {
                int cg = k0 + (ni << 3) + (tig << 1);
                if (cg > row_lo)     s[ni][0] = -1e30f;
                if (cg + 1 > row_lo) s[ni][1] = -1e30f;
                if (cg > row_hi)     s[ni][2] = -1e30f;
                if (cg + 1 > row_hi) s[ni][3] = -1e30f;
            }
        }

        // online softmax (base-2; scale folded into Q)
        float mx_lo = -1e30f, mx_hi = -1e30f;
#pragma unroll
        for (int ni = 0; ni < 8; ni++) {
            mx_lo = fmaxf(mx_lo, fmaxf(s[ni][0], s[ni][1]));
            mx_hi = fmaxf(mx_hi, fmaxf(s[ni][2], s[ni][3]));
        }
        mx_lo = fmaxf(mx_lo, __shfl_xor_sync(0xffffffffu, mx_lo, 1));
        mx_lo = fmaxf(mx_lo, __shfl_xor_sync(0xffffffffu, mx_lo, 2));
        mx_hi = fmaxf(mx_hi, __shfl_xor_sync(0xffffffffu, mx_hi, 1));
        mx_hi = fmaxf(mx_hi, __shfl_xor_sync(0xffffffffu, mx_hi, 2));

        float mn_lo = fmaxf(m_lo, mx_lo);
        float mn_hi = fmaxf(m_hi, mx_hi);
        bool rescale = (mn_lo > m_lo) || (mn_hi > m_hi);
        float alpha_lo = ex2(m_lo - mn_lo);
        float alpha_hi = ex2(m_hi - mn_hi);
        m_lo = mn_lo; m_hi = mn_hi;

        float sum_lo = 0.0f, sum_hi = 0.0f;
#pragma unroll
        for (int ni = 0; ni < 8; ni++) {
            s[ni][0] = ex2(s[ni][0] - mn_lo);
            s[ni][1] = ex2(s[ni][1] - mn_lo);
            s[ni][2] = ex2(s[ni][2] - mn_hi);
            s[ni][3] = ex2(s[ni][3] - mn_hi);
            sum_lo += s[ni][0] + s[ni][1];
            sum_hi += s[ni][2] + s[ni][3];
        }
        sum_lo += __shfl_xor_sync(0xffffffffu, sum_lo, 1);
        sum_lo += __shfl_xor_sync(0xffffffffu, sum_lo, 2);
        sum_hi += __shfl_xor_sync(0xffffffffu, sum_hi, 1);
        sum_hi += __shfl_xor_sync(0xffffffffu, sum_hi, 2);
        l_lo = l_lo * alpha_lo + sum_lo;
        l_hi = l_hi * alpha_hi + sum_hi;

        if (rescale) {
#pragma unroll
            for (int nd = 0; nd < 8; nd++) {
                acc[nd][0] *= alpha_lo; acc[nd][1] *= alpha_lo;
                acc[nd][2] *= alpha_hi; acc[nd][3] *= alpha_hi;
            }
        }

        // P: C-fragment of S == A-fragment for PV; pack in registers.
        unsigned pa[4][4];
#pragma unroll
        for (int jj2 = 0; jj2 < 4; jj2++) {
            pa[jj2][0] = pack_half2(s[2*jj2][0],   s[2*jj2][1]);
            pa[jj2][1] = pack_half2(s[2*jj2][2],   s[2*jj2][3]);
            pa[jj2][2] = pack_half2(s[2*jj2+1][0], s[2*jj2+1][1]);
            pa[jj2][3] = pack_half2(s[2*jj2+1][2], s[2*jj2+1][3]);
        }

        // O += P @ V : 4 key16-steps x 4 d16-pairs, ldmatrix.x4 per pair
#pragma unroll
        for (int jj2 = 0; jj2 < 4; jj2++) {
#pragma unroll
            for (int ndp = 0; ndp < 4; ndp++) {
                unsigned v00, v01, v10, v11;
                ldsm_x4(v00, v01, v10, v11,
                        vbase + ((ndp * 1152 + jj2 * 16) << 1));
                mma_f16(acc[2 * ndp],     pa[jj2], v00, v01);
                mma_f16(acc[2 * ndp + 1], pa[jj2], v10, v11);
            }
        }
        __syncthreads();
    }

    // epilogue: normalize, emit fp16 O (feeds fp16 final projection)
    float inv_lo = 1.0f / l_lo;
    float inv_hi = 1.0f / l_hi;
    __half* Og = O + (size_t)(b * TT + q0 + rl) * CC + h * HD;
#pragma unroll
    for (int nd = 0; nd < 8; nd++) {
        int c = (nd << 3) + (tig << 1);
        *(__half2*)&Og[c] =
            __floats2half2_rn(acc[nd][0] * inv_lo, acc[nd][1] * inv_lo);
        *(__half2*)&Og[(size_t)8 * CC + c] =
            __floats2half2_rn(acc[nd][2] * inv_hi, acc[nd][3] * inv_hi);
    }
#undef ATTN_ISSUE
}

// ---------------------------------------------------------------------------
extern "C" void kernel_launch(void* const* d_in, const int* in_sizes, int n_in,
                              void* d_out, int out_size)
{
    (void)in_sizes; (void)n_in; (void)out_size;
    const float* x  = (const float*)d_in[0];
    const float* Wq = (const float*)d_in[1];
    const float* bq = (const float*)d_in[2];
    const float* Wk = (const float*)d_in[3];
    const float* bk = (const float*)d_in[4];
    const float* Wv = (const float*)d_in[5];
    const float* bv = (const float*)d_in[6];
    const float* Wp = (const float*)d_in[7];
    const float* bp = (const float*)d_in[8];
    float* out = (float*)d_out;

    __half *Xh, *Qh, *Kh, *Vtp, *Oh, *Wqh, *Wkh, *Wvh, *Wph;
    cudaGetSymbolAddress((void**)&Xh, g_Xh);
    cudaGetSymbolAddress((void**)&Qh, g_Qh);
    cudaGetSymbolAddress((void**)&Kh, g_Kh);
    cudaGetSymbolAddress((void**)&Vtp, g_Vt);
    cudaGetSymbolAddress((void**)&Oh, g_Oh);
    cudaGetSymbolAddress((void**)&Wqh, g_Wqh);
    cudaGetSymbolAddress((void**)&Wkh, g_Wkh);
    cudaGetSymbolAddress((void**)&Wvh, g_Wvh);
    cudaGetSymbolAddress((void**)&Wph, g_Wph);

    cudaFuncSetAttribute(gemm_qkv_kernel,
                         cudaFuncAttributeMaxDynamicSharedMemorySize, GEMM_SMEM_BYTES);
    cudaFuncSetAttribute(gemm_p_kernel,
                         cudaFuncAttributeMaxDynamicSharedMemorySize, GEMM_SMEM_BYTES);

    // Prepass: x -> fp16; weights -> fp16 k-pair-interleaved (2 launches)
    cvt_x16_kernel<<<(ROWS * CC / 4 + 255) / 256, 256>>>(x, Xh, ROWS * CC / 4);
    cvt_weights_kernel<<<dim3((CC / 2 * CC + 255) / 256, 4), 256>>>(
        Wq, Wqh, Wk, Wkh, Wv, Wvh, Wp, Wph);

    // Fused Q/K/V projections (V emitted transposed)
    gemm_qkv_kernel<<<dim3(12, ROWS / 128), 128, GEMM_SMEM_BYTES>>>(
        Xh, Wqh, bq, Qh, Wkh, bk, Kh, Wvh, bv, Vtp);

    // Causal GQA attention (ldmatrix operand loads, register-resident P)
    attn_f16_kernel<<<dim3(TT / 128, HH, BB), 256>>>(Qh, Kh, Vtp, Oh);

    // Output projection (fp16 in, fp32 out)
    gemm_p_kernel<<<dim3(CC / 128, ROWS / 128), 128, GEMM_SMEM_BYTES>>>(
        Oh, Wph, bp, out);
}